// round 4
// baseline (speedup 1.0000x reference)
#include <cuda_runtime.h>
#include <math.h>

#define N_TOTAL 100000
#define NP_TYPE 50000
#define NP_G    50000
#define E_G     500000
#define NH      4
#define HD      64
#define HID     64
#define D       256
#define OUT_DIM 64
#define T_TGT   20000
#define G4      4

// ------------------------- scratch (static device globals) -------------------
__device__ float  g_transformed[N_TOTAL * HID];          // 25.6 MB
__device__ float  g_z[(size_t)G4 * NP_G * D];            // 204.8 MB
__device__ float  g_el[G4 * NP_G * NH];
__device__ float  g_er[G4 * NP_G * NH];
__device__ int    g_deg[G4 * NP_G];
__device__ int    g_offs[G4 * (NP_G + 1)];
__device__ int    g_cur[G4 * NP_G];
__device__ int    g_csr_src[G4 * E_G];
__device__ float4 g_csr_ex[G4 * E_G];                    // 32 MB
__device__ float  g_gout[(size_t)G4 * NP_G * D];         // 204.8 MB
__device__ float  g_meta[(size_t)G4 * T_TGT * D];        // 81.9 MB
__device__ float  g_wsum[4];

typedef unsigned long long ull;

// packed f32x2 FMA: one issue, 4 FLOPs, exact fp32 rounding per lane
#define FMA_F32X2(d, a, b, c) \
    asm("fma.rn.f32x2 %0, %1, %2, %3;" : "=l"(d) : "l"(a), "l"(b), "l"(c))

__device__ __forceinline__ float ulo(ull v) { return __uint_as_float((unsigned)v); }
__device__ __forceinline__ float uhi(ull v) { return __uint_as_float((unsigned)(v >> 32)); }

__device__ __forceinline__ float fast_tanh(float x) {
    float y;
    asm("tanh.approx.f32 %0, %1;" : "=f"(y) : "f"(x));
    return y;
}

// ------------------------------- init ---------------------------------------
__global__ void k_init() {
    int i = blockIdx.x * blockDim.x + threadIdx.x;
    if (i < G4 * NP_G) g_deg[i] = 0;
    if (i < 4) g_wsum[i] = 0.f;
}

// --------------------------- fc: type-wise linear ---------------------------
// block: 128 rows x 64 cols; 256 threads; thread tile 4 rows x 8 cols
// FFMA2: accumulators paired over rows; wt duplicated (float2) for broadcast
__global__ __launch_bounds__(256) void k_fc(
    const float* __restrict__ f0, const float* __restrict__ f1,
    const float* __restrict__ fcW, const float* __restrict__ fcb,
    const int* __restrict__ type_idx)
{
    __shared__ __align__(16) float  ft[32][128];   // 16 KB
    __shared__ __align__(16) float2 wt2[32][64];   // 16 KB (duplicated weights)

    int t = blockIdx.y;
    int base = blockIdx.x * 128;
    const float* feat = t ? f1 : f0;
    const float* W = fcW + (size_t)t * HID * D;    // W[o][k]
    int tid = threadIdx.x;
    int rg = tid & 31, cg = tid >> 5;              // rg = lane rows, cg warp-uniform cols

    ull acc2[2][8];
#pragma unroll
    for (int p = 0; p < 2; p++)
#pragma unroll
        for (int j = 0; j < 8; j++) acc2[p][j] = 0ull;

    for (int ch = 0; ch < 8; ch++) {               // 8 chunks of 32 k
        __syncthreads();
        {   // ft[k][r]: 128 rows x 32 k
            int r = tid & 127, qb = tid >> 7;
            int row = base + r;
            bool val = row < NP_TYPE;
            const float4* fp = (const float4*)(feat + (size_t)row * D) + ch * 8;
#pragma unroll
            for (int i = 0; i < 4; i++) {
                int q = qb + i * 2;
                float4 v = val ? __ldg(fp + q) : make_float4(0.f, 0.f, 0.f, 0.f);
                ft[q * 4 + 0][r] = v.x; ft[q * 4 + 1][r] = v.y;
                ft[q * 4 + 2][r] = v.z; ft[q * 4 + 3][r] = v.w;
            }
        }
        {   // wt2[k][o] duplicated, transpose-load from W[o][k]
            int o = tid & 63, qb = tid >> 6;
            const float4* wp = (const float4*)(W + (size_t)o * D) + ch * 8;
#pragma unroll
            for (int i = 0; i < 2; i++) {
                int q = qb + i * 4;
                float4 v = __ldg(wp + q);
                wt2[q * 4 + 0][o] = make_float2(v.x, v.x);
                wt2[q * 4 + 1][o] = make_float2(v.y, v.y);
                wt2[q * 4 + 2][o] = make_float2(v.z, v.z);
                wt2[q * 4 + 3][o] = make_float2(v.w, v.w);
            }
        }
        __syncthreads();
#pragma unroll
        for (int k = 0; k < 32; k++) {
            const ulonglong2* fp = (const ulonglong2*)&ft[k][rg * 4];
            const ulonglong2* wp = (const ulonglong2*)&wt2[k][cg * 8];
            ulonglong2 fv = fp[0];                 // row pairs (r0,r1),(r2,r3)
            ull F[2] = {fv.x, fv.y};
            ulonglong2 w0 = wp[0], w1 = wp[1], w2 = wp[2], w3 = wp[3];
            ull Wb[8] = {w0.x, w0.y, w1.x, w1.y, w2.x, w2.y, w3.x, w3.y};
#pragma unroll
            for (int p = 0; p < 2; p++)
#pragma unroll
                for (int j = 0; j < 8; j++)
                    FMA_F32X2(acc2[p][j], F[p], Wb[j], acc2[p][j]);
        }
    }
    float bo[8];
#pragma unroll
    for (int j = 0; j < 8; j++) bo[j] = __ldg(&fcb[t * HID + cg * 8 + j]);
    const int* ti = type_idx + t * NP_TYPE;
#pragma unroll
    for (int p = 0; p < 2; p++) {
#pragma unroll
        for (int h = 0; h < 2; h++) {
            int row = base + rg * 4 + p * 2 + h;
            if (row < NP_TYPE) {
                int dst = __ldg(&ti[row]);
                float c[8];
#pragma unroll
                for (int j = 0; j < 8; j++)
                    c[j] = (h ? uhi(acc2[p][j]) : ulo(acc2[p][j])) + bo[j];
                float* op = g_transformed + (size_t)dst * HID + cg * 8;
                *(float4*)op = make_float4(c[0], c[1], c[2], c[3]);
                *((float4*)op + 1) = make_float4(c[4], c[5], c[6], c[7]);
            }
        }
    }
}

// ------------- gatz (+fused el/er): z = gather(transformed) @ gat_W ---------
// block: 64 rows x 256 cols; thread tile 8 rows x 8 cols
// FFMA2: accumulators paired over cols; ft duplicated (float2) for broadcast
__global__ __launch_bounds__(256) void k_gatz(
    const int* __restrict__ node_idx, const float* __restrict__ gatW,
    const float* __restrict__ attn_l, const float* __restrict__ attn_r)
{
    __shared__ __align__(16) float2 ft2[16][64];   // 8 KB (duplicated rows)
    __shared__ __align__(16) float  wt[16][256];   // 16 KB
    __shared__ int   nd[64];
    __shared__ float al_s[256], ar_s[256];

    int g = blockIdx.y;
    int base = blockIdx.x * 64;
    int tid = threadIdx.x;
    int rg = tid >> 5, cg = tid & 31;              // warp-uniform rg, lane = cg

    if (tid < 64) {
        int rr = base + tid;
        nd[tid] = (rr < NP_G) ? __ldg(&node_idx[(size_t)g * NP_G + rr]) : -1;
    } else if (tid < 128) {
        ((float4*)al_s)[tid - 64] = __ldg((const float4*)(attn_l + (size_t)g * D) + tid - 64);
    } else if (tid < 192) {
        ((float4*)ar_s)[tid - 128] = __ldg((const float4*)(attn_r + (size_t)g * D) + tid - 128);
    }

    ull acc2[8][4];
#pragma unroll
    for (int a = 0; a < 8; a++)
#pragma unroll
        for (int j = 0; j < 4; j++) acc2[a][j] = 0ull;

    for (int ch = 0; ch < 4; ch++) {               // 4 chunks of 16 k
        __syncthreads();
        {   // ft2[k][r] duplicated: 64 rows x 16 k (gathered)
            int r = tid & 63, q = tid >> 6;        // each thread one float4
            int node = nd[r];
            float4 v = (node >= 0)
                ? __ldg((const float4*)(g_transformed + (size_t)node * HID) + ch * 4 + q)
                : make_float4(0.f, 0.f, 0.f, 0.f);
            ft2[q * 4 + 0][r] = make_float2(v.x, v.x);
            ft2[q * 4 + 1][r] = make_float2(v.y, v.y);
            ft2[q * 4 + 2][r] = make_float2(v.z, v.z);
            ft2[q * 4 + 3][r] = make_float2(v.w, v.w);
        }
        {   // wt direct copy (gat_W is k-major: W[k][o])
            const float4* wp = (const float4*)(gatW + (size_t)g * HID * D + (size_t)ch * 16 * D);
            float4* wd = (float4*)&wt[0][0];
#pragma unroll
            for (int i = 0; i < 4; i++)
                wd[tid + i * 256] = __ldg(wp + tid + i * 256);
        }
        __syncthreads();
#pragma unroll
        for (int k = 0; k < 16; k++) {
            const ulonglong2* fp = (const ulonglong2*)&ft2[k][rg * 8];
            const ulonglong2* wp = (const ulonglong2*)&wt[k][cg * 8];
            ulonglong2 fa = fp[0], fb = fp[1], fc4 = fp[2], fd = fp[3];
            ull F[8] = {fa.x, fa.y, fb.x, fb.y, fc4.x, fc4.y, fd.x, fd.y};
            ulonglong2 wa = wp[0], wb = wp[1];
            ull Wb[4] = {wa.x, wa.y, wb.x, wb.y};
#pragma unroll
            for (int a = 0; a < 8; a++)
#pragma unroll
                for (int j = 0; j < 4; j++)
                    FMA_F32X2(acc2[a][j], F[a], Wb[j], acc2[a][j]);
        }
    }

    // stores + fused el/er (head = cg>>3, cols cg*8..cg*8+7 all in one head)
#pragma unroll
    for (int a = 0; a < 8; a++) {
        int row = base + rg * 8 + a;
        bool valid = row < NP_G;
        float c[8];
#pragma unroll
        for (int j = 0; j < 4; j++) {
            c[2 * j] = ulo(acc2[a][j]);
            c[2 * j + 1] = uhi(acc2[a][j]);
        }
        if (valid) {
            float* zp = g_z + ((size_t)g * NP_G + row) * D + cg * 8;
            *(float4*)zp = make_float4(c[0], c[1], c[2], c[3]);
            *((float4*)zp + 1) = make_float4(c[4], c[5], c[6], c[7]);
        }
        float pl = 0.f, pr = 0.f;
#pragma unroll
        for (int j = 0; j < 8; j++) {
            pl += c[j] * al_s[cg * 8 + j];
            pr += c[j] * ar_s[cg * 8 + j];
        }
#pragma unroll
        for (int off = 4; off; off >>= 1) {
            pl += __shfl_down_sync(0xffffffffu, pl, off, 8);
            pr += __shfl_down_sync(0xffffffffu, pr, off, 8);
        }
        if ((cg & 7) == 0 && valid) {
            int h = cg >> 3;
            g_el[((size_t)g * NP_G + row) * NH + h] = pl;
            g_er[((size_t)g * NP_G + row) * NH + h] = pr;
        }
    }
}

// ------------------------------- CSR build ----------------------------------
__global__ void k_count(const int* __restrict__ dst) {
    int e = blockIdx.x * blockDim.x + threadIdx.x;
    if (e < G4 * E_G) {
        int g = e / E_G;
        atomicAdd(&g_deg[g * NP_G + __ldg(&dst[e])], 1);
    }
}

// one block per graph; warp-shuffle two-pass scan
__global__ __launch_bounds__(1024) void k_scan() {
    __shared__ int ws[32];
    int g = blockIdx.x;
    int tid = threadIdx.x;
    int lane = tid & 31, wid = tid >> 5;
    const int CH = (NP_G + 1023) / 1024;   // 49
    int lo = tid * CH;
    int hi = min(lo + CH, NP_G);
    const int* deg = g_deg + g * NP_G;
    int s = 0;
    for (int i = lo; i < hi; i++) s += deg[i];
    int v = s;
#pragma unroll
    for (int off = 1; off < 32; off <<= 1) {
        int n = __shfl_up_sync(0xffffffffu, v, off);
        if (lane >= off) v += n;
    }
    if (lane == 31) ws[wid] = v;
    __syncthreads();
    if (wid == 0) {
        int w = ws[lane];
#pragma unroll
        for (int off = 1; off < 32; off <<= 1) {
            int n = __shfl_up_sync(0xffffffffu, w, off);
            if (lane >= off) w += n;
        }
        ws[lane] = w;
    }
    __syncthreads();
    int excl = v - s + (wid ? ws[wid - 1] : 0);
    int* offs = g_offs + g * (NP_G + 1);
    int* cur = g_cur + g * NP_G;
    int run = excl;
    for (int i = lo; i < hi; i++) {
        offs[i] = run;
        cur[i] = run;
        run += deg[i];
    }
    if (tid == 0) offs[NP_G] = E_G;
}

__global__ void k_fill(const int* __restrict__ src, const int* __restrict__ dst) {
    int e = blockIdx.x * blockDim.x + threadIdx.x;
    if (e >= G4 * E_G) return;
    int g = e / E_G;
    int gn = g * NP_G;
    int s = __ldg(&src[e]);
    int d = __ldg(&dst[e]);
    float4 elv = __ldg((const float4*)g_el + gn + s);
    float4 erv = __ldg((const float4*)g_er + gn + d);
    float e0 = elv.x + erv.x, e1 = elv.y + erv.y;
    float e2 = elv.z + erv.z, e3 = elv.w + erv.w;
    e0 = e0 > 0.f ? e0 : 0.2f * e0;
    e1 = e1 > 0.f ? e1 : 0.2f * e1;
    e2 = e2 > 0.f ? e2 : 0.2f * e2;
    e3 = e3 > 0.f ? e3 : 0.2f * e3;
    float4 ex = make_float4(__expf(e0), __expf(e1), __expf(e2), __expf(e3));
    int pos = atomicAdd(&g_cur[gn + d], 1);
    g_csr_src[(size_t)g * E_G + pos] = s;
    g_csr_ex[(size_t)g * E_G + pos] = ex;
}

// --------------- aggregate: warp per dst node, fused softmax ----------------
__global__ __launch_bounds__(256) void k_aggregate() {
    int n = (blockIdx.x * blockDim.x + threadIdx.x) >> 5;
    if (n >= G4 * NP_G) return;
    int g = n / NP_G;
    int nl = n - g * NP_G;
    int lane = threadIdx.x & 31;
    int hsel = lane >> 3;
    int beg = g_offs[g * (NP_G + 1) + nl];
    int end = g_offs[g * (NP_G + 1) + nl + 1];
    const int* cs = g_csr_src + (size_t)g * E_G;
    const float4* ce = g_csr_ex + (size_t)g * E_G;
    const float* zb = g_z + (size_t)g * NP_G * D;

    float4 a0 = {0.f, 0.f, 0.f, 0.f}, a1 = {0.f, 0.f, 0.f, 0.f};
    float den = 0.f;

    int i = beg;
    for (; i + 4 <= end; i += 4) {                 // MLP: 8 z-row LDG.128s in flight
        int s0 = __ldg(cs + i), s1 = __ldg(cs + i + 1);
        int s2 = __ldg(cs + i + 2), s3 = __ldg(cs + i + 3);
        float4 e0 = __ldg(ce + i), e1 = __ldg(ce + i + 1);
        float4 e2 = __ldg(ce + i + 2), e3 = __ldg(ce + i + 3);
        const float4* z0p = (const float4*)(zb + (size_t)s0 * D) + lane * 2;
        const float4* z1p = (const float4*)(zb + (size_t)s1 * D) + lane * 2;
        const float4* z2p = (const float4*)(zb + (size_t)s2 * D) + lane * 2;
        const float4* z3p = (const float4*)(zb + (size_t)s3 * D) + lane * 2;
        float4 za0 = __ldg(z0p), zb0 = __ldg(z0p + 1);
        float4 za1 = __ldg(z1p), zb1 = __ldg(z1p + 1);
        float4 za2 = __ldg(z2p), zb2 = __ldg(z2p + 1);
        float4 za3 = __ldg(z3p), zb3 = __ldg(z3p + 1);
        float x0 = (hsel == 0) ? e0.x : (hsel == 1) ? e0.y : (hsel == 2) ? e0.z : e0.w;
        float x1 = (hsel == 0) ? e1.x : (hsel == 1) ? e1.y : (hsel == 2) ? e1.z : e1.w;
        float x2 = (hsel == 0) ? e2.x : (hsel == 1) ? e2.y : (hsel == 2) ? e2.z : e2.w;
        float x3 = (hsel == 0) ? e3.x : (hsel == 1) ? e3.y : (hsel == 2) ? e3.z : e3.w;
        a0.x += x0 * za0.x; a0.y += x0 * za0.y; a0.z += x0 * za0.z; a0.w += x0 * za0.w;
        a1.x += x0 * zb0.x; a1.y += x0 * zb0.y; a1.z += x0 * zb0.z; a1.w += x0 * zb0.w;
        a0.x += x1 * za1.x; a0.y += x1 * za1.y; a0.z += x1 * za1.z; a0.w += x1 * za1.w;
        a1.x += x1 * zb1.x; a1.y += x1 * zb1.y; a1.z += x1 * zb1.z; a1.w += x1 * zb1.w;
        a0.x += x2 * za2.x; a0.y += x2 * za2.y; a0.z += x2 * za2.z; a0.w += x2 * za2.w;
        a1.x += x2 * zb2.x; a1.y += x2 * zb2.y; a1.z += x2 * zb2.z; a1.w += x2 * zb2.w;
        a0.x += x3 * za3.x; a0.y += x3 * za3.y; a0.z += x3 * za3.z; a0.w += x3 * za3.w;
        a1.x += x3 * zb3.x; a1.y += x3 * zb3.y; a1.z += x3 * zb3.z; a1.w += x3 * zb3.w;
        den += x0 + x1 + x2 + x3;
    }
    for (; i < end; i++) {
        int s0 = __ldg(cs + i);
        float4 e0 = __ldg(ce + i);
        const float4* z0p = (const float4*)(zb + (size_t)s0 * D) + lane * 2;
        float4 za = __ldg(z0p), zc = __ldg(z0p + 1);
        float x0 = (hsel == 0) ? e0.x : (hsel == 1) ? e0.y : (hsel == 2) ? e0.z : e0.w;
        a0.x += x0 * za.x; a0.y += x0 * za.y; a0.z += x0 * za.z; a0.w += x0 * za.w;
        a1.x += x0 * zc.x; a1.y += x0 * zc.y; a1.z += x0 * zc.z; a1.w += x0 * zc.w;
        den += x0;
    }
    float inv = 1.f / (den + 1e-9f);
    float v[8] = {a0.x * inv, a0.y * inv, a0.z * inv, a0.w * inv,
                  a1.x * inv, a1.y * inv, a1.z * inv, a1.w * inv};
#pragma unroll
    for (int j = 0; j < 8; j++) v[j] = v[j] > 0.f ? v[j] : expm1f(v[j]);
    float* op = g_gout + (size_t)n * D + lane * 8;
    *(float4*)op = make_float4(v[0], v[1], v[2], v[3]);
    *((float4*)op + 1) = make_float4(v[4], v[5], v[6], v[7]);
}

// ---------------------- gather target rows into meta ------------------------
__global__ void k_gather(const int* __restrict__ tgt) {
    int tid = threadIdx.x;
    int t = blockIdx.x * 4 + (tid >> 6);
    int c = tid & 63;
    int g = t / T_TGT;
    int node = __ldg(&tgt[t]);
    ((float4*)g_meta)[(size_t)t * 64 + c] =
        __ldg((const float4*)g_gout + ((size_t)g * NP_G + node) * 64 + c);
}

// ------------- semantic attention: wsum[m] += tanh(zs@W+b)@q ----------------
// 80000 rows flat; block 64 rows x 256 cols; thread tile 8x8 (FFMA2, col pairs)
__global__ __launch_bounds__(256) void k_sem(
    const float* __restrict__ semW, const float* __restrict__ semb,
    const float* __restrict__ semq)
{
    __shared__ __align__(16) float2 ft2[16][64];   // 8 KB (duplicated rows)
    __shared__ __align__(16) float  wt[16][256];   // 16 KB
    __shared__ float bo_s[256], qo_s[256];
    __shared__ float rowsum[64];
    __shared__ float bucket[4];

    int base = blockIdx.x * 64;     // 1250 blocks exactly
    int b = base / (2 * T_TGT);
    const float* W = semW + (size_t)b * D * D;
    int tid = threadIdx.x;
    int rg = tid >> 5, cg = tid & 31;

    if (tid < 64)
        ((float4*)bo_s)[tid] = __ldg((const float4*)(semb + b * D) + tid);
    else if (tid < 128)
        ((float4*)qo_s)[tid - 64] = __ldg((const float4*)(semq + b * D) + tid - 64);
    if (tid < 4) bucket[tid] = 0.f;

    ull acc2[8][4];
#pragma unroll
    for (int a = 0; a < 8; a++)
#pragma unroll
        for (int j = 0; j < 4; j++) acc2[a][j] = 0ull;

    for (int ch = 0; ch < 16; ch++) {              // 16 chunks of 16 k
        __syncthreads();
        {
            int r = tid & 63, q = tid >> 6;
            const float4* fp = (const float4*)(g_meta + ((size_t)base + r) * D) + ch * 4;
            float4 v = __ldg(fp + q);
            ft2[q * 4 + 0][r] = make_float2(v.x, v.x);
            ft2[q * 4 + 1][r] = make_float2(v.y, v.y);
            ft2[q * 4 + 2][r] = make_float2(v.z, v.z);
            ft2[q * 4 + 3][r] = make_float2(v.w, v.w);
        }
        {   // sem_W is k-major: direct copy
            const float4* wp = (const float4*)(W + (size_t)ch * 16 * D);
            float4* wd = (float4*)&wt[0][0];
#pragma unroll
            for (int i = 0; i < 4; i++)
                wd[tid + i * 256] = __ldg(wp + tid + i * 256);
        }
        __syncthreads();
#pragma unroll
        for (int k = 0; k < 16; k++) {
            const ulonglong2* fp = (const ulonglong2*)&ft2[k][rg * 8];
            const ulonglong2* wp = (const ulonglong2*)&wt[k][cg * 8];
            ulonglong2 fa = fp[0], fb = fp[1], fc4 = fp[2], fd = fp[3];
            ull F[8] = {fa.x, fa.y, fb.x, fb.y, fc4.x, fc4.y, fd.x, fd.y};
            ulonglong2 wa = wp[0], wb = wp[1];
            ull Wb[4] = {wa.x, wa.y, wb.x, wb.y};
#pragma unroll
            for (int a = 0; a < 8; a++)
#pragma unroll
                for (int j = 0; j < 4; j++)
                    FMA_F32X2(acc2[a][j], F[a], Wb[j], acc2[a][j]);
        }
    }

    float part[8];
#pragma unroll
    for (int a = 0; a < 8; a++) {
        float c[8];
#pragma unroll
        for (int j = 0; j < 4; j++) {
            c[2 * j] = ulo(acc2[a][j]);
            c[2 * j + 1] = uhi(acc2[a][j]);
        }
        float p = 0.f;
#pragma unroll
        for (int j = 0; j < 8; j++) {
            float x = c[j] + bo_s[cg * 8 + j];
            p += fast_tanh(x) * qo_s[cg * 8 + j];
        }
        part[a] = p;
    }
#pragma unroll
    for (int off = 16; off; off >>= 1)
#pragma unroll
        for (int a = 0; a < 8; a++)
            part[a] += __shfl_down_sync(0xffffffffu, part[a], off);
    if (cg == 0)
#pragma unroll
        for (int a = 0; a < 8; a++) rowsum[rg * 8 + a] = part[a];
    __syncthreads();
    if (tid < 64) {
        int row = base + tid;
        atomicAdd(&bucket[row / T_TGT], rowsum[tid]);
    }
    __syncthreads();
    if (tid < 4 && bucket[tid] != 0.f) atomicAdd(&g_wsum[tid], bucket[tid]);
}

// -------------- combine: beta-blend metas, @ fcout_W + bias -----------------
// block: 128 rows x 64 cols; thread tile 4x8 (FFMA2, row pairs, dup weights)
__global__ __launch_bounds__(256) void k_combine(
    const float* __restrict__ fW, const float* __restrict__ fb,
    float* __restrict__ outp)
{
    __shared__ __align__(16) float  ft[32][128];   // 16 KB
    __shared__ __align__(16) float2 wt2[32][64];   // 16 KB

    int b = blockIdx.y;
    int base = blockIdx.x * 128;
    int tid = threadIdx.x;
    int rg = tid & 31, cg = tid >> 5;

    float w0 = g_wsum[b * 2 + 0] * (1.f / T_TGT);
    float w1 = g_wsum[b * 2 + 1] * (1.f / T_TGT);
    float mx = fmaxf(w0, w1);
    float b0 = __expf(w0 - mx), b1 = __expf(w1 - mx);
    float sm = b0 + b1;
    b0 /= sm; b1 /= sm;

    const float* m0 = g_meta + ((size_t)(b * 2 + 0) * T_TGT) * D;
    const float* m1 = g_meta + ((size_t)(b * 2 + 1) * T_TGT) * D;
    const float* W = fW + (size_t)b * D * OUT_DIM;

    ull acc2[2][8];
#pragma unroll
    for (int p = 0; p < 2; p++)
#pragma unroll
        for (int j = 0; j < 8; j++) acc2[p][j] = 0ull;

    for (int ch = 0; ch < 8; ch++) {               // 8 chunks of 32 k
        __syncthreads();
        {
            int r = tid & 127, qb = tid >> 7;
            int row = base + r;
            bool val = row < T_TGT;
            const float4* p0 = (const float4*)(m0 + (size_t)row * D) + ch * 8;
            const float4* p1 = (const float4*)(m1 + (size_t)row * D) + ch * 8;
#pragma unroll
            for (int i = 0; i < 4; i++) {
                int q = qb + i * 2;
                float4 v0 = val ? __ldg(p0 + q) : make_float4(0.f, 0.f, 0.f, 0.f);
                float4 v1 = val ? __ldg(p1 + q) : make_float4(0.f, 0.f, 0.f, 0.f);
                ft[q * 4 + 0][r] = b0 * v0.x + b1 * v1.x;
                ft[q * 4 + 1][r] = b0 * v0.y + b1 * v1.y;
                ft[q * 4 + 2][r] = b0 * v0.z + b1 * v1.z;
                ft[q * 4 + 3][r] = b0 * v0.w + b1 * v1.w;
            }
        }
        {   // fcout_W is k-major: W[k][o]; duplicate into wt2
            int o = tid & 63, qb = tid >> 6;       // qb 0..3 over k-groups
#pragma unroll
            for (int i = 0; i < 2; i++) {
                int kk = qb + i * 4;               // 8 k-rows of 4
                const float4* wp = (const float4*)(W + (size_t)(ch * 32 + kk * 4) * OUT_DIM);
                // load 4 consecutive k rows at col o? strided; simpler: scalar dup
                float va = __ldg(&W[(size_t)(ch * 32 + kk * 4 + 0) * OUT_DIM + o]);
                float vb = __ldg(&W[(size_t)(ch * 32 + kk * 4 + 1) * OUT_DIM + o]);
                float vc = __ldg(&W[(size_t)(ch * 32 + kk * 4 + 2) * OUT_DIM + o]);
                float vd = __ldg(&W[(size_t)(ch * 32 + kk * 4 + 3) * OUT_DIM + o]);
                (void)wp;
                wt2[kk * 4 + 0][o] = make_float2(va, va);
                wt2[kk * 4 + 1][o] = make_float2(vb, vb);
                wt2[kk * 4 + 2][o] = make_float2(vc, vc);
                wt2[kk * 4 + 3][o] = make_float2(vd, vd);
            }
        }
        __syncthreads();
#pragma unroll
        for (int k = 0; k < 32; k++) {
            const ulonglong2* fp = (const ulonglong2*)&ft[k][rg * 4];
            const ulonglong2* wp = (const ulonglong2*)&wt2[k][cg * 8];
            ulonglong2 fv = fp[0];
            ull F[2] = {fv.x, fv.y};
            ulonglong2 wq0 = wp[0], wq1 = wp[1], wq2 = wp[2], wq3 = wp[3];
            ull Wb[8] = {wq0.x, wq0.y, wq1.x, wq1.y, wq2.x, wq2.y, wq3.x, wq3.y};
#pragma unroll
            for (int p = 0; p < 2; p++)
#pragma unroll
                for (int j = 0; j < 8; j++)
                    FMA_F32X2(acc2[p][j], F[p], Wb[j], acc2[p][j]);
        }
    }
    float bo[8];
#pragma unroll
    for (int j = 0; j < 8; j++) bo[j] = __ldg(&fb[b * OUT_DIM + cg * 8 + j]);
#pragma unroll
    for (int p = 0; p < 2; p++) {
#pragma unroll
        for (int h = 0; h < 2; h++) {
            int row = base + rg * 4 + p * 2 + h;
            if (row < T_TGT) {
                float c[8];
#pragma unroll
                for (int j = 0; j < 8; j++)
                    c[j] = (h ? uhi(acc2[p][j]) : ulo(acc2[p][j])) + bo[j];
                float* op = outp + ((size_t)b * T_TGT + row) * OUT_DIM + cg * 8;
                *(float4*)op = make_float4(c[0], c[1], c[2], c[3]);
                *((float4*)op + 1) = make_float4(c[4], c[5], c[6], c[7]);
            }
        }
    }
}

// ------------------------------- launch -------------------------------------
extern "C" void kernel_launch(void* const* d_in, const int* in_sizes, int n_in,
                              void* d_out, int out_size)
{
    const float* features0 = (const float*)d_in[0];
    const float* features1 = (const float*)d_in[1];
    const float* fc_W      = (const float*)d_in[2];
    const float* fc_b      = (const float*)d_in[3];
    const float* gat_W     = (const float*)d_in[4];
    const float* attn_l    = (const float*)d_in[5];
    const float* attn_r    = (const float*)d_in[6];
    const float* sem_W     = (const float*)d_in[7];
    const float* sem_b     = (const float*)d_in[8];
    const float* sem_q     = (const float*)d_in[9];
    const float* fcout_W   = (const float*)d_in[10];
    const float* fcout_b   = (const float*)d_in[11];
    const int*   type_idx  = (const int*)d_in[12];
    const int*   node_idx  = (const int*)d_in[13];
    const int*   edge_src  = (const int*)d_in[14];
    const int*   edge_dst  = (const int*)d_in[15];
    const int*   tgt_idx   = (const int*)d_in[16];
    float* out = (float*)d_out;

    k_init<<<(G4 * NP_G + 255) / 256, 256>>>();
    k_fc<<<dim3((NP_TYPE + 127) / 128, 2), 256>>>(features0, features1, fc_W, fc_b, type_idx);
    k_gatz<<<dim3((NP_G + 63) / 64, G4), 256>>>(node_idx, gat_W, attn_l, attn_r);
    k_count<<<(G4 * E_G + 255) / 256, 256>>>(edge_dst);
    k_scan<<<G4, 1024>>>();
    k_fill<<<(G4 * E_G + 255) / 256, 256>>>(edge_src, edge_dst);
    k_aggregate<<<(G4 * NP_G) / 8, 256>>>();
    k_gather<<<(G4 * T_TGT) / 4, 256>>>(tgt_idx);
    k_sem<<<(G4 * T_TGT) / 64, 256>>>(sem_W, sem_b, sem_q);
    k_combine<<<dim3((T_TGT + 127) / 128, 2), 256>>>(fcout_W, fcout_b, out);
}

// round 5
// speedup vs baseline: 1.3022x; 1.3022x over previous
#include <cuda_runtime.h>
#include <math.h>

#define N_TOTAL 100000
#define NP_TYPE 50000
#define NP_G    50000
#define E_G     500000
#define NH      4
#define HD      64
#define HID     64
#define D       256
#define OUT_DIM 64
#define T_TGT   20000
#define G4      4

// ------------------------- scratch (static device globals) -------------------
__device__ float  g_transformed[N_TOTAL * HID];          // 25.6 MB
__device__ float  g_z[(size_t)G4 * NP_G * D];            // 204.8 MB
__device__ float  g_el[G4 * NP_G * NH];
__device__ float  g_er[G4 * NP_G * NH];
__device__ int    g_deg[G4 * NP_G];
__device__ int    g_offs[G4 * (NP_G + 1)];
__device__ int    g_cur[G4 * NP_G];
__device__ int    g_csr_src[G4 * E_G];
__device__ float4 g_csr_ex[G4 * E_G];                    // 32 MB
__device__ float  g_meta[(size_t)G4 * T_TGT * D];        // 81.9 MB
__device__ float  g_wsum[4];

__device__ __forceinline__ float fast_tanh(float x) {
    float y;
    asm("tanh.approx.f32 %0, %1;" : "=f"(y) : "f"(x));
    return y;
}

// ------------------------------- init ---------------------------------------
__global__ void k_init() {
    int i = blockIdx.x * blockDim.x + threadIdx.x;
    if (i < G4 * NP_G) g_deg[i] = 0;
    if (i < 4) g_wsum[i] = 0.f;
}

// --------------------------- fc: type-wise linear ---------------------------
// block: 128 rows x 64 cols; 256 threads; thread tile 4 rows x 8 cols
__global__ __launch_bounds__(256) void k_fc(
    const float* __restrict__ f0, const float* __restrict__ f1,
    const float* __restrict__ fcW, const float* __restrict__ fcb,
    const int* __restrict__ type_idx)
{
    __shared__ float ft[64][128];   // 32 KB
    __shared__ float wt[64][64];    // 16 KB

    int t = blockIdx.y;
    int base = blockIdx.x * 128;
    const float* feat = t ? f1 : f0;
    const float* W = fcW + (size_t)t * HID * D;          // W[o][k]
    int tid = threadIdx.x;
    int rg = tid & 31, cg = tid >> 5;

    float acc[4][8];
#pragma unroll
    for (int a = 0; a < 4; a++)
#pragma unroll
        for (int j = 0; j < 8; j++) acc[a][j] = 0.f;

    for (int ch = 0; ch < 4; ch++) {
        __syncthreads();
        {   // ft[k][r] transpose-load: 128 rows x 64 k
            int r = tid & 127, qb = tid >> 7;
            int row = base + r;
            bool val = row < NP_TYPE;
            const float4* fp = (const float4*)(feat + (size_t)row * D) + ch * 16;
#pragma unroll
            for (int i = 0; i < 8; i++) {
                int q = qb + i * 2;
                float4 v = val ? __ldg(fp + q) : make_float4(0.f, 0.f, 0.f, 0.f);
                ft[q * 4 + 0][r] = v.x; ft[q * 4 + 1][r] = v.y;
                ft[q * 4 + 2][r] = v.z; ft[q * 4 + 3][r] = v.w;
            }
        }
        {   // wt[k][o] transpose-load from W[o][k]
            int o = tid & 63, qb = tid >> 6;
            const float4* wp = (const float4*)(W + (size_t)o * D) + ch * 16;
#pragma unroll
            for (int i = 0; i < 4; i++) {
                int q = qb + i * 4;
                float4 v = __ldg(wp + q);
                wt[q * 4 + 0][o] = v.x; wt[q * 4 + 1][o] = v.y;
                wt[q * 4 + 2][o] = v.z; wt[q * 4 + 3][o] = v.w;
            }
        }
        __syncthreads();
#pragma unroll 16
        for (int k = 0; k < 64; k++) {
            float4 fv = *(const float4*)&ft[k][rg * 4];
            float4 w0 = *(const float4*)&wt[k][cg * 8];
            float4 w1 = *(const float4*)&wt[k][cg * 8 + 4];
            float fr[4] = {fv.x, fv.y, fv.z, fv.w};
            float wc[8] = {w0.x, w0.y, w0.z, w0.w, w1.x, w1.y, w1.z, w1.w};
#pragma unroll
            for (int a = 0; a < 4; a++)
#pragma unroll
                for (int j = 0; j < 8; j++) acc[a][j] += fr[a] * wc[j];
        }
    }
    float bo[8];
#pragma unroll
    for (int j = 0; j < 8; j++) bo[j] = __ldg(&fcb[t * HID + cg * 8 + j]);
    const int* ti = type_idx + t * NP_TYPE;
#pragma unroll
    for (int a = 0; a < 4; a++) {
        int row = base + rg * 4 + a;
        if (row < NP_TYPE) {
            int dst = __ldg(&ti[row]);
            float* op = g_transformed + (size_t)dst * HID + cg * 8;
            *(float4*)op = make_float4(acc[a][0] + bo[0], acc[a][1] + bo[1],
                                       acc[a][2] + bo[2], acc[a][3] + bo[3]);
            *((float4*)op + 1) = make_float4(acc[a][4] + bo[4], acc[a][5] + bo[5],
                                             acc[a][6] + bo[6], acc[a][7] + bo[7]);
        }
    }
}

// ------------- gatz (+fused el/er): z = gather(transformed) @ gat_W ---------
// block: 64 rows x 256 cols; 256 threads; thread tile 8 rows x 8 cols
__global__ __launch_bounds__(256) void k_gatz(
    const int* __restrict__ node_idx, const float* __restrict__ gatW,
    const float* __restrict__ attn_l, const float* __restrict__ attn_r)
{
    __shared__ float ft[32][64];    // 8 KB
    __shared__ float wt[32][256];   // 32 KB
    __shared__ int   nd[64];
    __shared__ float al_s[256], ar_s[256];

    int g = blockIdx.y;
    int base = blockIdx.x * 64;
    int tid = threadIdx.x;
    int rg = tid >> 5, cg = tid & 31;   // warp-uniform rg, lane = cg

    if (tid < 64) {
        int rr = base + tid;
        nd[tid] = (rr < NP_G) ? __ldg(&node_idx[(size_t)g * NP_G + rr]) : -1;
    } else if (tid < 128) {
        ((float4*)al_s)[tid - 64] = __ldg((const float4*)(attn_l + (size_t)g * D) + tid - 64);
    } else if (tid < 192) {
        ((float4*)ar_s)[tid - 128] = __ldg((const float4*)(attn_r + (size_t)g * D) + tid - 128);
    }

    float acc[8][8];
#pragma unroll
    for (int a = 0; a < 8; a++)
#pragma unroll
        for (int j = 0; j < 8; j++) acc[a][j] = 0.f;

    for (int ch = 0; ch < 2; ch++) {
        __syncthreads();
        {   // ft[k][r]: 64 rows x 32 k (gathered)
            int r = tid & 63, qb = tid >> 6;
            int node = nd[r];
#pragma unroll
            for (int i = 0; i < 2; i++) {
                int q = qb + i * 4;
                float4 v = (node >= 0)
                    ? __ldg((const float4*)(g_transformed + (size_t)node * HID) + ch * 8 + q)
                    : make_float4(0.f, 0.f, 0.f, 0.f);
                ft[q * 4 + 0][r] = v.x; ft[q * 4 + 1][r] = v.y;
                ft[q * 4 + 2][r] = v.z; ft[q * 4 + 3][r] = v.w;
            }
        }
        {   // wt direct copy (gat_W is k-major: W[k][o])
            const float4* wp = (const float4*)(gatW + (size_t)g * HID * D + (size_t)ch * 32 * D);
            float4* wd = (float4*)&wt[0][0];
#pragma unroll
            for (int i = 0; i < 8; i++)
                wd[tid + i * 256] = __ldg(wp + tid + i * 256);
        }
        __syncthreads();
#pragma unroll 8
        for (int k = 0; k < 32; k++) {
            float4 f0 = *(const float4*)&ft[k][rg * 8];
            float4 f1 = *(const float4*)&ft[k][rg * 8 + 4];
            float4 w0 = *(const float4*)&wt[k][cg * 8];
            float4 w1 = *(const float4*)&wt[k][cg * 8 + 4];
            float fr[8] = {f0.x, f0.y, f0.z, f0.w, f1.x, f1.y, f1.z, f1.w};
            float wc[8] = {w0.x, w0.y, w0.z, w0.w, w1.x, w1.y, w1.z, w1.w};
#pragma unroll
            for (int a = 0; a < 8; a++)
#pragma unroll
                for (int j = 0; j < 8; j++) acc[a][j] += fr[a] * wc[j];
        }
    }

    // stores + fused el/er (head = cg>>3, cols cg*8..cg*8+7 all in one head)
#pragma unroll
    for (int a = 0; a < 8; a++) {
        int row = base + rg * 8 + a;
        bool valid = row < NP_G;
        if (valid) {
            float* zp = g_z + ((size_t)g * NP_G + row) * D + cg * 8;
            *(float4*)zp = make_float4(acc[a][0], acc[a][1], acc[a][2], acc[a][3]);
            *((float4*)zp + 1) = make_float4(acc[a][4], acc[a][5], acc[a][6], acc[a][7]);
        }
        float pl = 0.f, pr = 0.f;
#pragma unroll
        for (int j = 0; j < 8; j++) {
            float zv = acc[a][j];
            pl += zv * al_s[cg * 8 + j];
            pr += zv * ar_s[cg * 8 + j];
        }
#pragma unroll
        for (int off = 4; off; off >>= 1) {
            pl += __shfl_down_sync(0xffffffffu, pl, off, 8);
            pr += __shfl_down_sync(0xffffffffu, pr, off, 8);
        }
        if ((cg & 7) == 0 && valid) {
            int h = cg >> 3;
            g_el[((size_t)g * NP_G + row) * NH + h] = pl;
            g_er[((size_t)g * NP_G + row) * NH + h] = pr;
        }
    }
}

// ------------------------------- CSR build ----------------------------------
__global__ void k_count(const int* __restrict__ dst) {
    int e = blockIdx.x * blockDim.x + threadIdx.x;
    if (e < G4 * E_G) {
        int g = e / E_G;
        atomicAdd(&g_deg[g * NP_G + __ldg(&dst[e])], 1);
    }
}

// one block per graph; warp-shuffle two-pass scan
__global__ __launch_bounds__(1024) void k_scan() {
    __shared__ int ws[32];
    int g = blockIdx.x;
    int tid = threadIdx.x;
    int lane = tid & 31, wid = tid >> 5;
    const int CH = (NP_G + 1023) / 1024;   // 49
    int lo = tid * CH;
    int hi = min(lo + CH, NP_G);
    const int* deg = g_deg + g * NP_G;
    int s = 0;
    for (int i = lo; i < hi; i++) s += deg[i];
    int v = s;
#pragma unroll
    for (int off = 1; off < 32; off <<= 1) {
        int n = __shfl_up_sync(0xffffffffu, v, off);
        if (lane >= off) v += n;
    }
    if (lane == 31) ws[wid] = v;
    __syncthreads();
    if (wid == 0) {
        int w = ws[lane];
#pragma unroll
        for (int off = 1; off < 32; off <<= 1) {
            int n = __shfl_up_sync(0xffffffffu, w, off);
            if (lane >= off) w += n;
        }
        ws[lane] = w;
    }
    __syncthreads();
    int excl = v - s + (wid ? ws[wid - 1] : 0);
    int* offs = g_offs + g * (NP_G + 1);
    int* cur = g_cur + g * NP_G;
    int run = excl;
    for (int i = lo; i < hi; i++) {
        offs[i] = run;
        cur[i] = run;
        run += deg[i];
    }
    if (tid == 0) offs[NP_G] = E_G;
}

__global__ void k_fill(const int* __restrict__ src, const int* __restrict__ dst) {
    int e = blockIdx.x * blockDim.x + threadIdx.x;
    if (e >= G4 * E_G) return;
    int g = e / E_G;
    int gn = g * NP_G;
    int s = __ldg(&src[e]);
    int d = __ldg(&dst[e]);
    float4 elv = __ldg((const float4*)g_el + gn + s);
    float4 erv = __ldg((const float4*)g_er + gn + d);
    float e0 = elv.x + erv.x, e1 = elv.y + erv.y;
    float e2 = elv.z + erv.z, e3 = elv.w + erv.w;
    e0 = e0 > 0.f ? e0 : 0.2f * e0;
    e1 = e1 > 0.f ? e1 : 0.2f * e1;
    e2 = e2 > 0.f ? e2 : 0.2f * e2;
    e3 = e3 > 0.f ? e3 : 0.2f * e3;
    float4 ex = make_float4(__expf(e0), __expf(e1), __expf(e2), __expf(e3));
    int pos = atomicAdd(&g_cur[gn + d], 1);
    g_csr_src[(size_t)g * E_G + pos] = s;
    g_csr_ex[(size_t)g * E_G + pos] = ex;
}

// ------ aggregate: warp per TARGET, fused softmax, writes meta directly -----
__global__ __launch_bounds__(256) void k_aggregate(const int* __restrict__ tgt) {
    int t = (blockIdx.x * blockDim.x + threadIdx.x) >> 5;
    if (t >= G4 * T_TGT) return;
    int g = t / T_TGT;
    int lane = threadIdx.x & 31;
    int hsel = lane >> 3;
    int nl = __ldg(&tgt[t]);                       // target node in graph g
    int beg = g_offs[g * (NP_G + 1) + nl];
    int end = g_offs[g * (NP_G + 1) + nl + 1];
    const int* cs = g_csr_src + (size_t)g * E_G;
    const float4* ce = g_csr_ex + (size_t)g * E_G;
    const float* zb = g_z + (size_t)g * NP_G * D;

    float4 a0 = {0.f, 0.f, 0.f, 0.f}, a1 = {0.f, 0.f, 0.f, 0.f};
    float den = 0.f;

    int i = beg;
    for (; i + 4 <= end; i += 4) {                 // MLP: 8 z-row LDG.128s in flight
        int s0 = __ldg(cs + i), s1 = __ldg(cs + i + 1);
        int s2 = __ldg(cs + i + 2), s3 = __ldg(cs + i + 3);
        float4 e0 = __ldg(ce + i), e1 = __ldg(ce + i + 1);
        float4 e2 = __ldg(ce + i + 2), e3 = __ldg(ce + i + 3);
        const float4* z0p = (const float4*)(zb + (size_t)s0 * D) + lane * 2;
        const float4* z1p = (const float4*)(zb + (size_t)s1 * D) + lane * 2;
        const float4* z2p = (const float4*)(zb + (size_t)s2 * D) + lane * 2;
        const float4* z3p = (const float4*)(zb + (size_t)s3 * D) + lane * 2;
        float4 za0 = __ldg(z0p), zb0 = __ldg(z0p + 1);
        float4 za1 = __ldg(z1p), zb1 = __ldg(z1p + 1);
        float4 za2 = __ldg(z2p), zb2 = __ldg(z2p + 1);
        float4 za3 = __ldg(z3p), zb3 = __ldg(z3p + 1);
        float x0 = (hsel == 0) ? e0.x : (hsel == 1) ? e0.y : (hsel == 2) ? e0.z : e0.w;
        float x1 = (hsel == 0) ? e1.x : (hsel == 1) ? e1.y : (hsel == 2) ? e1.z : e1.w;
        float x2 = (hsel == 0) ? e2.x : (hsel == 1) ? e2.y : (hsel == 2) ? e2.z : e2.w;
        float x3 = (hsel == 0) ? e3.x : (hsel == 1) ? e3.y : (hsel == 2) ? e3.z : e3.w;
        a0.x += x0 * za0.x; a0.y += x0 * za0.y; a0.z += x0 * za0.z; a0.w += x0 * za0.w;
        a1.x += x0 * zb0.x; a1.y += x0 * zb0.y; a1.z += x0 * zb0.z; a1.w += x0 * zb0.w;
        a0.x += x1 * za1.x; a0.y += x1 * za1.y; a0.z += x1 * za1.z; a0.w += x1 * za1.w;
        a1.x += x1 * zb1.x; a1.y += x1 * zb1.y; a1.z += x1 * zb1.z; a1.w += x1 * zb1.w;
        a0.x += x2 * za2.x; a0.y += x2 * za2.y; a0.z += x2 * za2.z; a0.w += x2 * za2.w;
        a1.x += x2 * zb2.x; a1.y += x2 * zb2.y; a1.z += x2 * zb2.z; a1.w += x2 * zb2.w;
        a0.x += x3 * za3.x; a0.y += x3 * za3.y; a0.z += x3 * za3.z; a0.w += x3 * za3.w;
        a1.x += x3 * zb3.x; a1.y += x3 * zb3.y; a1.z += x3 * zb3.z; a1.w += x3 * zb3.w;
        den += x0 + x1 + x2 + x3;
    }
    for (; i < end; i++) {
        int s0 = __ldg(cs + i);
        float4 e0 = __ldg(ce + i);
        const float4* z0p = (const float4*)(zb + (size_t)s0 * D) + lane * 2;
        float4 za = __ldg(z0p), zc = __ldg(z0p + 1);
        float x0 = (hsel == 0) ? e0.x : (hsel == 1) ? e0.y : (hsel == 2) ? e0.z : e0.w;
        a0.x += x0 * za.x; a0.y += x0 * za.y; a0.z += x0 * za.z; a0.w += x0 * za.w;
        a1.x += x0 * zc.x; a1.y += x0 * zc.y; a1.z += x0 * zc.z; a1.w += x0 * zc.w;
        den += x0;
    }
    float inv = 1.f / (den + 1e-9f);
    float v[8] = {a0.x * inv, a0.y * inv, a0.z * inv, a0.w * inv,
                  a1.x * inv, a1.y * inv, a1.z * inv, a1.w * inv};
#pragma unroll
    for (int j = 0; j < 8; j++) v[j] = v[j] > 0.f ? v[j] : expm1f(v[j]);
    float* op = g_meta + (size_t)t * D + lane * 8;
    *(float4*)op = make_float4(v[0], v[1], v[2], v[3]);
    *((float4*)op + 1) = make_float4(v[4], v[5], v[6], v[7]);
}

// ------------- semantic attention: wsum[m] += tanh(zs@W+b)@q ----------------
// 80000 rows flat; block 64 rows x 256 cols; thread tile 8x8
__global__ __launch_bounds__(256) void k_sem(
    const float* __restrict__ semW, const float* __restrict__ semb,
    const float* __restrict__ semq)
{
    __shared__ float ft[32][64];    // 8 KB
    __shared__ float wt[32][256];   // 32 KB
    __shared__ float bo_s[256], qo_s[256];
    __shared__ float rowsum[64];
    __shared__ float bucket[4];

    int base = blockIdx.x * 64;     // 1250 blocks exactly
    int b = base / (2 * T_TGT);
    const float* W = semW + (size_t)b * D * D;
    int tid = threadIdx.x;
    int rg = tid >> 5, cg = tid & 31;

    if (tid < 64)
        ((float4*)bo_s)[tid] = __ldg((const float4*)(semb + b * D) + tid);
    else if (tid < 128)
        ((float4*)qo_s)[tid - 64] = __ldg((const float4*)(semq + b * D) + tid - 64);
    if (tid < 4) bucket[tid] = 0.f;

    float acc[8][8];
#pragma unroll
    for (int a = 0; a < 8; a++)
#pragma unroll
        for (int j = 0; j < 8; j++) acc[a][j] = 0.f;

    for (int ch = 0; ch < 8; ch++) {
        __syncthreads();
        {
            int r = tid & 63, qb = tid >> 6;
            const float4* fp = (const float4*)(g_meta + ((size_t)base + r) * D) + ch * 8;
#pragma unroll
            for (int i = 0; i < 2; i++) {
                int q = qb + i * 4;
                float4 v = __ldg(fp + q);
                ft[q * 4 + 0][r] = v.x; ft[q * 4 + 1][r] = v.y;
                ft[q * 4 + 2][r] = v.z; ft[q * 4 + 3][r] = v.w;
            }
        }
        {   // sem_W is k-major: direct copy
            const float4* wp = (const float4*)(W + (size_t)ch * 32 * D);
            float4* wd = (float4*)&wt[0][0];
#pragma unroll
            for (int i = 0; i < 8; i++)
                wd[tid + i * 256] = __ldg(wp + tid + i * 256);
        }
        __syncthreads();
#pragma unroll 8
        for (int k = 0; k < 32; k++) {
            float4 f0 = *(const float4*)&ft[k][rg * 8];
            float4 f1 = *(const float4*)&ft[k][rg * 8 + 4];
            float4 w0 = *(const float4*)&wt[k][cg * 8];
            float4 w1 = *(const float4*)&wt[k][cg * 8 + 4];
            float fr[8] = {f0.x, f0.y, f0.z, f0.w, f1.x, f1.y, f1.z, f1.w};
            float wc[8] = {w0.x, w0.y, w0.z, w0.w, w1.x, w1.y, w1.z, w1.w};
#pragma unroll
            for (int a = 0; a < 8; a++)
#pragma unroll
                for (int j = 0; j < 8; j++) acc[a][j] += fr[a] * wc[j];
        }
    }

    float part[8];
#pragma unroll
    for (int a = 0; a < 8; a++) {
        float p = 0.f;
#pragma unroll
        for (int j = 0; j < 8; j++) {
            float x = acc[a][j] + bo_s[cg * 8 + j];
            p += fast_tanh(x) * qo_s[cg * 8 + j];
        }
        part[a] = p;
    }
#pragma unroll
    for (int off = 16; off; off >>= 1)
#pragma unroll
        for (int a = 0; a < 8; a++)
            part[a] += __shfl_down_sync(0xffffffffu, part[a], off);
    if (cg == 0)
#pragma unroll
        for (int a = 0; a < 8; a++) rowsum[rg * 8 + a] = part[a];
    __syncthreads();
    if (tid < 64) {
        int row = base + tid;
        atomicAdd(&bucket[row / T_TGT], rowsum[tid]);
    }
    __syncthreads();
    if (tid < 4 && bucket[tid] != 0.f) atomicAdd(&g_wsum[tid], bucket[tid]);
}

// -------------- combine: beta-blend metas, @ fcout_W + bias -----------------
// block: 128 rows x 64 cols; thread tile 4x8
__global__ __launch_bounds__(256) void k_combine(
    const float* __restrict__ fW, const float* __restrict__ fb,
    float* __restrict__ outp)
{
    __shared__ float ft[64][128];   // 32 KB
    __shared__ float wt[64][64];    // 16 KB

    int b = blockIdx.y;
    int base = blockIdx.x * 128;
    int tid = threadIdx.x;
    int rg = tid & 31, cg = tid >> 5;

    float w0 = g_wsum[b * 2 + 0] * (1.f / T_TGT);
    float w1 = g_wsum[b * 2 + 1] * (1.f / T_TGT);
    float mx = fmaxf(w0, w1);
    float b0 = __expf(w0 - mx), b1 = __expf(w1 - mx);
    float sm = b0 + b1;
    b0 /= sm; b1 /= sm;

    const float* m0 = g_meta + ((size_t)(b * 2 + 0) * T_TGT) * D;
    const float* m1 = g_meta + ((size_t)(b * 2 + 1) * T_TGT) * D;
    const float* W = fW + (size_t)b * D * OUT_DIM;

    float acc[4][8];
#pragma unroll
    for (int a = 0; a < 4; a++)
#pragma unroll
        for (int j = 0; j < 8; j++) acc[a][j] = 0.f;

    for (int ch = 0; ch < 4; ch++) {
        __syncthreads();
        {
            int r = tid & 127, qb = tid >> 7;
            int row = base + r;
            bool val = row < T_TGT;
            const float4* p0 = (const float4*)(m0 + (size_t)row * D) + ch * 16;
            const float4* p1 = (const float4*)(m1 + (size_t)row * D) + ch * 16;
#pragma unroll
            for (int i = 0; i < 8; i++) {
                int q = qb + i * 2;
                float4 v0 = val ? __ldg(p0 + q) : make_float4(0.f, 0.f, 0.f, 0.f);
                float4 v1 = val ? __ldg(p1 + q) : make_float4(0.f, 0.f, 0.f, 0.f);
                ft[q * 4 + 0][r] = b0 * v0.x + b1 * v1.x;
                ft[q * 4 + 1][r] = b0 * v0.y + b1 * v1.y;
                ft[q * 4 + 2][r] = b0 * v0.z + b1 * v1.z;
                ft[q * 4 + 3][r] = b0 * v0.w + b1 * v1.w;
            }
        }
        {   // fcout_W is k-major: direct copy
            const float4* wp = (const float4*)(W + (size_t)ch * 64 * OUT_DIM);
            float4* wd = (float4*)&wt[0][0];
#pragma unroll
            for (int i = 0; i < 4; i++)
                wd[tid + i * 256] = __ldg(wp + tid + i * 256);
        }
        __syncthreads();
#pragma unroll 16
        for (int k = 0; k < 64; k++) {
            float4 fv = *(const float4*)&ft[k][rg * 4];
            float4 wv0 = *(const float4*)&wt[k][cg * 8];
            float4 wv1 = *(const float4*)&wt[k][cg * 8 + 4];
            float fr[4] = {fv.x, fv.y, fv.z, fv.w};
            float wc[8] = {wv0.x, wv0.y, wv0.z, wv0.w, wv1.x, wv1.y, wv1.z, wv1.w};
#pragma unroll
            for (int a = 0; a < 4; a++)
#pragma unroll
                for (int j = 0; j < 8; j++) acc[a][j] += fr[a] * wc[j];
        }
    }
    float bo[8];
#pragma unroll
    for (int j = 0; j < 8; j++) bo[j] = __ldg(&fb[b * OUT_DIM + cg * 8 + j]);
#pragma unroll
    for (int a = 0; a < 4; a++) {
        int row = base + rg * 4 + a;
        if (row < T_TGT) {
            float* op = outp + ((size_t)b * T_TGT + row) * OUT_DIM + cg * 8;
            *(float4*)op = make_float4(acc[a][0] + bo[0], acc[a][1] + bo[1],
                                       acc[a][2] + bo[2], acc[a][3] + bo[3]);
            *((float4*)op + 1) = make_float4(acc[a][4] + bo[4], acc[a][5] + bo[5],
                                             acc[a][6] + bo[6], acc[a][7] + bo[7]);
        }
    }
}

// ------------------------------- launch -------------------------------------
extern "C" void kernel_launch(void* const* d_in, const int* in_sizes, int n_in,
                              void* d_out, int out_size)
{
    const float* features0 = (const float*)d_in[0];
    const float* features1 = (const float*)d_in[1];
    const float* fc_W      = (const float*)d_in[2];
    const float* fc_b      = (const float*)d_in[3];
    const float* gat_W     = (const float*)d_in[4];
    const float* attn_l    = (const float*)d_in[5];
    const float* attn_r    = (const float*)d_in[6];
    const float* sem_W     = (const float*)d_in[7];
    const float* sem_b     = (const float*)d_in[8];
    const float* sem_q     = (const float*)d_in[9];
    const float* fcout_W   = (const float*)d_in[10];
    const float* fcout_b   = (const float*)d_in[11];
    const int*   type_idx  = (const int*)d_in[12];
    const int*   node_idx  = (const int*)d_in[13];
    const int*   edge_src  = (const int*)d_in[14];
    const int*   edge_dst  = (const int*)d_in[15];
    const int*   tgt_idx   = (const int*)d_in[16];
    float* out = (float*)d_out;

    // side stream + events, created once (first call is outside graph capture)
    static cudaStream_t s_side = nullptr;
    static cudaEvent_t ev_fork = nullptr, ev_join = nullptr;
    if (!s_side) {
        cudaStreamCreateWithFlags(&s_side, cudaStreamNonBlocking);
        cudaEventCreateWithFlags(&ev_fork, cudaEventDisableTiming);
        cudaEventCreateWithFlags(&ev_join, cudaEventDisableTiming);
    }

    k_init<<<(G4 * NP_G + 255) / 256, 256>>>();

    // fork: CSR count+scan (depends only on edge_dst + zeroed deg) overlaps the GEMMs
    cudaEventRecord(ev_fork, 0);
    cudaStreamWaitEvent(s_side, ev_fork, 0);
    k_count<<<(G4 * E_G + 255) / 256, 256, 0, s_side>>>(edge_dst);
    k_scan<<<G4, 1024, 0, s_side>>>();
    cudaEventRecord(ev_join, s_side);

    k_fc<<<dim3((NP_TYPE + 127) / 128, 2), 256>>>(features0, features1, fc_W, fc_b, type_idx);
    k_gatz<<<dim3((NP_G + 63) / 64, G4), 256>>>(node_idx, gat_W, attn_l, attn_r);

    // join: fill needs el/er (gatz) + offs/cur (scan)
    cudaStreamWaitEvent(0, ev_join, 0);
    k_fill<<<(G4 * E_G + 255) / 256, 256>>>(edge_src, edge_dst);
    k_aggregate<<<(G4 * T_TGT) / 8, 256>>>(tgt_idx);
    k_sem<<<(G4 * T_TGT) / 64, 256>>>(sem_W, sem_b, sem_q);
    k_combine<<<dim3((T_TGT + 127) / 128, 2), 256>>>(fcout_W, fcout_b, out);
}

// round 8
// speedup vs baseline: 1.5599x; 1.1980x over previous
#include <cuda_runtime.h>
#include <cuda_bf16.h>
#include <cuda_fp16.h>
#include <math.h>
#include <stdint.h>

#define N_TOTAL 100000
#define NP_TYPE 50000
#define NP_G    50000
#define E_G     500000
#define NH      4
#define HD      64
#define HID     64
#define D       256
#define OUT_DIM 64
#define T_TGT   20000
#define G4      4

// ------------------------- scratch (static device globals) -------------------
__device__ float  g_transformed[N_TOTAL * HID];          // 25.6 MB
__device__ float  g_z[(size_t)G4 * NP_G * D];            // 204.8 MB
__device__ float  g_el[G4 * NP_G * NH];
__device__ float  g_er[G4 * NP_G * NH];
__device__ int    g_deg[G4 * NP_G];
__device__ int    g_offs[G4 * (NP_G + 1)];
__device__ int    g_cur[G4 * NP_G];
__device__ int    g_csr_src[G4 * E_G];
__device__ float4 g_csr_ex[G4 * E_G];                    // 32 MB
__device__ float  g_meta[(size_t)G4 * T_TGT * D];        // 81.9 MB
__device__ float  g_wsum[4];

// ------------------------------ small helpers --------------------------------
__device__ __forceinline__ uint32_t smem_u32(const void* p) {
    uint32_t a;
    asm("{ .reg .u64 t; cvta.to.shared.u64 t, %1; cvt.u32.u64 %0, t; }" : "=r"(a) : "l"(p));
    return a;
}
__device__ __forceinline__ uint32_t pack_bf16(float lo, float hi) {
    uint32_t r;
    asm("cvt.rn.bf16x2.f32 %0, %1, %2;" : "=r"(r) : "f"(hi), "f"(lo));
    return r;
}
__device__ __forceinline__ uint32_t pack_f16(float lo, float hi) {
    uint32_t r;
    asm("cvt.rn.f16x2.f32 %0, %1, %2;" : "=r"(r) : "f"(hi), "f"(lo));
    return r;
}
// packed tanh epilogue term: sum over 2 cols of tanh(x)*q  (fp16 path; MUFU x1)
__device__ __forceinline__ float tanh_dot2(float x0, float x1, uint32_t qh) {
    uint32_t xp = pack_f16(x0, x1), tp, pp;
    asm("tanh.approx.f16x2 %0, %1;" : "=r"(tp) : "r"(xp));
    asm("mul.f16x2 %0, %1, %2;" : "=r"(pp) : "r"(tp), "r"(qh));
    __half2 h = *reinterpret_cast<__half2*>(&pp);
    return __low2float(h) + __high2float(h);
}
__device__ __forceinline__ void ldsm_x4(uint32_t& r0, uint32_t& r1, uint32_t& r2,
                                        uint32_t& r3, uint32_t addr) {
    asm volatile("ldmatrix.sync.aligned.m8n8.x4.shared.b16 {%0,%1,%2,%3}, [%4];"
                 : "=r"(r0), "=r"(r1), "=r"(r2), "=r"(r3) : "r"(addr));
}
__device__ __forceinline__ void mma_bf16(float* c, uint32_t a0, uint32_t a1,
                                         uint32_t a2, uint32_t a3,
                                         uint32_t b0, uint32_t b1) {
    asm volatile(
        "mma.sync.aligned.m16n8k16.row.col.f32.bf16.bf16.f32 "
        "{%0,%1,%2,%3}, {%4,%5,%6,%7}, {%8,%9}, {%0,%1,%2,%3};"
        : "+f"(c[0]), "+f"(c[1]), "+f"(c[2]), "+f"(c[3])
        : "r"(a0), "r"(a1), "r"(a2), "r"(a3), "r"(b0), "r"(b1));
}

// k_sem_mma dynamic smem layout
#define SEMM_AS   264                         // A bf16 row stride (pad 8)
#define SEMM_WS   40                          // W bf16 row stride (pad 8)
#define SEMM_A_B  (64 * SEMM_AS * 2)          // 33792
#define SEMM_W_O  SEMM_A_B
#define SEMM_W_B  (256 * SEMM_WS * 2)         // 20480
#define SEMM_BO_O (SEMM_W_O + SEMM_W_B)       // 54272
#define SEMM_QH_O (SEMM_BO_O + 1024)          // 55296
#define SEMM_BK_O (SEMM_QH_O + 512)           // 55808
#define SEMM_SZ   (SEMM_BK_O + 128)           // 55936

// ------------------------------- init ---------------------------------------
__global__ void k_init() {
    int i = blockIdx.x * blockDim.x + threadIdx.x;
    if (i < G4 * NP_G) g_deg[i] = 0;
    if (i < 4) g_wsum[i] = 0.f;
}

// --------------------------- fc: type-wise linear ---------------------------
__global__ __launch_bounds__(256) void k_fc(
    const float* __restrict__ f0, const float* __restrict__ f1,
    const float* __restrict__ fcW, const float* __restrict__ fcb,
    const int* __restrict__ type_idx)
{
    __shared__ float ft[64][128];   // 32 KB
    __shared__ float wt[64][64];    // 16 KB

    int t = blockIdx.y;
    int base = blockIdx.x * 128;
    const float* feat = t ? f1 : f0;
    const float* W = fcW + (size_t)t * HID * D;          // W[o][k]
    int tid = threadIdx.x;
    int rg = tid & 31, cg = tid >> 5;

    float acc[4][8];
#pragma unroll
    for (int a = 0; a < 4; a++)
#pragma unroll
        for (int j = 0; j < 8; j++) acc[a][j] = 0.f;

    for (int ch = 0; ch < 4; ch++) {
        __syncthreads();
        {
            int r = tid & 127, qb = tid >> 7;
            int row = base + r;
            bool val = row < NP_TYPE;
            const float4* fp = (const float4*)(feat + (size_t)row * D) + ch * 16;
#pragma unroll
            for (int i = 0; i < 8; i++) {
                int q = qb + i * 2;
                float4 v = val ? __ldg(fp + q) : make_float4(0.f, 0.f, 0.f, 0.f);
                ft[q * 4 + 0][r] = v.x; ft[q * 4 + 1][r] = v.y;
                ft[q * 4 + 2][r] = v.z; ft[q * 4 + 3][r] = v.w;
            }
        }
        {
            int o = tid & 63, qb = tid >> 6;
            const float4* wp = (const float4*)(W + (size_t)o * D) + ch * 16;
#pragma unroll
            for (int i = 0; i < 4; i++) {
                int q = qb + i * 4;
                float4 v = __ldg(wp + q);
                wt[q * 4 + 0][o] = v.x; wt[q * 4 + 1][o] = v.y;
                wt[q * 4 + 2][o] = v.z; wt[q * 4 + 3][o] = v.w;
            }
        }
        __syncthreads();
#pragma unroll 16
        for (int k = 0; k < 64; k++) {
            float4 fv = *(const float4*)&ft[k][rg * 4];
            float4 w0 = *(const float4*)&wt[k][cg * 8];
            float4 w1 = *(const float4*)&wt[k][cg * 8 + 4];
            float fr[4] = {fv.x, fv.y, fv.z, fv.w};
            float wc[8] = {w0.x, w0.y, w0.z, w0.w, w1.x, w1.y, w1.z, w1.w};
#pragma unroll
            for (int a = 0; a < 4; a++)
#pragma unroll
                for (int j = 0; j < 8; j++) acc[a][j] += fr[a] * wc[j];
        }
    }
    float bo[8];
#pragma unroll
    for (int j = 0; j < 8; j++) bo[j] = __ldg(&fcb[t * HID + cg * 8 + j]);
    const int* ti = type_idx + t * NP_TYPE;
#pragma unroll
    for (int a = 0; a < 4; a++) {
        int row = base + rg * 4 + a;
        if (row < NP_TYPE) {
            int dst = __ldg(&ti[row]);
            float* op = g_transformed + (size_t)dst * HID + cg * 8;
            *(float4*)op = make_float4(acc[a][0] + bo[0], acc[a][1] + bo[1],
                                       acc[a][2] + bo[2], acc[a][3] + bo[3]);
            *((float4*)op + 1) = make_float4(acc[a][4] + bo[4], acc[a][5] + bo[5],
                                             acc[a][6] + bo[6], acc[a][7] + bo[7]);
        }
    }
}

// ------------- gatz (+fused el/er): z = gather(transformed) @ gat_W ---------
__global__ __launch_bounds__(256) void k_gatz(
    const int* __restrict__ node_idx, const float* __restrict__ gatW,
    const float* __restrict__ attn_l, const float* __restrict__ attn_r)
{
    __shared__ float ft[32][64];    // 8 KB
    __shared__ float wt[32][256];   // 32 KB
    __shared__ int   nd[64];
    __shared__ float al_s[256], ar_s[256];

    int g = blockIdx.y;
    int base = blockIdx.x * 64;
    int tid = threadIdx.x;
    int rg = tid >> 5, cg = tid & 31;

    if (tid < 64) {
        int rr = base + tid;
        nd[tid] = (rr < NP_G) ? __ldg(&node_idx[(size_t)g * NP_G + rr]) : -1;
    } else if (tid < 128) {
        ((float4*)al_s)[tid - 64] = __ldg((const float4*)(attn_l + (size_t)g * D) + tid - 64);
    } else if (tid < 192) {
        ((float4*)ar_s)[tid - 128] = __ldg((const float4*)(attn_r + (size_t)g * D) + tid - 128);
    }

    float acc[8][8];
#pragma unroll
    for (int a = 0; a < 8; a++)
#pragma unroll
        for (int j = 0; j < 8; j++) acc[a][j] = 0.f;

    for (int ch = 0; ch < 2; ch++) {
        __syncthreads();
        {
            int r = tid & 63, qb = tid >> 6;
            int node = nd[r];
#pragma unroll
            for (int i = 0; i < 2; i++) {
                int q = qb + i * 4;
                float4 v = (node >= 0)
                    ? __ldg((const float4*)(g_transformed + (size_t)node * HID) + ch * 8 + q)
                    : make_float4(0.f, 0.f, 0.f, 0.f);
                ft[q * 4 + 0][r] = v.x; ft[q * 4 + 1][r] = v.y;
                ft[q * 4 + 2][r] = v.z; ft[q * 4 + 3][r] = v.w;
            }
        }
        {
            const float4* wp = (const float4*)(gatW + (size_t)g * HID * D + (size_t)ch * 32 * D);
            float4* wd = (float4*)&wt[0][0];
#pragma unroll
            for (int i = 0; i < 8; i++)
                wd[tid + i * 256] = __ldg(wp + tid + i * 256);
        }
        __syncthreads();
#pragma unroll 8
        for (int k = 0; k < 32; k++) {
            float4 f0 = *(const float4*)&ft[k][rg * 8];
            float4 f1 = *(const float4*)&ft[k][rg * 8 + 4];
            float4 w0 = *(const float4*)&wt[k][cg * 8];
            float4 w1 = *(const float4*)&wt[k][cg * 8 + 4];
            float fr[8] = {f0.x, f0.y, f0.z, f0.w, f1.x, f1.y, f1.z, f1.w};
            float wc[8] = {w0.x, w0.y, w0.z, w0.w, w1.x, w1.y, w1.z, w1.w};
#pragma unroll
            for (int a = 0; a < 8; a++)
#pragma unroll
                for (int j = 0; j < 8; j++) acc[a][j] += fr[a] * wc[j];
        }
    }

#pragma unroll
    for (int a = 0; a < 8; a++) {
        int row = base + rg * 8 + a;
        bool valid = row < NP_G;
        if (valid) {
            float* zp = g_z + ((size_t)g * NP_G + row) * D + cg * 8;
            *(float4*)zp = make_float4(acc[a][0], acc[a][1], acc[a][2], acc[a][3]);
            *((float4*)zp + 1) = make_float4(acc[a][4], acc[a][5], acc[a][6], acc[a][7]);
        }
        float pl = 0.f, pr = 0.f;
#pragma unroll
        for (int j = 0; j < 8; j++) {
            float zv = acc[a][j];
            pl += zv * al_s[cg * 8 + j];
            pr += zv * ar_s[cg * 8 + j];
        }
#pragma unroll
        for (int off = 4; off; off >>= 1) {
            pl += __shfl_down_sync(0xffffffffu, pl, off, 8);
            pr += __shfl_down_sync(0xffffffffu, pr, off, 8);
        }
        if ((cg & 7) == 0 && valid) {
            int h = cg >> 3;
            g_el[((size_t)g * NP_G + row) * NH + h] = pl;
            g_er[((size_t)g * NP_G + row) * NH + h] = pr;
        }
    }
}

// ------------------------------- CSR build ----------------------------------
__global__ void k_count(const int* __restrict__ dst) {
    int e = blockIdx.x * blockDim.x + threadIdx.x;
    if (e < G4 * E_G) {
        int g = e / E_G;
        atomicAdd(&g_deg[g * NP_G + __ldg(&dst[e])], 1);
    }
}

__global__ __launch_bounds__(1024) void k_scan() {
    __shared__ int ws[32];
    int g = blockIdx.x;
    int tid = threadIdx.x;
    int lane = tid & 31, wid = tid >> 5;
    const int CH = (NP_G + 1023) / 1024;   // 49
    int lo = tid * CH;
    int hi = min(lo + CH, NP_G);
    const int* deg = g_deg + g * NP_G;
    int s = 0;
    for (int i = lo; i < hi; i++) s += deg[i];
    int v = s;
#pragma unroll
    for (int off = 1; off < 32; off <<= 1) {
        int n = __shfl_up_sync(0xffffffffu, v, off);
        if (lane >= off) v += n;
    }
    if (lane == 31) ws[wid] = v;
    __syncthreads();
    if (wid == 0) {
        int w = ws[lane];
#pragma unroll
        for (int off = 1; off < 32; off <<= 1) {
            int n = __shfl_up_sync(0xffffffffu, w, off);
            if (lane >= off) w += n;
        }
        ws[lane] = w;
    }
    __syncthreads();
    int excl = v - s + (wid ? ws[wid - 1] : 0);
    int* offs = g_offs + g * (NP_G + 1);
    int* cur = g_cur + g * NP_G;
    int run = excl;
    for (int i = lo; i < hi; i++) {
        offs[i] = run;
        cur[i] = run;
        run += deg[i];
    }
    if (tid == 0) offs[NP_G] = E_G;
}

__global__ void k_fill(const int* __restrict__ src, const int* __restrict__ dst) {
    int e = blockIdx.x * blockDim.x + threadIdx.x;
    if (e >= G4 * E_G) return;
    int g = e / E_G;
    int gn = g * NP_G;
    int s = __ldg(&src[e]);
    int d = __ldg(&dst[e]);
    float4 elv = __ldg((const float4*)g_el + gn + s);
    float4 erv = __ldg((const float4*)g_er + gn + d);
    float e0 = elv.x + erv.x, e1 = elv.y + erv.y;
    float e2 = elv.z + erv.z, e3 = elv.w + erv.w;
    e0 = e0 > 0.f ? e0 : 0.2f * e0;
    e1 = e1 > 0.f ? e1 : 0.2f * e1;
    e2 = e2 > 0.f ? e2 : 0.2f * e2;
    e3 = e3 > 0.f ? e3 : 0.2f * e3;
    float4 ex = make_float4(__expf(e0), __expf(e1), __expf(e2), __expf(e3));
    int pos = atomicAdd(&g_cur[gn + d], 1);
    g_csr_src[(size_t)g * E_G + pos] = s;
    g_csr_ex[(size_t)g * E_G + pos] = ex;
}

// ------ aggregate: warp per TARGET, fused softmax, writes meta directly -----
__global__ __launch_bounds__(256) void k_aggregate(const int* __restrict__ tgt) {
    int t = (blockIdx.x * blockDim.x + threadIdx.x) >> 5;
    if (t >= G4 * T_TGT) return;
    int g = t / T_TGT;
    int lane = threadIdx.x & 31;
    int hsel = lane >> 3;
    int nl = __ldg(&tgt[t]);
    int beg = g_offs[g * (NP_G + 1) + nl];
    int end = g_offs[g * (NP_G + 1) + nl + 1];
    const int* cs = g_csr_src + (size_t)g * E_G;
    const float4* ce = g_csr_ex + (size_t)g * E_G;
    const float* zb = g_z + (size_t)g * NP_G * D;

    float4 a0 = {0.f, 0.f, 0.f, 0.f}, a1 = {0.f, 0.f, 0.f, 0.f};
    float den = 0.f;

    int i = beg;
    for (; i + 4 <= end; i += 4) {
        int s0 = __ldg(cs + i), s1 = __ldg(cs + i + 1);
        int s2 = __ldg(cs + i + 2), s3 = __ldg(cs + i + 3);
        float4 e0 = __ldg(ce + i), e1 = __ldg(ce + i + 1);
        float4 e2 = __ldg(ce + i + 2), e3 = __ldg(ce + i + 3);
        const float4* z0p = (const float4*)(zb + (size_t)s0 * D) + lane * 2;
        const float4* z1p = (const float4*)(zb + (size_t)s1 * D) + lane * 2;
        const float4* z2p = (const float4*)(zb + (size_t)s2 * D) + lane * 2;
        const float4* z3p = (const float4*)(zb + (size_t)s3 * D) + lane * 2;
        float4 za0 = __ldg(z0p), zb0 = __ldg(z0p + 1);
        float4 za1 = __ldg(z1p), zb1 = __ldg(z1p + 1);
        float4 za2 = __ldg(z2p), zb2 = __ldg(z2p + 1);
        float4 za3 = __ldg(z3p), zb3 = __ldg(z3p + 1);
        float x0 = (hsel == 0) ? e0.x : (hsel == 1) ? e0.y : (hsel == 2) ? e0.z : e0.w;
        float x1 = (hsel == 0) ? e1.x : (hsel == 1) ? e1.y : (hsel == 2) ? e1.z : e1.w;
        float x2 = (hsel == 0) ? e2.x : (hsel == 1) ? e2.y : (hsel == 2) ? e2.z : e2.w;
        float x3 = (hsel == 0) ? e3.x : (hsel == 1) ? e3.y : (hsel == 2) ? e3.z : e3.w;
        a0.x += x0 * za0.x; a0.y += x0 * za0.y; a0.z += x0 * za0.z; a0.w += x0 * za0.w;
        a1.x += x0 * zb0.x; a1.y += x0 * zb0.y; a1.z += x0 * zb0.z; a1.w += x0 * zb0.w;
        a0.x += x1 * za1.x; a0.y += x1 * za1.y; a0.z += x1 * za1.z; a0.w += x1 * za1.w;
        a1.x += x1 * zb1.x; a1.y += x1 * zb1.y; a1.z += x1 * zb1.z; a1.w += x1 * zb1.w;
        a0.x += x2 * za2.x; a0.y += x2 * za2.y; a0.z += x2 * za2.z; a0.w += x2 * za2.w;
        a1.x += x2 * zb2.x; a1.y += x2 * zb2.y; a1.z += x2 * zb2.z; a1.w += x2 * zb2.w;
        a0.x += x3 * za3.x; a0.y += x3 * za3.y; a0.z += x3 * za3.z; a0.w += x3 * za3.w;
        a1.x += x3 * zb3.x; a1.y += x3 * zb3.y; a1.z += x3 * zb3.z; a1.w += x3 * zb3.w;
        den += x0 + x1 + x2 + x3;
    }
    for (; i < end; i++) {
        int s0 = __ldg(cs + i);
        float4 e0 = __ldg(ce + i);
        const float4* z0p = (const float4*)(zb + (size_t)s0 * D) + lane * 2;
        float4 za = __ldg(z0p), zc = __ldg(z0p + 1);
        float x0 = (hsel == 0) ? e0.x : (hsel == 1) ? e0.y : (hsel == 2) ? e0.z : e0.w;
        a0.x += x0 * za.x; a0.y += x0 * za.y; a0.z += x0 * za.z; a0.w += x0 * za.w;
        a1.x += x0 * zc.x; a1.y += x0 * zc.y; a1.z += x0 * zc.z; a1.w += x0 * zc.w;
        den += x0;
    }
    float inv = 1.f / (den + 1e-9f);
    float v[8] = {a0.x * inv, a0.y * inv, a0.z * inv, a0.w * inv,
                  a1.x * inv, a1.y * inv, a1.z * inv, a1.w * inv};
#pragma unroll
    for (int j = 0; j < 8; j++) v[j] = v[j] > 0.f ? v[j] : expm1f(v[j]);
    float* op = g_meta + (size_t)t * D + lane * 8;
    *(float4*)op = make_float4(v[0], v[1], v[2], v[3]);
    *((float4*)op + 1) = make_float4(v[4], v[5], v[6], v[7]);
}

// ----- semantic attention on mma.sync bf16 HMMA -----------------------------
// grid (625, 2); 256 thr (8 warps). CTA: 64 rows x 256 cols. Warp: 16r x 128c.
// A (64x256 bf16) smem-resident; W^T chunks (256 o x 32 k) per K-chunk.
// Epilogue: packed f16x2 tanh, row-reduce, bucket atomics.
__global__ __launch_bounds__(256) void k_sem_mma(
    const float* __restrict__ semW, const float* __restrict__ semb,
    const float* __restrict__ semq)
{
    extern __shared__ char smem[];
    __nv_bfloat16* ftA = (__nv_bfloat16*)smem;               // [64][264]
    __nv_bfloat16* wt  = (__nv_bfloat16*)(smem + SEMM_W_O);  // [256][40]
    float*    bo_s = (float*)(smem + SEMM_BO_O);             // [256]
    uint32_t* qh_s = (uint32_t*)(smem + SEMM_QH_O);          // [128] packed f16x2
    float*  bucket = (float*)(smem + SEMM_BK_O);             // [2]

    const int BR = 2 * T_TGT;                                // 40000 = 625*64
    int tid = threadIdx.x;
    int wid = tid >> 5, lane = tid & 31;
    int b = blockIdx.y;
    int base = blockIdx.x * 64;                              // all rows valid
    const float* W = semW + (size_t)b * D * D;               // k-major [k][o]

    if (tid < 64) ((float4*)bo_s)[tid] = __ldg((const float4*)(semb + b * D) + tid);
    else if (tid < 192) {
        int j = tid - 64;                                    // 0..127
        float q0 = __ldg(&semq[b * D + 2 * j]);
        float q1 = __ldg(&semq[b * D + 2 * j + 1]);
        qh_s[j] = pack_f16(q0, q1);
    }
    if (tid < 2) bucket[tid] = 0.f;

    // ---- A: 64 rows x 256 cols f32 -> bf16, padded stride 264 ----
    {
        int r = tid >> 2, kq = tid & 3;
        const float* arow = g_meta + ((size_t)b * BR + base + r) * D;
#pragma unroll
        for (int i = 0; i < 8; i++) {
            int k = kq * 64 + i * 8;
            float4 v0 = __ldg((const float4*)(arow + k));
            float4 v1 = __ldg((const float4*)(arow + k) + 1);
            uint4 pk;
            pk.x = pack_bf16(v0.x, v0.y);
            pk.y = pack_bf16(v0.z, v0.w);
            pk.z = pack_bf16(v1.x, v1.y);
            pk.w = pack_bf16(v1.z, v1.w);
            *(uint4*)&ftA[r * SEMM_AS + k] = pk;
        }
    }

    int rw = wid >> 1;            // row group 0..3 (rows rw*16)
    int cw = wid & 1;             // col group 0..1 (cols cw*128)
    float cacc[16][4];
#pragma unroll
    for (int ti = 0; ti < 16; ti++)
#pragma unroll
        for (int j = 0; j < 4; j++) cacc[ti][j] = 0.f;

    // lane-derived ldmatrix addressing
    int a_tile = lane >> 3;
    int a_row = rw * 16 + (lane & 7) + (a_tile & 1) * 8;
    int a_koff = (a_tile >> 1) * 8;
    int b_g = lane >> 3;
    int b_nbase = cw * 128 + (b_g >> 1) * 8 + (lane & 7);
    int b_koff = (b_g & 1) * 8;

    for (int ch = 0; ch < 8; ch++) {
        __syncthreads();                           // prev chunk consumed / A ready
        {   // W^T chunk: wt[o][k] = W[ch*32 + k][o]
            int o = tid;
            const float* wcol = W + (size_t)(ch * 32) * D + o;
            uint32_t* wrow = (uint32_t*)&wt[o * SEMM_WS];
#pragma unroll
            for (int j = 0; j < 16; j++) {
                float va = __ldg(wcol + (size_t)(2 * j) * D);
                float vb = __ldg(wcol + (size_t)(2 * j + 1) * D);
                wrow[j] = pack_bf16(va, vb);
            }
        }
        __syncthreads();
#pragma unroll
        for (int ks = 0; ks < 2; ks++) {
            uint32_t a0, a1, a2, a3;
            ldsm_x4(a0, a1, a2, a3,
                    smem_u32(&ftA[a_row * SEMM_AS + ch * 32 + ks * 16 + a_koff]));
#pragma unroll
            for (int nt = 0; nt < 8; nt++) {
                uint32_t b0, b1, b2, b3;
                ldsm_x4(b0, b1, b2, b3,
                        smem_u32(&wt[(b_nbase + nt * 16) * SEMM_WS + ks * 16 + b_koff]));
                mma_bf16(cacc[nt * 2 + 0], a0, a1, a2, a3, b0, b1);
                mma_bf16(cacc[nt * 2 + 1], a0, a1, a2, a3, b2, b3);
            }
        }
    }

    // ---- epilogue: packed tanh, reduce over lane%4, bucket atomics ----
    int lr = lane >> 2, lc = lane & 3;
    float rs0 = 0.f, rs1 = 0.f;
#pragma unroll
    for (int ti = 0; ti < 16; ti++) {
        int col = cw * 128 + ti * 8 + lc * 2;
        uint32_t qh = qh_s[col >> 1];
        float b0v = bo_s[col], b1v = bo_s[col + 1];
        rs0 += tanh_dot2(cacc[ti][0] + b0v, cacc[ti][1] + b1v, qh);
        rs1 += tanh_dot2(cacc[ti][2] + b0v, cacc[ti][3] + b1v, qh);
    }
    rs0 += __shfl_down_sync(0xffffffffu, rs0, 2, 4);
    rs0 += __shfl_down_sync(0xffffffffu, rs0, 1, 4);
    rs1 += __shfl_down_sync(0xffffffffu, rs1, 2, 4);
    rs1 += __shfl_down_sync(0xffffffffu, rs1, 1, 4);
    if (lc == 0) {
        int r0 = base + rw * 16 + lr;
        int r1 = r0 + 8;
        atomicAdd(&bucket[r0 >= T_TGT ? 1 : 0], rs0);
        atomicAdd(&bucket[r1 >= T_TGT ? 1 : 0], rs1);
    }
    __syncthreads();
    if (tid < 2 && bucket[tid] != 0.f) atomicAdd(&g_wsum[b * 2 + tid], bucket[tid]);
}

// -------------- combine: beta-blend metas, @ fcout_W + bias -----------------
__global__ __launch_bounds__(256) void k_combine(
    const float* __restrict__ fW, const float* __restrict__ fb,
    float* __restrict__ outp)
{
    __shared__ float ft[64][128];   // 32 KB
    __shared__ float wt[64][64];    // 16 KB

    int b = blockIdx.y;
    int base = blockIdx.x * 128;
    int tid = threadIdx.x;
    int rg = tid & 31, cg = tid >> 5;

    float w0 = g_wsum[b * 2 + 0] * (1.f / T_TGT);
    float w1 = g_wsum[b * 2 + 1] * (1.f / T_TGT);
    float mx = fmaxf(w0, w1);
    float b0 = __expf(w0 - mx), b1 = __expf(w1 - mx);
    float sm = b0 + b1;
    b0 /= sm; b1 /= sm;

    const float* m0 = g_meta + ((size_t)(b * 2 + 0) * T_TGT) * D;
    const float* m1 = g_meta + ((size_t)(b * 2 + 1) * T_TGT) * D;
    const float* W = fW + (size_t)b * D * OUT_DIM;

    float acc[4][8];
#pragma unroll
    for (int a = 0; a < 4; a++)
#pragma unroll
        for (int j = 0; j < 8; j++) acc[a][j] = 0.f;

    for (int ch = 0; ch < 4; ch++) {
        __syncthreads();
        {
            int r = tid & 127, qb = tid >> 7;
            int row = base + r;
            bool val = row < T_TGT;
            const float4* p0 = (const float4*)(m0 + (size_t)row * D) + ch * 16;
            const float4* p1 = (const float4*)(m1 + (size_t)row * D) + ch * 16;
#pragma unroll
            for (int i = 0; i < 8; i++) {
                int q = qb + i * 2;
                float4 v0 = val ? __ldg(p0 + q) : make_float4(0.f, 0.f, 0.f, 0.f);
                float4 v1 = val ? __ldg(p1 + q) : make_float4(0.f, 0.f, 0.f, 0.f);
                ft[q * 4 + 0][r] = b0 * v0.x + b1 * v1.x;
                ft[q * 4 + 1][r] = b0 * v0.y + b1 * v1.y;
                ft[q * 4 + 2][r] = b0 * v0.z + b1 * v1.z;
                ft[q * 4 + 3][r] = b0 * v0.w + b1 * v1.w;
            }
        }
        {
            const float4* wp = (const float4*)(W + (size_t)ch * 64 * OUT_DIM);
            float4* wd = (float4*)&wt[0][0];
#pragma unroll
            for (int i = 0; i < 4; i++)
                wd[tid + i * 256] = __ldg(wp + tid + i * 256);
        }
        __syncthreads();
#pragma unroll 16
        for (int k = 0; k < 64; k++) {
            float4 fv = *(const float4*)&ft[k][rg * 4];
            float4 wv0 = *(const float4*)&wt[k][cg * 8];
            float4 wv1 = *(const float4*)&wt[k][cg * 8 + 4];
            float fr[4] = {fv.x, fv.y, fv.z, fv.w};
            float wc[8] = {wv0.x, wv0.y, wv0.z, wv0.w, wv1.x, wv1.y, wv1.z, wv1.w};
#pragma unroll
            for (int a = 0; a < 4; a++)
#pragma unroll
                for (int j = 0; j < 8; j++) acc[a][j] += fr[a] * wc[j];
        }
    }
    float bo[8];
#pragma unroll
    for (int j = 0; j < 8; j++) bo[j] = __ldg(&fb[b * OUT_DIM + cg * 8 + j]);
#pragma unroll
    for (int a = 0; a < 4; a++) {
        int row = base + rg * 4 + a;
        if (row < T_TGT) {
            float* op = outp + ((size_t)b * T_TGT + row) * OUT_DIM + cg * 8;
            *(float4*)op = make_float4(acc[a][0] + bo[0], acc[a][1] + bo[1],
                                       acc[a][2] + bo[2], acc[a][3] + bo[3]);
            *((float4*)op + 1) = make_float4(acc[a][4] + bo[4], acc[a][5] + bo[5],
                                             acc[a][6] + bo[6], acc[a][7] + bo[7]);
        }
    }
}

// ------------------------------- launch -------------------------------------
extern "C" void kernel_launch(void* const* d_in, const int* in_sizes, int n_in,
                              void* d_out, int out_size)
{
    const float* features0 = (const float*)d_in[0];
    const float* features1 = (const float*)d_in[1];
    const float* fc_W      = (const float*)d_in[2];
    const float* fc_b      = (const float*)d_in[3];
    const float* gat_W     = (const float*)d_in[4];
    const float* attn_l    = (const float*)d_in[5];
    const float* attn_r    = (const float*)d_in[6];
    const float* sem_W     = (const float*)d_in[7];
    const float* sem_b     = (const float*)d_in[8];
    const float* sem_q     = (const float*)d_in[9];
    const float* fcout_W   = (const float*)d_in[10];
    const float* fcout_b   = (const float*)d_in[11];
    const int*   type_idx  = (const int*)d_in[12];
    const int*   node_idx  = (const int*)d_in[13];
    const int*   edge_src  = (const int*)d_in[14];
    const int*   edge_dst  = (const int*)d_in[15];
    const int*   tgt_idx   = (const int*)d_in[16];
    float* out = (float*)d_out;

    static cudaStream_t s_side = nullptr;
    static cudaEvent_t ev_fork = nullptr, ev_join = nullptr;
    static bool attr_done = false;
    if (!s_side) {
        cudaStreamCreateWithFlags(&s_side, cudaStreamNonBlocking);
        cudaEventCreateWithFlags(&ev_fork, cudaEventDisableTiming);
        cudaEventCreateWithFlags(&ev_join, cudaEventDisableTiming);
    }
    if (!attr_done) {
        cudaFuncSetAttribute(k_sem_mma, cudaFuncAttributeMaxDynamicSharedMemorySize,
                             SEMM_SZ);
        attr_done = true;
    }

    k_init<<<(G4 * NP_G + 255) / 256, 256>>>();

    cudaEventRecord(ev_fork, 0);
    cudaStreamWaitEvent(s_side, ev_fork, 0);
    k_count<<<(G4 * E_G + 255) / 256, 256, 0, s_side>>>(edge_dst);
    k_scan<<<G4, 1024, 0, s_side>>>();
    cudaEventRecord(ev_join, s_side);

    k_fc<<<dim3((NP_TYPE + 127) / 128, 2), 256>>>(features0, features1, fc_W, fc_b, type_idx);
    k_gatz<<<dim3((NP_G + 63) / 64, G4), 256>>>(node_idx, gat_W, attn_l, attn_r);

    cudaStreamWaitEvent(0, ev_join, 0);
    k_fill<<<(G4 * E_G + 255) / 256, 256>>>(edge_src, edge_dst);
    k_aggregate<<<(G4 * T_TGT) / 8, 256>>>(tgt_idx);
    k_sem_mma<<<dim3((2 * T_TGT) / 64, 2), 256, SEMM_SZ>>>(sem_W, sem_b, sem_q);
    k_combine<<<dim3((T_TGT + 127) / 128, 2), 256>>>(fcout_W, fcout_b, out);
}

// round 9
// speedup vs baseline: 1.5981x; 1.0245x over previous
#include <cuda_runtime.h>
#include <cuda_bf16.h>
#include <cuda_fp16.h>
#include <math.h>
#include <stdint.h>

#define N_TOTAL 100000
#define NP_TYPE 50000
#define NP_G    50000
#define E_G     500000
#define NH      4
#define HD      64
#define HID     64
#define D       256
#define OUT_DIM 64
#define T_TGT   20000
#define G4      4

// ------------------------- scratch (static device globals) -------------------
__device__ float  g_transformed[N_TOTAL * HID];          // 25.6 MB
__device__ float  g_z[(size_t)G4 * NP_G * D];            // 204.8 MB
__device__ float  g_el[G4 * NP_G * NH];
__device__ float  g_er[G4 * NP_G * NH];
__device__ float  g_wal[G4 * 64 * 8];                    // W@attn per graph
__device__ int    g_deg[G4 * NP_G];
__device__ int    g_offs[G4 * (NP_G + 1)];
__device__ int    g_cur[G4 * NP_G];
__device__ int    g_csr_src[G4 * E_G];
__device__ float4 g_csr_ex[G4 * E_G];                    // 32 MB
__device__ float  g_meta[(size_t)G4 * T_TGT * D];        // 81.9 MB
__device__ float  g_wsum[4];

// ------------------------------ small helpers --------------------------------
__device__ __forceinline__ uint32_t smem_u32(const void* p) {
    uint32_t a;
    asm("{ .reg .u64 t; cvta.to.shared.u64 t, %1; cvt.u32.u64 %0, t; }" : "=r"(a) : "l"(p));
    return a;
}
__device__ __forceinline__ uint32_t pack_bf16(float lo, float hi) {
    uint32_t r;
    asm("cvt.rn.bf16x2.f32 %0, %1, %2;" : "=r"(r) : "f"(hi), "f"(lo));
    return r;
}
__device__ __forceinline__ uint32_t pack_f16(float lo, float hi) {
    uint32_t r;
    asm("cvt.rn.f16x2.f32 %0, %1, %2;" : "=r"(r) : "f"(hi), "f"(lo));
    return r;
}
// packed tanh epilogue term: sum over 2 cols of tanh(x)*q  (fp16 path; MUFU x1)
__device__ __forceinline__ float tanh_dot2(float x0, float x1, uint32_t qh) {
    uint32_t xp = pack_f16(x0, x1), tp, pp;
    asm("tanh.approx.f16x2 %0, %1;" : "=r"(tp) : "r"(xp));
    asm("mul.f16x2 %0, %1, %2;" : "=r"(pp) : "r"(tp), "r"(qh));
    __half2 h = *reinterpret_cast<__half2*>(&pp);
    return __low2float(h) + __high2float(h);
}
__device__ __forceinline__ void ldsm_x4(uint32_t& r0, uint32_t& r1, uint32_t& r2,
                                        uint32_t& r3, uint32_t addr) {
    asm volatile("ldmatrix.sync.aligned.m8n8.x4.shared.b16 {%0,%1,%2,%3}, [%4];"
                 : "=r"(r0), "=r"(r1), "=r"(r2), "=r"(r3) : "r"(addr));
}
__device__ __forceinline__ void mma_bf16(float* c, uint32_t a0, uint32_t a1,
                                         uint32_t a2, uint32_t a3,
                                         uint32_t b0, uint32_t b1) {
    asm volatile(
        "mma.sync.aligned.m16n8k16.row.col.f32.bf16.bf16.f32 "
        "{%0,%1,%2,%3}, {%4,%5,%6,%7}, {%8,%9}, {%0,%1,%2,%3};"
        : "+f"(c[0]), "+f"(c[1]), "+f"(c[2]), "+f"(c[3])
        : "r"(a0), "r"(a1), "r"(a2), "r"(a3), "r"(b0), "r"(b1));
}

// k_sem_mma dynamic smem layout
#define SEMM_AS   264                         // A bf16 row stride (pad 8)
#define SEMM_WS   40                          // W bf16 row stride (pad 8)
#define SEMM_A_B  (64 * SEMM_AS * 2)          // 33792
#define SEMM_W_O  SEMM_A_B
#define SEMM_W_B  (256 * SEMM_WS * 2)         // 20480
#define SEMM_BO_O (SEMM_W_O + SEMM_W_B)       // 54272
#define SEMM_QH_O (SEMM_BO_O + 1024)          // 55296
#define SEMM_BK_O (SEMM_QH_O + 512)           // 55808
#define SEMM_SZ   (SEMM_BK_O + 128)           // 55936

// k_gatz_mma dynamic smem layout: A 64x(64+8), B 256x(64+8), hi+lo
#define GZ_S      72
#define GZ_AH_O   0
#define GZ_AL_O   9216
#define GZ_BH_O   18432
#define GZ_BL_O   55296
#define GZ_WAL_O  92160
#define GZ_SZ     (GZ_WAL_O + 2048)           // 94208

// ------------------------------- init ---------------------------------------
__global__ void k_init() {
    int i = blockIdx.x * blockDim.x + threadIdx.x;
    if (i < G4 * NP_G) g_deg[i] = 0;
    if (i < 4) g_wsum[i] = 0.f;
}

// ---- wal/war: per-graph W @ attn  (el = h . wal exactly == (hW) . al) ------
__global__ void k_wal(const float* __restrict__ gatW,
                      const float* __restrict__ attn_l,
                      const float* __restrict__ attn_r)
{
    int g = blockIdx.x;
    int idx = threadIdx.x;                     // 512 = 64 k x 8 o
    int k = idx >> 3, o = idx & 7;
    int side = o >> 2, h = o & 3;
    const float* att = (side ? attn_r : attn_l) + (size_t)g * D + h * 64;
    const float* wr = gatW + (size_t)g * HID * D + (size_t)k * D + h * 64;
    float s = 0.f;
#pragma unroll 16
    for (int d = 0; d < 64; d++) s += __ldg(&wr[d]) * __ldg(&att[d]);
    g_wal[g * 512 + k * 8 + o] = s;
}

// --------------------------- fc: type-wise linear ---------------------------
__global__ __launch_bounds__(256) void k_fc(
    const float* __restrict__ f0, const float* __restrict__ f1,
    const float* __restrict__ fcW, const float* __restrict__ fcb,
    const int* __restrict__ type_idx)
{
    __shared__ float ft[64][128];   // 32 KB
    __shared__ float wt[64][64];    // 16 KB

    int t = blockIdx.y;
    int base = blockIdx.x * 128;
    const float* feat = t ? f1 : f0;
    const float* W = fcW + (size_t)t * HID * D;          // W[o][k]
    int tid = threadIdx.x;
    int rg = tid & 31, cg = tid >> 5;

    float acc[4][8];
#pragma unroll
    for (int a = 0; a < 4; a++)
#pragma unroll
        for (int j = 0; j < 8; j++) acc[a][j] = 0.f;

    for (int ch = 0; ch < 4; ch++) {
        __syncthreads();
        {
            int r = tid & 127, qb = tid >> 7;
            int row = base + r;
            bool val = row < NP_TYPE;
            const float4* fp = (const float4*)(feat + (size_t)row * D) + ch * 16;
#pragma unroll
            for (int i = 0; i < 8; i++) {
                int q = qb + i * 2;
                float4 v = val ? __ldg(fp + q) : make_float4(0.f, 0.f, 0.f, 0.f);
                ft[q * 4 + 0][r] = v.x; ft[q * 4 + 1][r] = v.y;
                ft[q * 4 + 2][r] = v.z; ft[q * 4 + 3][r] = v.w;
            }
        }
        {
            int o = tid & 63, qb = tid >> 6;
            const float4* wp = (const float4*)(W + (size_t)o * D) + ch * 16;
#pragma unroll
            for (int i = 0; i < 4; i++) {
                int q = qb + i * 4;
                float4 v = __ldg(wp + q);
                wt[q * 4 + 0][o] = v.x; wt[q * 4 + 1][o] = v.y;
                wt[q * 4 + 2][o] = v.z; wt[q * 4 + 3][o] = v.w;
            }
        }
        __syncthreads();
#pragma unroll 16
        for (int k = 0; k < 64; k++) {
            float4 fv = *(const float4*)&ft[k][rg * 4];
            float4 w0 = *(const float4*)&wt[k][cg * 8];
            float4 w1 = *(const float4*)&wt[k][cg * 8 + 4];
            float fr[4] = {fv.x, fv.y, fv.z, fv.w};
            float wc[8] = {w0.x, w0.y, w0.z, w0.w, w1.x, w1.y, w1.z, w1.w};
#pragma unroll
            for (int a = 0; a < 4; a++)
#pragma unroll
                for (int j = 0; j < 8; j++) acc[a][j] += fr[a] * wc[j];
        }
    }
    float bo[8];
#pragma unroll
    for (int j = 0; j < 8; j++) bo[j] = __ldg(&fcb[t * HID + cg * 8 + j]);
    const int* ti = type_idx + t * NP_TYPE;
#pragma unroll
    for (int a = 0; a < 4; a++) {
        int row = base + rg * 4 + a;
        if (row < NP_TYPE) {
            int dst = __ldg(&ti[row]);
            float* op = g_transformed + (size_t)dst * HID + cg * 8;
            *(float4*)op = make_float4(acc[a][0] + bo[0], acc[a][1] + bo[1],
                                       acc[a][2] + bo[2], acc[a][3] + bo[3]);
            *((float4*)op + 1) = make_float4(acc[a][4] + bo[4], acc[a][5] + bo[5],
                                             acc[a][6] + bo[6], acc[a][7] + bo[7]);
        }
    }
}

// -------- gatz on mma.sync bf16x3: z = gather(h) @ W, + el/er via wal --------
// grid (782, G4); 256 thr (8 warps). CTA: 64 rows x 256 cols. Warp: 16r x 128c.
// A (64x64) hi+lo, B=W^T (256x64) hi+lo in smem; 3 MMA passes (hh, lh, hl).
__global__ __launch_bounds__(256) void k_gatz_mma(
    const int* __restrict__ node_idx, const float* __restrict__ gatW)
{
    extern __shared__ char smem[];
    __nv_bfloat16* ah  = (__nv_bfloat16*)(smem + GZ_AH_O);   // [64][72]
    __nv_bfloat16* alo = (__nv_bfloat16*)(smem + GZ_AL_O);   // [64][72]
    __nv_bfloat16* bh  = (__nv_bfloat16*)(smem + GZ_BH_O);   // [256][72]
    __nv_bfloat16* blo = (__nv_bfloat16*)(smem + GZ_BL_O);   // [256][72]
    float* wal_s = (float*)(smem + GZ_WAL_O);                // [64][8]

    int g = blockIdx.y;
    int base = blockIdx.x * 64;
    int tid = threadIdx.x;
    int wid = tid >> 5, lane = tid & 31;
    const float* W = gatW + (size_t)g * HID * D;             // [k][o] k-major

    // ---- A: gather 64 rows x 64 cols fp32 -> bf16 hi/lo ----
    {
        int r = tid >> 2, kq = tid & 3;
        int row = base + r;
        int node = (row < NP_G) ? __ldg(&node_idx[(size_t)g * NP_G + row]) : -1;
        const float4* hp = (const float4*)(g_transformed + (size_t)node * HID) + kq * 4;
#pragma unroll
        for (int i = 0; i < 4; i++) {
            float4 v = (node >= 0) ? __ldg(hp + i) : make_float4(0.f, 0.f, 0.f, 0.f);
            uint32_t ph0 = pack_bf16(v.x, v.y), ph1 = pack_bf16(v.z, v.w);
            __nv_bfloat162 hb0 = *(__nv_bfloat162*)&ph0;
            __nv_bfloat162 hb1 = *(__nv_bfloat162*)&ph1;
            uint32_t pl0 = pack_bf16(v.x - __bfloat162float(hb0.x),
                                     v.y - __bfloat162float(hb0.y));
            uint32_t pl1 = pack_bf16(v.z - __bfloat162float(hb1.x),
                                     v.w - __bfloat162float(hb1.y));
            int idx = r * GZ_S + kq * 16 + i * 4;
            *(uint2*)&ah[idx]  = make_uint2(ph0, ph1);
            *(uint2*)&alo[idx] = make_uint2(pl0, pl1);
        }
    }
    // ---- B: W^T 256 o x 64 k, hi/lo ----
    {
        int o = tid;
#pragma unroll 8
        for (int k = 0; k < 64; k++) {
            float v = __ldg(&W[(size_t)k * D + o]);
            __nv_bfloat16 hbv = __float2bfloat16(v);
            bh[o * GZ_S + k] = hbv;
            blo[o * GZ_S + k] = __float2bfloat16(v - __bfloat162float(hbv));
        }
    }
    wal_s[tid] = g_wal[g * 512 + tid];
    wal_s[tid + 256] = g_wal[g * 512 + tid + 256];
    __syncthreads();

    int rw = wid >> 1;            // row group 0..3
    int cw = wid & 1;             // col group 0..1
    float cacc[16][4];
#pragma unroll
    for (int ti = 0; ti < 16; ti++)
#pragma unroll
        for (int j = 0; j < 4; j++) cacc[ti][j] = 0.f;

    int a_tile = lane >> 3;
    int a_row = rw * 16 + (lane & 7) + (a_tile & 1) * 8;
    int a_koff = (a_tile >> 1) * 8;
    int b_g = lane >> 3;
    int b_nbase = cw * 128 + (b_g >> 1) * 8 + (lane & 7);
    int b_koff = (b_g & 1) * 8;

    const __nv_bfloat16* Asrc[3] = {ah, alo, ah};
    const __nv_bfloat16* Bsrc[3] = {bh, bh, blo};
#pragma unroll
    for (int s = 0; s < 3; s++) {
        const __nv_bfloat16* As = Asrc[s];
        const __nv_bfloat16* Bs = Bsrc[s];
#pragma unroll
        for (int ks = 0; ks < 4; ks++) {
            uint32_t a0, a1, a2, a3;
            ldsm_x4(a0, a1, a2, a3,
                    smem_u32(&As[a_row * GZ_S + ks * 16 + a_koff]));
#pragma unroll
            for (int nt = 0; nt < 8; nt++) {
                uint32_t b0, b1, b2, b3;
                ldsm_x4(b0, b1, b2, b3,
                        smem_u32(&Bs[(b_nbase + nt * 16) * GZ_S + ks * 16 + b_koff]));
                mma_bf16(cacc[nt * 2 + 0], a0, a1, a2, a3, b0, b1);
                mma_bf16(cacc[nt * 2 + 1], a0, a1, a2, a3, b2, b3);
            }
        }
    }

    // ---- z stores (fp32) ----
    {
        int lr = lane >> 2, lc = lane & 3;
        int r0 = base + rw * 16 + lr, r1 = r0 + 8;
        bool v0 = r0 < NP_G, v1 = r1 < NP_G;
        float* z0 = g_z + ((size_t)g * NP_G + r0) * D + cw * 128 + lc * 2;
        float* z1 = g_z + ((size_t)g * NP_G + r1) * D + cw * 128 + lc * 2;
#pragma unroll
        for (int ti = 0; ti < 16; ti++) {
            if (v0) *(float2*)(z0 + ti * 8) = make_float2(cacc[ti][0], cacc[ti][1]);
            if (v1) *(float2*)(z1 + ti * 8) = make_float2(cacc[ti][2], cacc[ti][3]);
        }
    }

    // ---- el/er: h . wal (A smem hi+lo reconstructs h to ~1e-5) ----
    {
        int r = tid & 63;
        int ob = (tid >> 6) * 2;               // 0,2,4,6
        int row = base + r;
        if (row < NP_G) {
            float e0 = 0.f, e1 = 0.f;
#pragma unroll 8
            for (int k = 0; k < 64; k += 2) {
                __nv_bfloat162 hb = *(__nv_bfloat162*)&ah[r * GZ_S + k];
                __nv_bfloat162 lb = *(__nv_bfloat162*)&alo[r * GZ_S + k];
                float h0 = __bfloat162float(hb.x) + __bfloat162float(lb.x);
                float h1 = __bfloat162float(hb.y) + __bfloat162float(lb.y);
                e0 += h0 * wal_s[k * 8 + ob]     + h1 * wal_s[(k + 1) * 8 + ob];
                e1 += h0 * wal_s[k * 8 + ob + 1] + h1 * wal_s[(k + 1) * 8 + ob + 1];
            }
            size_t nbase = ((size_t)g * NP_G + row) * NH;
            if (ob < 4) {
                g_el[nbase + ob] = e0;
                g_el[nbase + ob + 1] = e1;
            } else {
                g_er[nbase + ob - 4] = e0;
                g_er[nbase + ob - 3] = e1;
            }
        }
    }
}

// ------------------------------- CSR build ----------------------------------
__global__ void k_count(const int* __restrict__ dst) {
    int e = blockIdx.x * blockDim.x + threadIdx.x;
    if (e < G4 * E_G) {
        int g = e / E_G;
        atomicAdd(&g_deg[g * NP_G + __ldg(&dst[e])], 1);
    }
}

__global__ __launch_bounds__(1024) void k_scan() {
    __shared__ int ws[32];
    int g = blockIdx.x;
    int tid = threadIdx.x;
    int lane = tid & 31, wid = tid >> 5;
    const int CH = (NP_G + 1023) / 1024;   // 49
    int lo = tid * CH;
    int hi = min(lo + CH, NP_G);
    const int* deg = g_deg + g * NP_G;
    int s = 0;
    for (int i = lo; i < hi; i++) s += deg[i];
    int v = s;
#pragma unroll
    for (int off = 1; off < 32; off <<= 1) {
        int n = __shfl_up_sync(0xffffffffu, v, off);
        if (lane >= off) v += n;
    }
    if (lane == 31) ws[wid] = v;
    __syncthreads();
    if (wid == 0) {
        int w = ws[lane];
#pragma unroll
        for (int off = 1; off < 32; off <<= 1) {
            int n = __shfl_up_sync(0xffffffffu, w, off);
            if (lane >= off) w += n;
        }
        ws[lane] = w;
    }
    __syncthreads();
    int excl = v - s + (wid ? ws[wid - 1] : 0);
    int* offs = g_offs + g * (NP_G + 1);
    int* cur = g_cur + g * NP_G;
    int run = excl;
    for (int i = lo; i < hi; i++) {
        offs[i] = run;
        cur[i] = run;
        run += deg[i];
    }
    if (tid == 0) offs[NP_G] = E_G;
}

__global__ void k_fill(const int* __restrict__ src, const int* __restrict__ dst) {
    int e = blockIdx.x * blockDim.x + threadIdx.x;
    if (e >= G4 * E_G) return;
    int g = e / E_G;
    int gn = g * NP_G;
    int s = __ldg(&src[e]);
    int d = __ldg(&dst[e]);
    float4 elv = __ldg((const float4*)g_el + gn + s);
    float4 erv = __ldg((const float4*)g_er + gn + d);
    float e0 = elv.x + erv.x, e1 = elv.y + erv.y;
    float e2 = elv.z + erv.z, e3 = elv.w + erv.w;
    e0 = e0 > 0.f ? e0 : 0.2f * e0;
    e1 = e1 > 0.f ? e1 : 0.2f * e1;
    e2 = e2 > 0.f ? e2 : 0.2f * e2;
    e3 = e3 > 0.f ? e3 : 0.2f * e3;
    float4 ex = make_float4(__expf(e0), __expf(e1), __expf(e2), __expf(e3));
    int pos = atomicAdd(&g_cur[gn + d], 1);
    g_csr_src[(size_t)g * E_G + pos] = s;
    g_csr_ex[(size_t)g * E_G + pos] = ex;
}

// ------ aggregate: warp per TARGET, fused softmax, writes meta directly -----
__global__ __launch_bounds__(256) void k_aggregate(const int* __restrict__ tgt) {
    int t = (blockIdx.x * blockDim.x + threadIdx.x) >> 5;
    if (t >= G4 * T_TGT) return;
    int g = t / T_TGT;
    int lane = threadIdx.x & 31;
    int hsel = lane >> 3;
    int nl = __ldg(&tgt[t]);
    int beg = g_offs[g * (NP_G + 1) + nl];
    int end = g_offs[g * (NP_G + 1) + nl + 1];
    const int* cs = g_csr_src + (size_t)g * E_G;
    const float4* ce = g_csr_ex + (size_t)g * E_G;
    const float* zb = g_z + (size_t)g * NP_G * D;

    float4 a0 = {0.f, 0.f, 0.f, 0.f}, a1 = {0.f, 0.f, 0.f, 0.f};
    float den = 0.f;

    int i = beg;
    for (; i + 4 <= end; i += 4) {
        int s0 = __ldg(cs + i), s1 = __ldg(cs + i + 1);
        int s2 = __ldg(cs + i + 2), s3 = __ldg(cs + i + 3);
        float4 e0 = __ldg(ce + i), e1 = __ldg(ce + i + 1);
        float4 e2 = __ldg(ce + i + 2), e3 = __ldg(ce + i + 3);
        const float4* z0p = (const float4*)(zb + (size_t)s0 * D) + lane * 2;
        const float4* z1p = (const float4*)(zb + (size_t)s1 * D) + lane * 2;
        const float4* z2p = (const float4*)(zb + (size_t)s2 * D) + lane * 2;
        const float4* z3p = (const float4*)(zb + (size_t)s3 * D) + lane * 2;
        float4 za0 = __ldg(z0p), zb0 = __ldg(z0p + 1);
        float4 za1 = __ldg(z1p), zb1 = __ldg(z1p + 1);
        float4 za2 = __ldg(z2p), zb2 = __ldg(z2p + 1);
        float4 za3 = __ldg(z3p), zb3 = __ldg(z3p + 1);
        float x0 = (hsel == 0) ? e0.x : (hsel == 1) ? e0.y : (hsel == 2) ? e0.z : e0.w;
        float x1 = (hsel == 0) ? e1.x : (hsel == 1) ? e1.y : (hsel == 2) ? e1.z : e1.w;
        float x2 = (hsel == 0) ? e2.x : (hsel == 1) ? e2.y : (hsel == 2) ? e2.z : e2.w;
        float x3 = (hsel == 0) ? e3.x : (hsel == 1) ? e3.y : (hsel == 2) ? e3.z : e3.w;
        a0.x += x0 * za0.x; a0.y += x0 * za0.y; a0.z += x0 * za0.z; a0.w += x0 * za0.w;
        a1.x += x0 * zb0.x; a1.y += x0 * zb0.y; a1.z += x0 * zb0.z; a1.w += x0 * zb0.w;
        a0.x += x1 * za1.x; a0.y += x1 * za1.y; a0.z += x1 * za1.z; a0.w += x1 * za1.w;
        a1.x += x1 * zb1.x; a1.y += x1 * zb1.y; a1.z += x1 * zb1.z; a1.w += x1 * zb1.w;
        a0.x += x2 * za2.x; a0.y += x2 * za2.y; a0.z += x2 * za2.z; a0.w += x2 * za2.w;
        a1.x += x2 * zb2.x; a1.y += x2 * zb2.y; a1.z += x2 * zb2.z; a1.w += x2 * zb2.w;
        a0.x += x3 * za3.x; a0.y += x3 * za3.y; a0.z += x3 * za3.z; a0.w += x3 * za3.w;
        a1.x += x3 * zb3.x; a1.y += x3 * zb3.y; a1.z += x3 * zb3.z; a1.w += x3 * zb3.w;
        den += x0 + x1 + x2 + x3;
    }
    for (; i < end; i++) {
        int s0 = __ldg(cs + i);
        float4 e0 = __ldg(ce + i);
        const float4* z0p = (const float4*)(zb + (size_t)s0 * D) + lane * 2;
        float4 za = __ldg(z0p), zc = __ldg(z0p + 1);
        float x0 = (hsel == 0) ? e0.x : (hsel == 1) ? e0.y : (hsel == 2) ? e0.z : e0.w;
        a0.x += x0 * za.x; a0.y += x0 * za.y; a0.z += x0 * za.z; a0.w += x0 * za.w;
        a1.x += x0 * zc.x; a1.y += x0 * zc.y; a1.z += x0 * zc.z; a1.w += x0 * zc.w;
        den += x0;
    }
    float inv = 1.f / (den + 1e-9f);
    float v[8] = {a0.x * inv, a0.y * inv, a0.z * inv, a0.w * inv,
                  a1.x * inv, a1.y * inv, a1.z * inv, a1.w * inv};
#pragma unroll
    for (int j = 0; j < 8; j++) v[j] = v[j] > 0.f ? v[j] : expm1f(v[j]);
    float* op = g_meta + (size_t)t * D + lane * 8;
    *(float4*)op = make_float4(v[0], v[1], v[2], v[3]);
    *((float4*)op + 1) = make_float4(v[4], v[5], v[6], v[7]);
}

// ----- semantic attention on mma.sync bf16 HMMA -----------------------------
__global__ __launch_bounds__(256) void k_sem_mma(
    const float* __restrict__ semW, const float* __restrict__ semb,
    const float* __restrict__ semq)
{
    extern __shared__ char smem[];
    __nv_bfloat16* ftA = (__nv_bfloat16*)smem;               // [64][264]
    __nv_bfloat16* wt  = (__nv_bfloat16*)(smem + SEMM_W_O);  // [256][40]
    float*    bo_s = (float*)(smem + SEMM_BO_O);             // [256]
    uint32_t* qh_s = (uint32_t*)(smem + SEMM_QH_O);          // [128] packed f16x2
    float*  bucket = (float*)(smem + SEMM_BK_O);             // [2]

    const int BR = 2 * T_TGT;                                // 40000 = 625*64
    int tid = threadIdx.x;
    int wid = tid >> 5, lane = tid & 31;
    int b = blockIdx.y;
    int base = blockIdx.x * 64;
    const float* W = semW + (size_t)b * D * D;               // k-major [k][o]

    if (tid < 64) ((float4*)bo_s)[tid] = __ldg((const float4*)(semb + b * D) + tid);
    else if (tid < 192) {
        int j = tid - 64;
        float q0 = __ldg(&semq[b * D + 2 * j]);
        float q1 = __ldg(&semq[b * D + 2 * j + 1]);
        qh_s[j] = pack_f16(q0, q1);
    }
    if (tid < 2) bucket[tid] = 0.f;

    {
        int r = tid >> 2, kq = tid & 3;
        const float* arow = g_meta + ((size_t)b * BR + base + r) * D;
#pragma unroll
        for (int i = 0; i < 8; i++) {
            int k = kq * 64 + i * 8;
            float4 v0 = __ldg((const float4*)(arow + k));
            float4 v1 = __ldg((const float4*)(arow + k) + 1);
            uint4 pk;
            pk.x = pack_bf16(v0.x, v0.y);
            pk.y = pack_bf16(v0.z, v0.w);
            pk.z = pack_bf16(v1.x, v1.y);
            pk.w = pack_bf16(v1.z, v1.w);
            *(uint4*)&ftA[r * SEMM_AS + k] = pk;
        }
    }

    int rw = wid >> 1;
    int cw = wid & 1;
    float cacc[16][4];
#pragma unroll
    for (int ti = 0; ti < 16; ti++)
#pragma unroll
        for (int j = 0; j < 4; j++) cacc[ti][j] = 0.f;

    int a_tile = lane >> 3;
    int a_row = rw * 16 + (lane & 7) + (a_tile & 1) * 8;
    int a_koff = (a_tile >> 1) * 8;
    int b_g = lane >> 3;
    int b_nbase = cw * 128 + (b_g >> 1) * 8 + (lane & 7);
    int b_koff = (b_g & 1) * 8;

    for (int ch = 0; ch < 8; ch++) {
        __syncthreads();
        {
            int o = tid;
            const float* wcol = W + (size_t)(ch * 32) * D + o;
            uint32_t* wrow = (uint32_t*)&wt[o * SEMM_WS];
#pragma unroll
            for (int j = 0; j < 16; j++) {
                float va = __ldg(wcol + (size_t)(2 * j) * D);
                float vb = __ldg(wcol + (size_t)(2 * j + 1) * D);
                wrow[j] = pack_bf16(va, vb);
            }
        }
        __syncthreads();
#pragma unroll
        for (int ks = 0; ks < 2; ks++) {
            uint32_t a0, a1, a2, a3;
            ldsm_x4(a0, a1, a2, a3,
                    smem_u32(&ftA[a_row * SEMM_AS + ch * 32 + ks * 16 + a_koff]));
#pragma unroll
            for (int nt = 0; nt < 8; nt++) {
                uint32_t b0, b1, b2, b3;
                ldsm_x4(b0, b1, b2, b3,
                        smem_u32(&wt[(b_nbase + nt * 16) * SEMM_WS + ks * 16 + b_koff]));
                mma_bf16(cacc[nt * 2 + 0], a0, a1, a2, a3, b0, b1);
                mma_bf16(cacc[nt * 2 + 1], a0, a1, a2, a3, b2, b3);
            }
        }
    }

    int lr = lane >> 2, lc = lane & 3;
    float rs0 = 0.f, rs1 = 0.f;
#pragma unroll
    for (int ti = 0; ti < 16; ti++) {
        int col = cw * 128 + ti * 8 + lc * 2;
        uint32_t qh = qh_s[col >> 1];
        float b0v = bo_s[col], b1v = bo_s[col + 1];
        rs0 += tanh_dot2(cacc[ti][0] + b0v, cacc[ti][1] + b1v, qh);
        rs1 += tanh_dot2(cacc[ti][2] + b0v, cacc[ti][3] + b1v, qh);
    }
    rs0 += __shfl_down_sync(0xffffffffu, rs0, 2, 4);
    rs0 += __shfl_down_sync(0xffffffffu, rs0, 1, 4);
    rs1 += __shfl_down_sync(0xffffffffu, rs1, 2, 4);
    rs1 += __shfl_down_sync(0xffffffffu, rs1, 1, 4);
    if (lc == 0) {
        int r0 = base + rw * 16 + lr;
        int r1 = r0 + 8;
        atomicAdd(&bucket[r0 >= T_TGT ? 1 : 0], rs0);
        atomicAdd(&bucket[r1 >= T_TGT ? 1 : 0], rs1);
    }
    __syncthreads();
    if (tid < 2 && bucket[tid] != 0.f) atomicAdd(&g_wsum[b * 2 + tid], bucket[tid]);
}

// -------------- combine: beta-blend metas, @ fcout_W + bias -----------------
__global__ __launch_bounds__(256) void k_combine(
    const float* __restrict__ fW, const float* __restrict__ fb,
    float* __restrict__ outp)
{
    __shared__ float ft[64][128];   // 32 KB
    __shared__ float wt[64][64];    // 16 KB

    int b = blockIdx.y;
    int base = blockIdx.x * 128;
    int tid = threadIdx.x;
    int rg = tid & 31, cg = tid >> 5;

    float w0 = g_wsum[b * 2 + 0] * (1.f / T_TGT);
    float w1 = g_wsum[b * 2 + 1] * (1.f / T_TGT);
    float mx = fmaxf(w0, w1);
    float b0 = __expf(w0 - mx), b1 = __expf(w1 - mx);
    float sm = b0 + b1;
    b0 /= sm; b1 /= sm;

    const float* m0 = g_meta + ((size_t)(b * 2 + 0) * T_TGT) * D;
    const float* m1 = g_meta + ((size_t)(b * 2 + 1) * T_TGT) * D;
    const float* W = fW + (size_t)b * D * OUT_DIM;

    float acc[4][8];
#pragma unroll
    for (int a = 0; a < 4; a++)
#pragma unroll
        for (int j = 0; j < 8; j++) acc[a][j] = 0.f;

    for (int ch = 0; ch < 4; ch++) {
        __syncthreads();
        {
            int r = tid & 127, qb = tid >> 7;
            int row = base + r;
            bool val = row < T_TGT;
            const float4* p0 = (const float4*)(m0 + (size_t)row * D) + ch * 16;
            const float4* p1 = (const float4*)(m1 + (size_t)row * D) + ch * 16;
#pragma unroll
            for (int i = 0; i < 8; i++) {
                int q = qb + i * 2;
                float4 v0 = val ? __ldg(p0 + q) : make_float4(0.f, 0.f, 0.f, 0.f);
                float4 v1 = val ? __ldg(p1 + q) : make_float4(0.f, 0.f, 0.f, 0.f);
                ft[q * 4 + 0][r] = b0 * v0.x + b1 * v1.x;
                ft[q * 4 + 1][r] = b0 * v0.y + b1 * v1.y;
                ft[q * 4 + 2][r] = b0 * v0.z + b1 * v1.z;
                ft[q * 4 + 3][r] = b0 * v0.w + b1 * v1.w;
            }
        }
        {
            const float4* wp = (const float4*)(W + (size_t)ch * 64 * OUT_DIM);
            float4* wd = (float4*)&wt[0][0];
#pragma unroll
            for (int i = 0; i < 4; i++)
                wd[tid + i * 256] = __ldg(wp + tid + i * 256);
        }
        __syncthreads();
#pragma unroll 16
        for (int k = 0; k < 64; k++) {
            float4 fv = *(const float4*)&ft[k][rg * 4];
            float4 wv0 = *(const float4*)&wt[k][cg * 8];
            float4 wv1 = *(const float4*)&wt[k][cg * 8 + 4];
            float fr[4] = {fv.x, fv.y, fv.z, fv.w};
            float wc[8] = {wv0.x, wv0.y, wv0.z, wv0.w, wv1.x, wv1.y, wv1.z, wv1.w};
#pragma unroll
            for (int a = 0; a < 4; a++)
#pragma unroll
                for (int j = 0; j < 8; j++) acc[a][j] += fr[a] * wc[j];
        }
    }
    float bo[8];
#pragma unroll
    for (int j = 0; j < 8; j++) bo[j] = __ldg(&fb[b * OUT_DIM + cg * 8 + j]);
#pragma unroll
    for (int a = 0; a < 4; a++) {
        int row = base + rg * 4 + a;
        if (row < T_TGT) {
            float* op = outp + ((size_t)b * T_TGT + row) * OUT_DIM + cg * 8;
            *(float4*)op = make_float4(acc[a][0] + bo[0], acc[a][1] + bo[1],
                                       acc[a][2] + bo[2], acc[a][3] + bo[3]);
            *((float4*)op + 1) = make_float4(acc[a][4] + bo[4], acc[a][5] + bo[5],
                                             acc[a][6] + bo[6], acc[a][7] + bo[7]);
        }
    }
}

// ------------------------------- launch -------------------------------------
extern "C" void kernel_launch(void* const* d_in, const int* in_sizes, int n_in,
                              void* d_out, int out_size)
{
    const float* features0 = (const float*)d_in[0];
    const float* features1 = (const float*)d_in[1];
    const float* fc_W      = (const float*)d_in[2];
    const float* fc_b      = (const float*)d_in[3];
    const float* gat_W     = (const float*)d_in[4];
    const float* attn_l    = (const float*)d_in[5];
    const float* attn_r    = (const float*)d_in[6];
    const float* sem_W     = (const float*)d_in[7];
    const float* sem_b     = (const float*)d_in[8];
    const float* sem_q     = (const float*)d_in[9];
    const float* fcout_W   = (const float*)d_in[10];
    const float* fcout_b   = (const float*)d_in[11];
    const int*   type_idx  = (const int*)d_in[12];
    const int*   node_idx  = (const int*)d_in[13];
    const int*   edge_src  = (const int*)d_in[14];
    const int*   edge_dst  = (const int*)d_in[15];
    const int*   tgt_idx   = (const int*)d_in[16];
    float* out = (float*)d_out;

    static cudaStream_t s_side = nullptr;
    static cudaEvent_t ev_fork = nullptr, ev_join = nullptr;
    static bool attr_done = false;
    if (!s_side) {
        cudaStreamCreateWithFlags(&s_side, cudaStreamNonBlocking);
        cudaEventCreateWithFlags(&ev_fork, cudaEventDisableTiming);
        cudaEventCreateWithFlags(&ev_join, cudaEventDisableTiming);
    }
    if (!attr_done) {
        cudaFuncSetAttribute(k_sem_mma, cudaFuncAttributeMaxDynamicSharedMemorySize,
                             SEMM_SZ);
        cudaFuncSetAttribute(k_gatz_mma, cudaFuncAttributeMaxDynamicSharedMemorySize,
                             GZ_SZ);
        attr_done = true;
    }

    k_init<<<(G4 * NP_G + 255) / 256, 256>>>();
    k_wal<<<G4, 512>>>(gat_W, attn_l, attn_r);

    cudaEventRecord(ev_fork, 0);
    cudaStreamWaitEvent(s_side, ev_fork, 0);
    k_count<<<(G4 * E_G + 255) / 256, 256, 0, s_side>>>(edge_dst);
    k_scan<<<G4, 1024, 0, s_side>>>();
    cudaEventRecord(ev_join, s_side);

    k_fc<<<dim3((NP_TYPE + 127) / 128, 2), 256>>>(features0, features1, fc_W, fc_b, type_idx);
    k_gatz_mma<<<dim3((NP_G + 63) / 64, G4), 256, GZ_SZ>>>(node_idx, gat_W);

    cudaStreamWaitEvent(0, ev_join, 0);
    k_fill<<<(G4 * E_G + 255) / 256, 256>>>(edge_src, edge_dst);
    k_aggregate<<<(G4 * T_TGT) / 8, 256>>>(tgt_idx);
    k_sem_mma<<<dim3((2 * T_TGT) / 64, 2), 256, SEMM_SZ>>>(sem_W, sem_b, sem_q);
    k_combine<<<dim3((T_TGT + 127) / 128, 2), 256>>>(fcout_W, fcout_b, out);
}

// round 11
// speedup vs baseline: 1.6698x; 1.0449x over previous
#include <cuda_runtime.h>
#include <cuda_bf16.h>
#include <cuda_fp16.h>
#include <math.h>
#include <stdint.h>

#define N_TOTAL 100000
#define NP_TYPE 50000
#define NP_G    50000
#define E_G     500000
#define NH      4
#define HD      64
#define HID     64
#define D       256
#define OUT_DIM 64
#define T_TGT   20000
#define G4      4

// ------------------------- scratch (static device globals) -------------------
__device__ float  g_transformed[N_TOTAL * HID];          // 25.6 MB
__device__ float  g_z[(size_t)G4 * NP_G * D];            // 204.8 MB
__device__ float  g_el[G4 * NP_G * NH];
__device__ float  g_er[G4 * NP_G * NH];
__device__ float  g_wal[G4 * 64 * 8];                    // W@attn per graph
__device__ int    g_deg[G4 * NP_G];
__device__ int    g_offs[G4 * (NP_G + 1)];
__device__ int    g_cur[G4 * NP_G];
__device__ int    g_csr_src[G4 * E_G];
__device__ float4 g_csr_ex[G4 * E_G];                    // 32 MB
__device__ float  g_meta[(size_t)G4 * T_TGT * D];        // 81.9 MB
__device__ float  g_wsum[4];

// ------------------------------ small helpers --------------------------------
__device__ __forceinline__ uint32_t smem_u32(const void* p) {
    uint32_t a;
    asm("{ .reg .u64 t; cvta.to.shared.u64 t, %1; cvt.u32.u64 %0, t; }" : "=r"(a) : "l"(p));
    return a;
}
__device__ __forceinline__ uint32_t pack_bf16(float lo, float hi) {
    uint32_t r;
    asm("cvt.rn.bf16x2.f32 %0, %1, %2;" : "=r"(r) : "f"(hi), "f"(lo));
    return r;
}
__device__ __forceinline__ uint32_t pack_f16(float lo, float hi) {
    uint32_t r;
    asm("cvt.rn.f16x2.f32 %0, %1, %2;" : "=r"(r) : "f"(hi), "f"(lo));
    return r;
}
// packed tanh epilogue term: sum over 2 cols of tanh(x)*q  (fp16 path; MUFU x1)
__device__ __forceinline__ float tanh_dot2(float x0, float x1, uint32_t qh) {
    uint32_t xp = pack_f16(x0, x1), tp, pp;
    asm("tanh.approx.f16x2 %0, %1;" : "=r"(tp) : "r"(xp));
    asm("mul.f16x2 %0, %1, %2;" : "=r"(pp) : "r"(tp), "r"(qh));
    __half2 h = *reinterpret_cast<__half2*>(&pp);
    return __low2float(h) + __high2float(h);
}
__device__ __forceinline__ void ldsm_x4(uint32_t& r0, uint32_t& r1, uint32_t& r2,
                                        uint32_t& r3, uint32_t addr) {
    asm volatile("ldmatrix.sync.aligned.m8n8.x4.shared.b16 {%0,%1,%2,%3}, [%4];"
                 : "=r"(r0), "=r"(r1), "=r"(r2), "=r"(r3) : "r"(addr));
}
__device__ __forceinline__ void mma_bf16(float* c, uint32_t a0, uint32_t a1,
                                         uint32_t a2, uint32_t a3,
                                         uint32_t b0, uint32_t b1) {
    asm volatile(
        "mma.sync.aligned.m16n8k16.row.col.f32.bf16.bf16.f32 "
        "{%0,%1,%2,%3}, {%4,%5,%6,%7}, {%8,%9}, {%0,%1,%2,%3};"
        : "+f"(c[0]), "+f"(c[1]), "+f"(c[2]), "+f"(c[3])
        : "r"(a0), "r"(a1), "r"(a2), "r"(a3), "r"(b0), "r"(b1));
}
__device__ __forceinline__ void mma_f16(float* c, uint32_t a0, uint32_t a1,
                                        uint32_t a2, uint32_t a3,
                                        uint32_t b0, uint32_t b1) {
    asm volatile(
        "mma.sync.aligned.m16n8k16.row.col.f32.f16.f16.f32 "
        "{%0,%1,%2,%3}, {%4,%5,%6,%7}, {%8,%9}, {%0,%1,%2,%3};"
        : "+f"(c[0]), "+f"(c[1]), "+f"(c[2]), "+f"(c[3])
        : "r"(a0), "r"(a1), "r"(a2), "r"(a3), "r"(b0), "r"(b1));
}

// k_sem_mma dynamic smem layout
#define SEMM_AS   264                         // A bf16 row stride (pad 8)
#define SEMM_WS   40                          // W bf16 row stride (pad 8)
#define SEMM_A_B  (64 * SEMM_AS * 2)          // 33792
#define SEMM_W_O  SEMM_A_B
#define SEMM_W_B  (256 * SEMM_WS * 2)         // 20480
#define SEMM_BO_O (SEMM_W_O + SEMM_W_B)       // 54272
#define SEMM_QH_O (SEMM_BO_O + 1024)          // 55296
#define SEMM_BK_O (SEMM_QH_O + 512)           // 55808
#define SEMM_SZ   (SEMM_BK_O + 128)           // 55936

// k_gatz_mma fp16 layout: A 64x(64+8), B 256x(64+8)
#define GZ_S      72
#define GZ_AH_O   0
#define GZ_BH_O   9216
#define GZ_WAL_O  46080
#define GZ_SZ     (GZ_WAL_O + 2048)           // 48128

// k_fc_mma fp16 layout: A 128x(256+8), B 64x(256+8)
#define FC_AS     264
#define FC_A_O    0
#define FC_A_B    (128 * FC_AS * 2)           // 67584
#define FC_B_O    FC_A_B
#define FC_B_B    (64 * FC_AS * 2)            // 33792
#define FC_BO_O   (FC_B_O + FC_B_B)           // 101376
#define FC_SZ     (FC_BO_O + 256)             // 101632

// ------------------------------- init ---------------------------------------
__global__ void k_init() {
    int i = blockIdx.x * blockDim.x + threadIdx.x;
    if (i < G4 * NP_G) g_deg[i] = 0;
    if (i < 4) g_wsum[i] = 0.f;
}

// ---- wal/war: per-graph W @ attn  (el = h . wal exactly == (hW) . al) ------
__global__ void k_wal(const float* __restrict__ gatW,
                      const float* __restrict__ attn_l,
                      const float* __restrict__ attn_r)
{
    int g = blockIdx.x;
    int idx = threadIdx.x;                     // 512 = 64 k x 8 o
    int k = idx >> 3, o = idx & 7;
    int side = o >> 2, h = o & 3;
    const float* att = (side ? attn_r : attn_l) + (size_t)g * D + h * 64;
    const float* wr = gatW + (size_t)g * HID * D + (size_t)k * D + h * 64;
    float s = 0.f;
#pragma unroll 16
    for (int d = 0; d < 64; d++) s += __ldg(&wr[d]) * __ldg(&att[d]);
    g_wal[g * 512 + k * 8 + o] = s;
}

// ---------- fc on mma.sync fp16: transformed = features @ W^T + b -----------
// grid (391, 2); 256 thr (8 warps). CTA: 128 rows x 64 cols, K=256 resident.
__global__ __launch_bounds__(256) void k_fc_mma(
    const float* __restrict__ f0, const float* __restrict__ f1,
    const float* __restrict__ fcW, const float* __restrict__ fcb,
    const int* __restrict__ type_idx)
{
    extern __shared__ char smem[];
    __half* fA = (__half*)(smem + FC_A_O);     // [128][264]
    __half* fB = (__half*)(smem + FC_B_O);     // [64][264]
    float* bo_s = (float*)(smem + FC_BO_O);    // [64]

    int t = blockIdx.y;
    int base = blockIdx.x * 128;
    const float* feat = t ? f1 : f0;
    const float* W = fcW + (size_t)t * HID * D;          // [o][k]
    int tid = threadIdx.x;
    int wid = tid >> 5, lane = tid & 31;

    if (tid < 64) bo_s[tid] = __ldg(&fcb[t * HID + tid]);

    // A: 128 rows x 256 k fp32 -> fp16
    {
        int r = tid >> 2, kq = tid & 3;        // kq*64 col segment
#pragma unroll
        for (int rr = 0; rr < 2; rr++) {
            int row = base + rr * 64 + r;
            bool val = row < NP_TYPE;
            const float4* fp = (const float4*)(feat + (size_t)row * D) + kq * 16;
            __half* dst = &fA[(rr * 64 + r) * FC_AS + kq * 64];
#pragma unroll 4
            for (int i = 0; i < 16; i++) {
                float4 v = val ? __ldg(fp + i) : make_float4(0.f, 0.f, 0.f, 0.f);
                *(uint2*)(dst + i * 4) =
                    make_uint2(pack_f16(v.x, v.y), pack_f16(v.z, v.w));
            }
        }
    }
    // B: W 64 o x 256 k fp32 -> fp16 (row-major o, k contiguous)
    {
        int o = tid & 63, sq = tid >> 6;       // sq*64 k segment
        const float4* wp = (const float4*)(W + (size_t)o * D) + sq * 16;
        __half* dst = &fB[o * FC_AS + sq * 64];
#pragma unroll 4
        for (int i = 0; i < 16; i++) {
            float4 v = __ldg(wp + i);
            *(uint2*)(dst + i * 4) =
                make_uint2(pack_f16(v.x, v.y), pack_f16(v.z, v.w));
        }
    }
    __syncthreads();

    float cacc[8][4];
#pragma unroll
    for (int ti = 0; ti < 8; ti++)
#pragma unroll
        for (int j = 0; j < 4; j++) cacc[ti][j] = 0.f;

    int a_tile = lane >> 3;
    int a_row = wid * 16 + (lane & 7) + (a_tile & 1) * 8;
    int a_koff = (a_tile >> 1) * 8;
    int b_g = lane >> 3;
    int b_nbase = (b_g >> 1) * 8 + (lane & 7);
    int b_koff = (b_g & 1) * 8;

#pragma unroll
    for (int ks = 0; ks < 16; ks++) {
        uint32_t a0, a1, a2, a3;
        ldsm_x4(a0, a1, a2, a3, smem_u32(&fA[a_row * FC_AS + ks * 16 + a_koff]));
#pragma unroll
        for (int nt = 0; nt < 4; nt++) {
            uint32_t b0, b1, b2, b3;
            ldsm_x4(b0, b1, b2, b3,
                    smem_u32(&fB[(b_nbase + nt * 16) * FC_AS + ks * 16 + b_koff]));
            mma_f16(cacc[nt * 2 + 0], a0, a1, a2, a3, b0, b1);
            mma_f16(cacc[nt * 2 + 1], a0, a1, a2, a3, b2, b3);
        }
    }

    // epilogue: bias + scatter via type_idx
    int lr = lane >> 2, lc = lane & 3;
    int r0 = base + wid * 16 + lr, r1 = r0 + 8;
    const int* ti_p = type_idx + t * NP_TYPE;
    int d0 = (r0 < NP_TYPE) ? __ldg(&ti_p[r0]) : -1;
    int d1 = (r1 < NP_TYPE) ? __ldg(&ti_p[r1]) : -1;
#pragma unroll
    for (int ti = 0; ti < 8; ti++) {
        int col = ti * 8 + lc * 2;
        float b0v = bo_s[col], b1v = bo_s[col + 1];
        if (d0 >= 0)
            *(float2*)&g_transformed[(size_t)d0 * HID + col] =
                make_float2(cacc[ti][0] + b0v, cacc[ti][1] + b1v);
        if (d1 >= 0)
            *(float2*)&g_transformed[(size_t)d1 * HID + col] =
                make_float2(cacc[ti][2] + b0v, cacc[ti][3] + b1v);
    }
}

// -------- gatz on mma.sync fp16 (single pass): z = gather(h) @ W ------------
// grid (782, G4); 256 thr. CTA: 64 rows x 256 cols. Warp: 16r x 128c.
// el/er from fp16 h . wal (error ~1e-4 on logits, harmless through exp).
__global__ __launch_bounds__(256) void k_gatz_mma(
    const int* __restrict__ node_idx, const float* __restrict__ gatW)
{
    extern __shared__ char smem[];
    __half* ah = (__half*)(smem + GZ_AH_O);    // [64][72]
    __half* bh = (__half*)(smem + GZ_BH_O);    // [256][72]
    float* wal_s = (float*)(smem + GZ_WAL_O);  // [64][8]

    int g = blockIdx.y;
    int base = blockIdx.x * 64;
    int tid = threadIdx.x;
    int wid = tid >> 5, lane = tid & 31;
    const float* W = gatW + (size_t)g * HID * D;         // [k][o] k-major

    // A: gather 64 rows x 64 cols fp32 -> fp16
    {
        int r = tid >> 2, kq = tid & 3;
        int row = base + r;
        int node = (row < NP_G) ? __ldg(&node_idx[(size_t)g * NP_G + row]) : -1;
        const float4* hp = (const float4*)(g_transformed + (size_t)node * HID) + kq * 4;
#pragma unroll
        for (int i = 0; i < 4; i++) {
            float4 v = (node >= 0) ? __ldg(hp + i) : make_float4(0.f, 0.f, 0.f, 0.f);
            *(uint2*)&ah[r * GZ_S + kq * 16 + i * 4] =
                make_uint2(pack_f16(v.x, v.y), pack_f16(v.z, v.w));
        }
    }
    // B: W^T 256 o x 64 k fp16
    {
        int o = tid;
#pragma unroll 8
        for (int k = 0; k < 64; k++)
            bh[o * GZ_S + k] = __float2half(__ldg(&W[(size_t)k * D + o]));
    }
    wal_s[tid] = g_wal[g * 512 + tid];
    wal_s[tid + 256] = g_wal[g * 512 + tid + 256];
    __syncthreads();

    int rw = wid >> 1;            // row group 0..3
    int cw = wid & 1;             // col group 0..1
    float cacc[16][4];
#pragma unroll
    for (int ti = 0; ti < 16; ti++)
#pragma unroll
        for (int j = 0; j < 4; j++) cacc[ti][j] = 0.f;

    int a_tile = lane >> 3;
    int a_row = rw * 16 + (lane & 7) + (a_tile & 1) * 8;
    int a_koff = (a_tile >> 1) * 8;
    int b_g = lane >> 3;
    int b_nbase = cw * 128 + (b_g >> 1) * 8 + (lane & 7);
    int b_koff = (b_g & 1) * 8;

#pragma unroll
    for (int ks = 0; ks < 4; ks++) {
        uint32_t a0, a1, a2, a3;
        ldsm_x4(a0, a1, a2, a3, smem_u32(&ah[a_row * GZ_S + ks * 16 + a_koff]));
#pragma unroll
        for (int nt = 0; nt < 8; nt++) {
            uint32_t b0, b1, b2, b3;
            ldsm_x4(b0, b1, b2, b3,
                    smem_u32(&bh[(b_nbase + nt * 16) * GZ_S + ks * 16 + b_koff]));
            mma_f16(cacc[nt * 2 + 0], a0, a1, a2, a3, b0, b1);
            mma_f16(cacc[nt * 2 + 1], a0, a1, a2, a3, b2, b3);
        }
    }

    // z stores (fp32)
    {
        int lr = lane >> 2, lc = lane & 3;
        int r0 = base + rw * 16 + lr, r1 = r0 + 8;
        bool v0 = r0 < NP_G, v1 = r1 < NP_G;
        float* z0 = g_z + ((size_t)g * NP_G + r0) * D + cw * 128 + lc * 2;
        float* z1 = g_z + ((size_t)g * NP_G + r1) * D + cw * 128 + lc * 2;
#pragma unroll
        for (int ti = 0; ti < 16; ti++) {
            if (v0) *(float2*)(z0 + ti * 8) = make_float2(cacc[ti][0], cacc[ti][1]);
            if (v1) *(float2*)(z1 + ti * 8) = make_float2(cacc[ti][2], cacc[ti][3]);
        }
    }

    // el/er: h . wal (fp16 h)
    {
        int r = tid & 63;
        int ob = (tid >> 6) * 2;               // 0,2,4,6
        int row = base + r;
        if (row < NP_G) {
            float e0 = 0.f, e1 = 0.f;
#pragma unroll 8
            for (int k = 0; k < 64; k += 2) {
                __half2 hb = *(__half2*)&ah[r * GZ_S + k];
                float h0 = __low2float(hb), h1 = __high2float(hb);
                e0 += h0 * wal_s[k * 8 + ob]     + h1 * wal_s[(k + 1) * 8 + ob];
                e1 += h0 * wal_s[k * 8 + ob + 1] + h1 * wal_s[(k + 1) * 8 + ob + 1];
            }
            size_t nbase = ((size_t)g * NP_G + row) * NH;
            if (ob < 4) {
                g_el[nbase + ob] = e0;
                g_el[nbase + ob + 1] = e1;
            } else {
                g_er[nbase + ob - 4] = e0;
                g_er[nbase + ob - 3] = e1;
            }
        }
    }
}

// ------------------------------- CSR build ----------------------------------
__global__ void k_count(const int* __restrict__ dst) {
    int e = blockIdx.x * blockDim.x + threadIdx.x;
    if (e < G4 * E_G) {
        int g = e / E_G;
        atomicAdd(&g_deg[g * NP_G + __ldg(&dst[e])], 1);
    }
}

__global__ __launch_bounds__(1024) void k_scan() {
    __shared__ int ws[32];
    int g = blockIdx.x;
    int tid = threadIdx.x;
    int lane = tid & 31, wid = tid >> 5;
    const int CH = (NP_G + 1023) / 1024;   // 49
    int lo = tid * CH;
    int hi = min(lo + CH, NP_G);
    const int* deg = g_deg + g * NP_G;
    int s = 0;
    for (int i = lo; i < hi; i++) s += deg[i];
    int v = s;
#pragma unroll
    for (int off = 1; off < 32; off <<= 1) {
        int n = __shfl_up_sync(0xffffffffu, v, off);
        if (lane >= off) v += n;
    }
    if (lane == 31) ws[wid] = v;
    __syncthreads();
    if (wid == 0) {
        int w = ws[lane];
#pragma unroll
        for (int off = 1; off < 32; off <<= 1) {
            int n = __shfl_up_sync(0xffffffffu, w, off);
            if (lane >= off) w += n;
        }
        ws[lane] = w;
    }
    __syncthreads();
    int excl = v - s + (wid ? ws[wid - 1] : 0);
    int* offs = g_offs + g * (NP_G + 1);
    int* cur = g_cur + g * NP_G;
    int run = excl;
    for (int i = lo; i < hi; i++) {
        offs[i] = run;
        cur[i] = run;
        run += deg[i];
    }
    if (tid == 0) offs[NP_G] = E_G;
}

__global__ void k_fill(const int* __restrict__ src, const int* __restrict__ dst) {
    int e = blockIdx.x * blockDim.x + threadIdx.x;
    if (e >= G4 * E_G) return;
    int g = e / E_G;
    int gn = g * NP_G;
    int s = __ldg(&src[e]);
    int d = __ldg(&dst[e]);
    float4 elv = __ldg((const float4*)g_el + gn + s);
    float4 erv = __ldg((const float4*)g_er + gn + d);
    float e0 = elv.x + erv.x, e1 = elv.y + erv.y;
    float e2 = elv.z + erv.z, e3 = elv.w + erv.w;
    e0 = e0 > 0.f ? e0 : 0.2f * e0;
    e1 = e1 > 0.f ? e1 : 0.2f * e1;
    e2 = e2 > 0.f ? e2 : 0.2f * e2;
    e3 = e3 > 0.f ? e3 : 0.2f * e3;
    float4 ex = make_float4(__expf(e0), __expf(e1), __expf(e2), __expf(e3));
    int pos = atomicAdd(&g_cur[gn + d], 1);
    g_csr_src[(size_t)g * E_G + pos] = s;
    g_csr_ex[(size_t)g * E_G + pos] = ex;
}

// ------ aggregate: warp per TARGET, fused softmax, writes meta directly -----
__global__ __launch_bounds__(256) void k_aggregate(const int* __restrict__ tgt) {
    int t = (blockIdx.x * blockDim.x + threadIdx.x) >> 5;
    if (t >= G4 * T_TGT) return;
    int g = t / T_TGT;
    int lane = threadIdx.x & 31;
    int hsel = lane >> 3;
    int nl = __ldg(&tgt[t]);
    int beg = g_offs[g * (NP_G + 1) + nl];
    int end = g_offs[g * (NP_G + 1) + nl + 1];
    const int* cs = g_csr_src + (size_t)g * E_G;
    const float4* ce = g_csr_ex + (size_t)g * E_G;
    const float* zb = g_z + (size_t)g * NP_G * D;

    float4 a0 = {0.f, 0.f, 0.f, 0.f}, a1 = {0.f, 0.f, 0.f, 0.f};
    float den = 0.f;

    int i = beg;
    for (; i + 4 <= end; i += 4) {
        int s0 = __ldg(cs + i), s1 = __ldg(cs + i + 1);
        int s2 = __ldg(cs + i + 2), s3 = __ldg(cs + i + 3);
        float4 e0 = __ldg(ce + i), e1 = __ldg(ce + i + 1);
        float4 e2 = __ldg(ce + i + 2), e3 = __ldg(ce + i + 3);
        const float4* z0p = (const float4*)(zb + (size_t)s0 * D) + lane * 2;
        const float4* z1p = (const float4*)(zb + (size_t)s1 * D) + lane * 2;
        const float4* z2p = (const float4*)(zb + (size_t)s2 * D) + lane * 2;
        const float4* z3p = (const float4*)(zb + (size_t)s3 * D) + lane * 2;
        float4 za0 = __ldg(z0p), zb0 = __ldg(z0p + 1);
        float4 za1 = __ldg(z1p), zb1 = __ldg(z1p + 1);
        float4 za2 = __ldg(z2p), zb2 = __ldg(z2p + 1);
        float4 za3 = __ldg(z3p), zb3 = __ldg(z3p + 1);
        float x0 = (hsel == 0) ? e0.x : (hsel == 1) ? e0.y : (hsel == 2) ? e0.z : e0.w;
        float x1 = (hsel == 0) ? e1.x : (hsel == 1) ? e1.y : (hsel == 2) ? e1.z : e1.w;
        float x2 = (hsel == 0) ? e2.x : (hsel == 1) ? e2.y : (hsel == 2) ? e2.z : e2.w;
        float x3 = (hsel == 0) ? e3.x : (hsel == 1) ? e3.y : (hsel == 2) ? e3.z : e3.w;
        a0.x += x0 * za0.x; a0.y += x0 * za0.y; a0.z += x0 * za0.z; a0.w += x0 * za0.w;
        a1.x += x0 * zb0.x; a1.y += x0 * zb0.y; a1.z += x0 * zb0.z; a1.w += x0 * zb0.w;
        a0.x += x1 * za1.x; a0.y += x1 * za1.y; a0.z += x1 * za1.z; a0.w += x1 * za1.w;
        a1.x += x1 * zb1.x; a1.y += x1 * zb1.y; a1.z += x1 * zb1.z; a1.w += x1 * zb1.w;
        a0.x += x2 * za2.x; a0.y += x2 * za2.y; a0.z += x2 * za2.z; a0.w += x2 * za2.w;
        a1.x += x2 * zb2.x; a1.y += x2 * zb2.y; a1.z += x2 * zb2.z; a1.w += x2 * zb2.w;
        a0.x += x3 * za3.x; a0.y += x3 * za3.y; a0.z += x3 * za3.z; a0.w += x3 * za3.w;
        a1.x += x3 * zb3.x; a1.y += x3 * zb3.y; a1.z += x3 * zb3.z; a1.w += x3 * zb3.w;
        den += x0 + x1 + x2 + x3;
    }
    for (; i < end; i++) {
        int s0 = __ldg(cs + i);
        float4 e0 = __ldg(ce + i);
        const float4* z0p = (const float4*)(zb + (size_t)s0 * D) + lane * 2;
        float4 za = __ldg(z0p), zc = __ldg(z0p + 1);
        float x0 = (hsel == 0) ? e0.x : (hsel == 1) ? e0.y : (hsel == 2) ? e0.z : e0.w;
        a0.x += x0 * za.x; a0.y += x0 * za.y; a0.z += x0 * za.z; a0.w += x0 * za.w;
        a1.x += x0 * zc.x; a1.y += x0 * zc.y; a1.z += x0 * zc.z; a1.w += x0 * zc.w;
        den += x0;
    }
    float inv = 1.f / (den + 1e-9f);
    float v[8] = {a0.x * inv, a0.y * inv, a0.z * inv, a0.w * inv,
                  a1.x * inv, a1.y * inv, a1.z * inv, a1.w * inv};
#pragma unroll
    for (int j = 0; j < 8; j++) v[j] = v[j] > 0.f ? v[j] : expm1f(v[j]);
    float* op = g_meta + (size_t)t * D + lane * 8;
    *(float4*)op = make_float4(v[0], v[1], v[2], v[3]);
    *((float4*)op + 1) = make_float4(v[4], v[5], v[6], v[7]);
}

// ----- semantic attention on mma.sync bf16 HMMA -----------------------------
__global__ __launch_bounds__(256) void k_sem_mma(
    const float* __restrict__ semW, const float* __restrict__ semb,
    const float* __restrict__ semq)
{
    extern __shared__ char smem[];
    __nv_bfloat16* ftA = (__nv_bfloat16*)smem;               // [64][264]
    __nv_bfloat16* wt  = (__nv_bfloat16*)(smem + SEMM_W_O);  // [256][40]
    float*    bo_s = (float*)(smem + SEMM_BO_O);             // [256]
    uint32_t* qh_s = (uint32_t*)(smem + SEMM_QH_O);          // [128] packed f16x2
    float*  bucket = (float*)(smem + SEMM_BK_O);             // [2]

    const int BR = 2 * T_TGT;                                // 40000 = 625*64
    int tid = threadIdx.x;
    int wid = tid >> 5, lane = tid & 31;
    int b = blockIdx.y;
    int base = blockIdx.x * 64;
    const float* W = semW + (size_t)b * D * D;               // k-major [k][o]

    if (tid < 64) ((float4*)bo_s)[tid] = __ldg((const float4*)(semb + b * D) + tid);
    else if (tid < 192) {
        int j = tid - 64;
        float q0 = __ldg(&semq[b * D + 2 * j]);
        float q1 = __ldg(&semq[b * D + 2 * j + 1]);
        qh_s[j] = pack_f16(q0, q1);
    }
    if (tid < 2) bucket[tid] = 0.f;

    {
        int r = tid >> 2, kq = tid & 3;
        const float* arow = g_meta + ((size_t)b * BR + base + r) * D;
#pragma unroll
        for (int i = 0; i < 8; i++) {
            int k = kq * 64 + i * 8;
            float4 v0 = __ldg((const float4*)(arow + k));
            float4 v1 = __ldg((const float4*)(arow + k) + 1);
            uint4 pk;
            pk.x = pack_bf16(v0.x, v0.y);
            pk.y = pack_bf16(v0.z, v0.w);
            pk.z = pack_bf16(v1.x, v1.y);
            pk.w = pack_bf16(v1.z, v1.w);
            *(uint4*)&ftA[r * SEMM_AS + k] = pk;
        }
    }

    int rw = wid >> 1;
    int cw = wid & 1;
    float cacc[16][4];
#pragma unroll
    for (int ti = 0; ti < 16; ti++)
#pragma unroll
        for (int j = 0; j < 4; j++) cacc[ti][j] = 0.f;

    int a_tile = lane >> 3;
    int a_row = rw * 16 + (lane & 7) + (a_tile & 1) * 8;
    int a_koff = (a_tile >> 1) * 8;
    int b_g = lane >> 3;
    int b_nbase = cw * 128 + (b_g >> 1) * 8 + (lane & 7);
    int b_koff = (b_g & 1) * 8;

    for (int ch = 0; ch < 8; ch++) {
        __syncthreads();
        {
            int o = tid;
            const float* wcol = W + (size_t)(ch * 32) * D + o;
            uint32_t* wrow = (uint32_t*)&wt[o * SEMM_WS];
#pragma unroll
            for (int j = 0; j < 16; j++) {
                float va = __ldg(wcol + (size_t)(2 * j) * D);
                float vb = __ldg(wcol + (size_t)(2 * j + 1) * D);
                wrow[j] = pack_bf16(va, vb);
            }
        }
        __syncthreads();
#pragma unroll
        for (int ks = 0; ks < 2; ks++) {
            uint32_t a0, a1, a2, a3;
            ldsm_x4(a0, a1, a2, a3,
                    smem_u32(&ftA[a_row * SEMM_AS + ch * 32 + ks * 16 + a_koff]));
#pragma unroll
            for (int nt = 0; nt < 8; nt++) {
                uint32_t b0, b1, b2, b3;
                ldsm_x4(b0, b1, b2, b3,
                        smem_u32(&wt[(b_nbase + nt * 16) * SEMM_WS + ks * 16 + b_koff]));
                mma_bf16(cacc[nt * 2 + 0], a0, a1, a2, a3, b0, b1);
                mma_bf16(cacc[nt * 2 + 1], a0, a1, a2, a3, b2, b3);
            }
        }
    }

    int lr = lane >> 2, lc = lane & 3;
    float rs0 = 0.f, rs1 = 0.f;
#pragma unroll
    for (int ti = 0; ti < 16; ti++) {
        int col = cw * 128 + ti * 8 + lc * 2;
        uint32_t qh = qh_s[col >> 1];
        float b0v = bo_s[col], b1v = bo_s[col + 1];
        rs0 += tanh_dot2(cacc[ti][0] + b0v, cacc[ti][1] + b1v, qh);
        rs1 += tanh_dot2(cacc[ti][2] + b0v, cacc[ti][3] + b1v, qh);
    }
    rs0 += __shfl_down_sync(0xffffffffu, rs0, 2, 4);
    rs0 += __shfl_down_sync(0xffffffffu, rs0, 1, 4);
    rs1 += __shfl_down_sync(0xffffffffu, rs1, 2, 4);
    rs1 += __shfl_down_sync(0xffffffffu, rs1, 1, 4);
    if (lc == 0) {
        int r0 = base + rw * 16 + lr;
        int r1 = r0 + 8;
        atomicAdd(&bucket[r0 >= T_TGT ? 1 : 0], rs0);
        atomicAdd(&bucket[r1 >= T_TGT ? 1 : 0], rs1);
    }
    __syncthreads();
    if (tid < 2 && bucket[tid] != 0.f) atomicAdd(&g_wsum[b * 2 + tid], bucket[tid]);
}

// -------------- combine: beta-blend metas, @ fcout_W + bias -----------------
__global__ __launch_bounds__(256) void k_combine(
    const float* __restrict__ fW, const float* __restrict__ fb,
    float* __restrict__ outp)
{
    __shared__ float ft[64][128];   // 32 KB
    __shared__ float wt[64][64];    // 16 KB

    int b = blockIdx.y;
    int base = blockIdx.x * 128;
    int tid = threadIdx.x;
    int rg = tid & 31, cg = tid >> 5;

    float w0 = g_wsum[b * 2 + 0] * (1.f / T_TGT);
    float w1 = g_wsum[b * 2 + 1] * (1.f / T_TGT);
    float mx = fmaxf(w0, w1);
    float b0 = __expf(w0 - mx), b1 = __expf(w1 - mx);
    float sm = b0 + b1;
    b0 /= sm; b1 /= sm;

    const float* m0 = g_meta + ((size_t)(b * 2 + 0) * T_TGT) * D;
    const float* m1 = g_meta + ((size_t)(b * 2 + 1) * T_TGT) * D;
    const float* W = fW + (size_t)b * D * OUT_DIM;

    float acc[4][8];
#pragma unroll
    for (int a = 0; a < 4; a++)
#pragma unroll
        for (int j = 0; j < 8; j++) acc[a][j] = 0.f;

    for (int ch = 0; ch < 4; ch++) {
        __syncthreads();
        {
            int r = tid & 127, qb = tid >> 7;
            int row = base + r;
            bool val = row < T_TGT;
            const float4* p0 = (const float4*)(m0 + (size_t)row * D) + ch * 16;
            const float4* p1 = (const float4*)(m1 + (size_t)row * D) + ch * 16;
#pragma unroll
            for (int i = 0; i < 8; i++) {
                int q = qb + i * 2;
                float4 v0 = val ? __ldg(p0 + q) : make_float4(0.f, 0.f, 0.f, 0.f);
                float4 v1 = val ? __ldg(p1 + q) : make_float4(0.f, 0.f, 0.f, 0.f);
                ft[q * 4 + 0][r] = b0 * v0.x + b1 * v1.x;
                ft[q * 4 + 1][r] = b0 * v0.y + b1 * v1.y;
                ft[q * 4 + 2][r] = b0 * v0.z + b1 * v1.z;
                ft[q * 4 + 3][r] = b0 * v0.w + b1 * v1.w;
            }
        }
        {
            const float4* wp = (const float4*)(W + (size_t)ch * 64 * OUT_DIM);
            float4* wd = (float4*)&wt[0][0];
#pragma unroll
            for (int i = 0; i < 4; i++)
                wd[tid + i * 256] = __ldg(wp + tid + i * 256);
        }
        __syncthreads();
#pragma unroll 16
        for (int k = 0; k < 64; k++) {
            float4 fv = *(const float4*)&ft[k][rg * 4];
            float4 wv0 = *(const float4*)&wt[k][cg * 8];
            float4 wv1 = *(const float4*)&wt[k][cg * 8 + 4];
            float fr[4] = {fv.x, fv.y, fv.z, fv.w};
            float wc[8] = {wv0.x, wv0.y, wv0.z, wv0.w, wv1.x, wv1.y, wv1.z, wv1.w};
#pragma unroll
            for (int a = 0; a < 4; a++)
#pragma unroll
                for (int j = 0; j < 8; j++) acc[a][j] += fr[a] * wc[j];
        }
    }
    float bo[8];
#pragma unroll
    for (int j = 0; j < 8; j++) bo[j] = __ldg(&fb[b * OUT_DIM + cg * 8 + j]);
#pragma unroll
    for (int a = 0; a < 4; a++) {
        int row = base + rg * 4 + a;
        if (row < T_TGT) {
            float* op = outp + ((size_t)b * T_TGT + row) * OUT_DIM + cg * 8;
            *(float4*)op = make_float4(acc[a][0] + bo[0], acc[a][1] + bo[1],
                                       acc[a][2] + bo[2], acc[a][3] + bo[3]);
            *((float4*)op + 1) = make_float4(acc[a][4] + bo[4], acc[a][5] + bo[5],
                                             acc[a][6] + bo[6], acc[a][7] + bo[7]);
        }
    }
}

// ------------------------------- launch -------------------------------------
extern "C" void kernel_launch(void* const* d_in, const int* in_sizes, int n_in,
                              void* d_out, int out_size)
{
    const float* features0 = (const float*)d_in[0];
    const float* features1 = (const float*)d_in[1];
    const float* fc_W      = (const float*)d_in[2];
    const float* fc_b      = (const float*)d_in[3];
    const float* gat_W     = (const float*)d_in[4];
    const float* attn_l    = (const float*)d_in[5];
    const float* attn_r    = (const float*)d_in[6];
    const float* sem_W     = (const float*)d_in[7];
    const float* sem_b     = (const float*)d_in[8];
    const float* sem_q     = (const float*)d_in[9];
    const float* fcout_W   = (const float*)d_in[10];
    const float* fcout_b   = (const float*)d_in[11];
    const int*   type_idx  = (const int*)d_in[12];
    const int*   node_idx  = (const int*)d_in[13];
    const int*   edge_src  = (const int*)d_in[14];
    const int*   edge_dst  = (const int*)d_in[15];
    const int*   tgt_idx   = (const int*)d_in[16];
    float* out = (float*)d_out;

    static cudaStream_t s_side = nullptr;
    static cudaEvent_t ev_fork = nullptr, ev_join = nullptr;
    static bool attr_done = false;
    if (!s_side) {
        cudaStreamCreateWithFlags(&s_side, cudaStreamNonBlocking);
        cudaEventCreateWithFlags(&ev_fork, cudaEventDisableTiming);
        cudaEventCreateWithFlags(&ev_join, cudaEventDisableTiming);
    }
    if (!attr_done) {
        cudaFuncSetAttribute(k_sem_mma, cudaFuncAttributeMaxDynamicSharedMemorySize,
                             SEMM_SZ);
        cudaFuncSetAttribute(k_gatz_mma, cudaFuncAttributeMaxDynamicSharedMemorySize,
                             GZ_SZ);
        cudaFuncSetAttribute(k_fc_mma, cudaFuncAttributeMaxDynamicSharedMemorySize,
                             FC_SZ);
        attr_done = true;
    }

    k_init<<<(G4 * NP_G + 255) / 256, 256>>>();
    k_wal<<<G4, 512>>>(gat_W, attn_l, attn_r);

    cudaEventRecord(ev_fork, 0);
    cudaStreamWaitEvent(s_side, ev_fork, 0);
    k_count<<<(G4 * E_G + 255) / 256, 256, 0, s_side>>>(edge_dst);
    k_scan<<<G4, 1024, 0, s_side>>>();
    cudaEventRecord(ev_join, s_side);

    k_fc_mma<<<dim3((NP_TYPE + 127) / 128, 2), 256, FC_SZ>>>(
        features0, features1, fc_W, fc_b, type_idx);
    k_gatz_mma<<<dim3((NP_G + 63) / 64, G4), 256, GZ_SZ>>>(node_idx, gat_W);

    cudaStreamWaitEvent(0, ev_join, 0);
    k_fill<<<(G4 * E_G + 255) / 256, 256>>>(edge_src, edge_dst);
    k_aggregate<<<(G4 * T_TGT) / 8, 256>>>(tgt_idx);
    k_sem_mma<<<dim3((2 * T_TGT) / 64, 2), 256, SEMM_SZ>>>(sem_W, sem_b, sem_q);
    k_combine<<<dim3((T_TGT + 127) / 128, 2), 256>>>(fcout_W, fcout_b, out);
}

// round 12
// speedup vs baseline: 2.4323x; 1.4567x over previous
#include <cuda_runtime.h>
#include <cuda_bf16.h>
#include <cuda_fp16.h>
#include <math.h>
#include <stdint.h>

#define N_TOTAL 100000
#define NP_TYPE 50000
#define NP_G    50000
#define E_G     500000
#define NH      4
#define HD      64
#define HID     64
#define D       256
#define OUT_DIM 64
#define T_TGT   20000
#define G4      4
#define OFFS_S  50016   // padded offs stride (16B-aligned per graph)

// ------------------------- scratch (static device globals) -------------------
__device__ float  g_transformed[N_TOTAL * HID];          // 25.6 MB
__device__ float  g_z[(size_t)G4 * NP_G * D];            // 204.8 MB
__device__ float  g_el[G4 * NP_G * NH];
__device__ float  g_er[G4 * NP_G * NH];
__device__ float  g_wal[G4 * 64 * 8];                    // W@attn per graph
__device__ int    g_istgt[G4 * NP_G];
__device__ int    g_deg[G4 * NP_G];
__device__ int    g_offs[G4 * OFFS_S];
__device__ int    g_cur[G4 * NP_G];
__device__ int    g_csr_src[G4 * E_G];
__device__ float4 g_csr_ex[G4 * E_G];
__device__ float  g_meta[(size_t)G4 * T_TGT * D];        // 81.9 MB
__device__ float  g_wsum[4];
// preconverted weights
__device__ __half         g_fcWh[2 * 64 * 256];          // [t][o][k]
__device__ __half         g_gatWT[G4 * 256 * 64];        // [g][o][k]
__device__ __nv_bfloat16  g_semWT[2 * 8 * 256 * 32];     // [b][ch][o][kk]

// ------------------------------ small helpers --------------------------------
__device__ __forceinline__ uint32_t smem_u32(const void* p) {
    uint32_t a;
    asm("{ .reg .u64 t; cvta.to.shared.u64 t, %1; cvt.u32.u64 %0, t; }" : "=r"(a) : "l"(p));
    return a;
}
__device__ __forceinline__ uint32_t pack_bf16(float lo, float hi) {
    uint32_t r;
    asm("cvt.rn.bf16x2.f32 %0, %1, %2;" : "=r"(r) : "f"(hi), "f"(lo));
    return r;
}
__device__ __forceinline__ uint32_t pack_f16(float lo, float hi) {
    uint32_t r;
    asm("cvt.rn.f16x2.f32 %0, %1, %2;" : "=r"(r) : "f"(hi), "f"(lo));
    return r;
}
__device__ __forceinline__ float tanh_dot2(float x0, float x1, uint32_t qh) {
    uint32_t xp = pack_f16(x0, x1), tp, pp;
    asm("tanh.approx.f16x2 %0, %1;" : "=r"(tp) : "r"(xp));
    asm("mul.f16x2 %0, %1, %2;" : "=r"(pp) : "r"(tp), "r"(qh));
    __half2 h = *reinterpret_cast<__half2*>(&pp);
    return __low2float(h) + __high2float(h);
}
__device__ __forceinline__ void ldsm_x4(uint32_t& r0, uint32_t& r1, uint32_t& r2,
                                        uint32_t& r3, uint32_t addr) {
    asm volatile("ldmatrix.sync.aligned.m8n8.x4.shared.b16 {%0,%1,%2,%3}, [%4];"
                 : "=r"(r0), "=r"(r1), "=r"(r2), "=r"(r3) : "r"(addr));
}
__device__ __forceinline__ void mma_bf16(float* c, uint32_t a0, uint32_t a1,
                                         uint32_t a2, uint32_t a3,
                                         uint32_t b0, uint32_t b1) {
    asm volatile(
        "mma.sync.aligned.m16n8k16.row.col.f32.bf16.bf16.f32 "
        "{%0,%1,%2,%3}, {%4,%5,%6,%7}, {%8,%9}, {%0,%1,%2,%3};"
        : "+f"(c[0]), "+f"(c[1]), "+f"(c[2]), "+f"(c[3])
        : "r"(a0), "r"(a1), "r"(a2), "r"(a3), "r"(b0), "r"(b1));
}
__device__ __forceinline__ void mma_f16(float* c, uint32_t a0, uint32_t a1,
                                        uint32_t a2, uint32_t a3,
                                        uint32_t b0, uint32_t b1) {
    asm volatile(
        "mma.sync.aligned.m16n8k16.row.col.f32.f16.f16.f32 "
        "{%0,%1,%2,%3}, {%4,%5,%6,%7}, {%8,%9}, {%0,%1,%2,%3};"
        : "+f"(c[0]), "+f"(c[1]), "+f"(c[2]), "+f"(c[3])
        : "r"(a0), "r"(a1), "r"(a2), "r"(a3), "r"(b0), "r"(b1));
}

// k_sem_mma dynamic smem layout
#define SEMM_AS   264
#define SEMM_WS   40
#define SEMM_A_B  (64 * SEMM_AS * 2)
#define SEMM_W_O  SEMM_A_B
#define SEMM_W_B  (256 * SEMM_WS * 2)
#define SEMM_BO_O (SEMM_W_O + SEMM_W_B)
#define SEMM_QH_O (SEMM_BO_O + 1024)
#define SEMM_BK_O (SEMM_QH_O + 512)
#define SEMM_SZ   (SEMM_BK_O + 128)

// k_gatz_mma fp16 layout
#define GZ_S      72
#define GZ_AH_O   0
#define GZ_BH_O   9216
#define GZ_WAL_O  46080
#define GZ_SZ     (GZ_WAL_O + 2048)

// k_fc_mma fp16 layout
#define FC_AS     264
#define FC_A_O    0
#define FC_A_B    (128 * FC_AS * 2)
#define FC_B_O    FC_A_B
#define FC_B_B    (64 * FC_AS * 2)
#define FC_BO_O   (FC_B_O + FC_B_B)
#define FC_SZ     (FC_BO_O + 256)

// ------------------------------- init ---------------------------------------
__global__ void k_init() {
    int i = blockIdx.x * blockDim.x + threadIdx.x;
    if (i < G4 * NP_G) { g_deg[i] = 0; g_istgt[i] = 0; }
    if (i < 4) g_wsum[i] = 0.f;
}

__global__ void k_mark(const int* __restrict__ tgt) {
    int t = blockIdx.x * blockDim.x + threadIdx.x;
    if (t < G4 * T_TGT) {
        int g = t / T_TGT;
        g_istgt[g * NP_G + __ldg(&tgt[t])] = 1;
    }
}

// one-time weight preconversion into MMA-friendly layouts
__global__ void k_wprep(const float* __restrict__ fcW,
                        const float* __restrict__ gatW,
                        const float* __restrict__ semW) {
    int i = blockIdx.x * blockDim.x + threadIdx.x;
    if (i < 2 * 64 * 256) {
        g_fcWh[i] = __float2half(__ldg(&fcW[i]));
        return;
    }
    int j = i - 2 * 64 * 256;
    if (j < G4 * 256 * 64) {
        int g = j >> 14, r = j & 16383;
        int o = r >> 6, k = r & 63;
        g_gatWT[j] = __float2half(__ldg(&gatW[g * 16384 + k * 256 + o]));
        return;
    }
    int m = j - G4 * 256 * 64;
    if (m < 2 * 8 * 256 * 32) {
        int b = m >> 16, r2 = m & 65535;
        int ch = r2 >> 13, r3 = r2 & 8191;
        int o = r3 >> 5, kk = r3 & 31;
        g_semWT[m] = __float2bfloat16(__ldg(&semW[b * 65536 + (ch * 32 + kk) * 256 + o]));
    }
}

// ---- wal/war: per-graph W @ attn --------------------------------------------
__global__ void k_wal(const float* __restrict__ gatW,
                      const float* __restrict__ attn_l,
                      const float* __restrict__ attn_r)
{
    int g = blockIdx.x;
    int idx = threadIdx.x;
    int k = idx >> 3, o = idx & 7;
    int side = o >> 2, h = o & 3;
    const float* att = (side ? attn_r : attn_l) + (size_t)g * D + h * 64;
    const float* wr = gatW + (size_t)g * HID * D + (size_t)k * D + h * 64;
    float s = 0.f;
#pragma unroll 16
    for (int d = 0; d < 64; d++) s += __ldg(&wr[d]) * __ldg(&att[d]);
    g_wal[g * 512 + k * 8 + o] = s;
}

// ---------- fc on mma.sync fp16 ----------------------------------------------
__global__ __launch_bounds__(256) void k_fc_mma(
    const float* __restrict__ f0, const float* __restrict__ f1,
    const float* __restrict__ fcb, const int* __restrict__ type_idx)
{
    extern __shared__ char smem[];
    __half* fA = (__half*)(smem + FC_A_O);
    __half* fB = (__half*)(smem + FC_B_O);
    float* bo_s = (float*)(smem + FC_BO_O);

    int t = blockIdx.y;
    int base = blockIdx.x * 128;
    const float* feat = t ? f1 : f0;
    int tid = threadIdx.x;
    int wid = tid >> 5, lane = tid & 31;

    if (tid < 64) bo_s[tid] = __ldg(&fcb[t * HID + tid]);

    {   // A: 128 rows x 256 k fp32 -> fp16
        int r = tid >> 2, kq = tid & 3;
#pragma unroll
        for (int rr = 0; rr < 2; rr++) {
            int row = base + rr * 64 + r;
            bool val = row < NP_TYPE;
            const float4* fp = (const float4*)(feat + (size_t)row * D) + kq * 16;
            __half* dst = &fA[(rr * 64 + r) * FC_AS + kq * 64];
#pragma unroll 4
            for (int i = 0; i < 16; i++) {
                float4 v = val ? __ldg(fp + i) : make_float4(0.f, 0.f, 0.f, 0.f);
                *(uint2*)(dst + i * 4) =
                    make_uint2(pack_f16(v.x, v.y), pack_f16(v.z, v.w));
            }
        }
    }
    {   // B: coalesced copy of preconverted fp16 weights
        int o = tid & 63, sq = tid >> 6;
        const uint4* wsrc = (const uint4*)&g_fcWh[(size_t)t * 16384 + o * 256 + sq * 64];
        uint4* wdst = (uint4*)&fB[o * FC_AS + sq * 64];
#pragma unroll
        for (int i = 0; i < 8; i++) wdst[i] = __ldg(wsrc + i);
    }
    __syncthreads();

    float cacc[8][4];
#pragma unroll
    for (int ti = 0; ti < 8; ti++)
#pragma unroll
        for (int j = 0; j < 4; j++) cacc[ti][j] = 0.f;

    int a_tile = lane >> 3;
    int a_row = wid * 16 + (lane & 7) + (a_tile & 1) * 8;
    int a_koff = (a_tile >> 1) * 8;
    int b_g = lane >> 3;
    int b_nbase = (b_g >> 1) * 8 + (lane & 7);
    int b_koff = (b_g & 1) * 8;

#pragma unroll
    for (int ks = 0; ks < 16; ks++) {
        uint32_t a0, a1, a2, a3;
        ldsm_x4(a0, a1, a2, a3, smem_u32(&fA[a_row * FC_AS + ks * 16 + a_koff]));
#pragma unroll
        for (int nt = 0; nt < 4; nt++) {
            uint32_t b0, b1, b2, b3;
            ldsm_x4(b0, b1, b2, b3,
                    smem_u32(&fB[(b_nbase + nt * 16) * FC_AS + ks * 16 + b_koff]));
            mma_f16(cacc[nt * 2 + 0], a0, a1, a2, a3, b0, b1);
            mma_f16(cacc[nt * 2 + 1], a0, a1, a2, a3, b2, b3);
        }
    }

    int lr = lane >> 2, lc = lane & 3;
    int r0 = base + wid * 16 + lr, r1 = r0 + 8;
    const int* ti_p = type_idx + t * NP_TYPE;
    int d0 = (r0 < NP_TYPE) ? __ldg(&ti_p[r0]) : -1;
    int d1 = (r1 < NP_TYPE) ? __ldg(&ti_p[r1]) : -1;
#pragma unroll
    for (int ti = 0; ti < 8; ti++) {
        int col = ti * 8 + lc * 2;
        float b0v = bo_s[col], b1v = bo_s[col + 1];
        if (d0 >= 0)
            *(float2*)&g_transformed[(size_t)d0 * HID + col] =
                make_float2(cacc[ti][0] + b0v, cacc[ti][1] + b1v);
        if (d1 >= 0)
            *(float2*)&g_transformed[(size_t)d1 * HID + col] =
                make_float2(cacc[ti][2] + b0v, cacc[ti][3] + b1v);
    }
}

// -------- gatz on mma.sync fp16 ----------------------------------------------
__global__ __launch_bounds__(256) void k_gatz_mma(const int* __restrict__ node_idx)
{
    extern __shared__ char smem[];
    __half* ah = (__half*)(smem + GZ_AH_O);
    __half* bh = (__half*)(smem + GZ_BH_O);
    float* wal_s = (float*)(smem + GZ_WAL_O);

    int g = blockIdx.y;
    int base = blockIdx.x * 64;
    int tid = threadIdx.x;
    int wid = tid >> 5, lane = tid & 31;

    {   // A: gather 64 rows x 64 cols fp32 -> fp16
        int r = tid >> 2, kq = tid & 3;
        int row = base + r;
        int node = (row < NP_G) ? __ldg(&node_idx[(size_t)g * NP_G + row]) : -1;
        const float4* hp = (const float4*)(g_transformed + (size_t)node * HID) + kq * 4;
#pragma unroll
        for (int i = 0; i < 4; i++) {
            float4 v = (node >= 0) ? __ldg(hp + i) : make_float4(0.f, 0.f, 0.f, 0.f);
            *(uint2*)&ah[r * GZ_S + kq * 16 + i * 4] =
                make_uint2(pack_f16(v.x, v.y), pack_f16(v.z, v.w));
        }
    }
    {   // B: coalesced copy of preconverted W^T fp16
        const uint4* wsrc = (const uint4*)&g_gatWT[(size_t)g * 16384 + tid * 64];
        uint4* wdst = (uint4*)&bh[tid * GZ_S];
#pragma unroll
        for (int i = 0; i < 8; i++) wdst[i] = __ldg(wsrc + i);
    }
    wal_s[tid] = g_wal[g * 512 + tid];
    wal_s[tid + 256] = g_wal[g * 512 + tid + 256];
    __syncthreads();

    int rw = wid >> 1, cw = wid & 1;
    float cacc[16][4];
#pragma unroll
    for (int ti = 0; ti < 16; ti++)
#pragma unroll
        for (int j = 0; j < 4; j++) cacc[ti][j] = 0.f;

    int a_tile = lane >> 3;
    int a_row = rw * 16 + (lane & 7) + (a_tile & 1) * 8;
    int a_koff = (a_tile >> 1) * 8;
    int b_g = lane >> 3;
    int b_nbase = cw * 128 + (b_g >> 1) * 8 + (lane & 7);
    int b_koff = (b_g & 1) * 8;

#pragma unroll
    for (int ks = 0; ks < 4; ks++) {
        uint32_t a0, a1, a2, a3;
        ldsm_x4(a0, a1, a2, a3, smem_u32(&ah[a_row * GZ_S + ks * 16 + a_koff]));
#pragma unroll
        for (int nt = 0; nt < 8; nt++) {
            uint32_t b0, b1, b2, b3;
            ldsm_x4(b0, b1, b2, b3,
                    smem_u32(&bh[(b_nbase + nt * 16) * GZ_S + ks * 16 + b_koff]));
            mma_f16(cacc[nt * 2 + 0], a0, a1, a2, a3, b0, b1);
            mma_f16(cacc[nt * 2 + 1], a0, a1, a2, a3, b2, b3);
        }
    }

    {   // z stores (fp32)
        int lr = lane >> 2, lc = lane & 3;
        int r0 = base + rw * 16 + lr, r1 = r0 + 8;
        bool v0 = r0 < NP_G, v1 = r1 < NP_G;
        float* z0 = g_z + ((size_t)g * NP_G + r0) * D + cw * 128 + lc * 2;
        float* z1 = g_z + ((size_t)g * NP_G + r1) * D + cw * 128 + lc * 2;
#pragma unroll
        for (int ti = 0; ti < 16; ti++) {
            if (v0) *(float2*)(z0 + ti * 8) = make_float2(cacc[ti][0], cacc[ti][1]);
            if (v1) *(float2*)(z1 + ti * 8) = make_float2(cacc[ti][2], cacc[ti][3]);
        }
    }

    {   // el/er: h . wal (fp16 h)
        int r = tid & 63;
        int ob = (tid >> 6) * 2;
        int row = base + r;
        if (row < NP_G) {
            float e0 = 0.f, e1 = 0.f;
#pragma unroll 8
            for (int k = 0; k < 64; k += 2) {
                __half2 hb = *(__half2*)&ah[r * GZ_S + k];
                float h0 = __low2float(hb), h1 = __high2float(hb);
                e0 += h0 * wal_s[k * 8 + ob]     + h1 * wal_s[(k + 1) * 8 + ob];
                e1 += h0 * wal_s[k * 8 + ob + 1] + h1 * wal_s[(k + 1) * 8 + ob + 1];
            }
            size_t nbase = ((size_t)g * NP_G + row) * NH;
            if (ob < 4) {
                g_el[nbase + ob] = e0;
                g_el[nbase + ob + 1] = e1;
            } else {
                g_er[nbase + ob - 4] = e0;
                g_er[nbase + ob - 3] = e1;
            }
        }
    }
}

// ------------------------------- CSR build (target-filtered) -----------------
__global__ void k_count(const int* __restrict__ dst) {
    int e = blockIdx.x * blockDim.x + threadIdx.x;
    if (e < G4 * E_G) {
        int g = e / E_G;
        int gn = g * NP_G + __ldg(&dst[e]);
        if (g_istgt[gn]) atomicAdd(&g_deg[gn], 1);
    }
}

// vectorized single-block-per-graph scan; offs[NP_G] = filtered total
__global__ __launch_bounds__(1024) void k_scan() {
    __shared__ int ws[32];
    int g = blockIdx.x;
    int tid = threadIdx.x;
    int lane = tid & 31, wid = tid >> 5;
    const int CH = 52;
    int lo = tid * CH;
    const int* deg = g_deg + g * NP_G;
    bool fast = (lo + CH) <= NP_G;
    int s = 0;
    if (fast) {
        const int4* p = (const int4*)(deg + lo);
#pragma unroll
        for (int c = 0; c < 13; c++) {
            int4 v = p[c];
            s += v.x + v.y + v.z + v.w;
        }
    } else {
        for (int i = lo; i < NP_G; i++) s += deg[i];
    }
    int v = s;
#pragma unroll
    for (int off = 1; off < 32; off <<= 1) {
        int n = __shfl_up_sync(0xffffffffu, v, off);
        if (lane >= off) v += n;
    }
    if (lane == 31) ws[wid] = v;
    __syncthreads();
    if (wid == 0) {
        int w = ws[lane];
#pragma unroll
        for (int off = 1; off < 32; off <<= 1) {
            int n = __shfl_up_sync(0xffffffffu, w, off);
            if (lane >= off) w += n;
        }
        ws[lane] = w;
    }
    __syncthreads();
    int run = v - s + (wid ? ws[wid - 1] : 0);
    int* offs = g_offs + g * OFFS_S;
    int* cur = g_cur + g * NP_G;
    if (fast) {
        const int4* p = (const int4*)(deg + lo);
        int4* po = (int4*)(offs + lo);
        int4* pc = (int4*)(cur + lo);
#pragma unroll
        for (int c = 0; c < 13; c++) {
            int4 d4 = p[c];
            int4 o4;
            o4.x = run;
            o4.y = run + d4.x;
            o4.z = o4.y + d4.y;
            o4.w = o4.z + d4.z;
            run = o4.w + d4.w;
            po[c] = o4;
            pc[c] = o4;
        }
    } else {
        for (int i = lo; i < NP_G; i++) {
            offs[i] = run;
            cur[i] = run;
            run += deg[i];
        }
    }
    if (tid == 0) offs[NP_G] = ws[31];
}

__global__ void k_fill(const int* __restrict__ src, const int* __restrict__ dst,
                       int gbase) {
    int e = blockIdx.x * blockDim.x + threadIdx.x;
    if (e >= 2 * E_G) return;
    int gl = e / E_G;
    int g = gbase + gl;
    size_t eidx = (size_t)g * E_G + (e - gl * E_G);
    int d = __ldg(&dst[eidx]);
    int gn = g * NP_G;
    if (!g_istgt[gn + d]) return;
    int s = __ldg(&src[eidx]);
    float4 elv = __ldg((const float4*)g_el + gn + s);
    float4 erv = __ldg((const float4*)g_er + gn + d);
    float e0 = elv.x + erv.x, e1 = elv.y + erv.y;
    float e2 = elv.z + erv.z, e3 = elv.w + erv.w;
    e0 = e0 > 0.f ? e0 : 0.2f * e0;
    e1 = e1 > 0.f ? e1 : 0.2f * e1;
    e2 = e2 > 0.f ? e2 : 0.2f * e2;
    e3 = e3 > 0.f ? e3 : 0.2f * e3;
    float4 ex = make_float4(__expf(e0), __expf(e1), __expf(e2), __expf(e3));
    int pos = atomicAdd(&g_cur[gn + d], 1);
    g_csr_src[(size_t)g * E_G + pos] = s;
    g_csr_ex[(size_t)g * E_G + pos] = ex;
}

// ------ aggregate: warp per TARGET, fused softmax, writes meta directly -----
__global__ __launch_bounds__(256) void k_aggregate(const int* __restrict__ tgt,
                                                   int gbase) {
    int t = (blockIdx.x * blockDim.x + threadIdx.x) >> 5;
    if (t >= 2 * T_TGT) return;
    int g = gbase + t / T_TGT;
    int tglob = gbase * T_TGT + t;
    int lane = threadIdx.x & 31;
    int hsel = lane >> 3;
    int nl = __ldg(&tgt[tglob]);
    int beg = g_offs[g * OFFS_S + nl];
    int end = g_offs[g * OFFS_S + nl + 1];
    const int* cs = g_csr_src + (size_t)g * E_G;
    const float4* ce = g_csr_ex + (size_t)g * E_G;
    const float* zb = g_z + (size_t)g * NP_G * D;

    float4 a0 = {0.f, 0.f, 0.f, 0.f}, a1 = {0.f, 0.f, 0.f, 0.f};
    float den = 0.f;

    int i = beg;
    for (; i + 4 <= end; i += 4) {
        int s0 = __ldg(cs + i), s1 = __ldg(cs + i + 1);
        int s2 = __ldg(cs + i + 2), s3 = __ldg(cs + i + 3);
        float4 e0 = __ldg(ce + i), e1 = __ldg(ce + i + 1);
        float4 e2 = __ldg(ce + i + 2), e3 = __ldg(ce + i + 3);
        const float4* z0p = (const float4*)(zb + (size_t)s0 * D) + lane * 2;
        const float4* z1p = (const float4*)(zb + (size_t)s1 * D) + lane * 2;
        const float4* z2p = (const float4*)(zb + (size_t)s2 * D) + lane * 2;
        const float4* z3p = (const float4*)(zb + (size_t)s3 * D) + lane * 2;
        float4 za0 = __ldg(z0p), zb0 = __ldg(z0p + 1);
        float4 za1 = __ldg(z1p), zb1 = __ldg(z1p + 1);
        float4 za2 = __ldg(z2p), zb2 = __ldg(z2p + 1);
        float4 za3 = __ldg(z3p), zb3 = __ldg(z3p + 1);
        float x0 = (hsel == 0) ? e0.x : (hsel == 1) ? e0.y : (hsel == 2) ? e0.z : e0.w;
        float x1 = (hsel == 0) ? e1.x : (hsel == 1) ? e1.y : (hsel == 2) ? e1.z : e1.w;
        float x2 = (hsel == 0) ? e2.x : (hsel == 1) ? e2.y : (hsel == 2) ? e2.z : e2.w;
        float x3 = (hsel == 0) ? e3.x : (hsel == 1) ? e3.y : (hsel == 2) ? e3.z : e3.w;
        a0.x += x0 * za0.x; a0.y += x0 * za0.y; a0.z += x0 * za0.z; a0.w += x0 * za0.w;
        a1.x += x0 * zb0.x; a1.y += x0 * zb0.y; a1.z += x0 * zb0.z; a1.w += x0 * zb0.w;
        a0.x += x1 * za1.x; a0.y += x1 * za1.y; a0.z += x1 * za1.z; a0.w += x1 * za1.w;
        a1.x += x1 * zb1.x; a1.y += x1 * zb1.y; a1.z += x1 * zb1.z; a1.w += x1 * zb1.w;
        a0.x += x2 * za2.x; a0.y += x2 * za2.y; a0.z += x2 * za2.z; a0.w += x2 * za2.w;
        a1.x += x2 * zb2.x; a1.y += x2 * zb2.y; a1.z += x2 * zb2.z; a1.w += x2 * zb2.w;
        a0.x += x3 * za3.x; a0.y += x3 * za3.y; a0.z += x3 * za3.z; a0.w += x3 * za3.w;
        a1.x += x3 * zb3.x; a1.y += x3 * zb3.y; a1.z += x3 * zb3.z; a1.w += x3 * zb3.w;
        den += x0 + x1 + x2 + x3;
    }
    for (; i < end; i++) {
        int s0 = __ldg(cs + i);
        float4 e0 = __ldg(ce + i);
        const float4* z0p = (const float4*)(zb + (size_t)s0 * D) + lane * 2;
        float4 za = __ldg(z0p), zc = __ldg(z0p + 1);
        float x0 = (hsel == 0) ? e0.x : (hsel == 1) ? e0.y : (hsel == 2) ? e0.z : e0.w;
        a0.x += x0 * za.x; a0.y += x0 * za.y; a0.z += x0 * za.z; a0.w += x0 * za.w;
        a1.x += x0 * zc.x; a1.y += x0 * zc.y; a1.z += x0 * zc.z; a1.w += x0 * zc.w;
        den += x0;
    }
    float inv = 1.f / (den + 1e-9f);
    float v[8] = {a0.x * inv, a0.y * inv, a0.z * inv, a0.w * inv,
                  a1.x * inv, a1.y * inv, a1.z * inv, a1.w * inv};
#pragma unroll
    for (int j = 0; j < 8; j++) v[j] = v[j] > 0.f ? v[j] : expm1f(v[j]);
    float* op = g_meta + (size_t)tglob * D + lane * 8;
    *(float4*)op = make_float4(v[0], v[1], v[2], v[3]);
    *((float4*)op + 1) = make_float4(v[4], v[5], v[6], v[7]);
}

// ----- semantic attention on mma.sync bf16 HMMA -----------------------------
__global__ __launch_bounds__(256) void k_sem_mma(
    const float* __restrict__ semb, const float* __restrict__ semq, int b)
{
    extern __shared__ char smem[];
    __nv_bfloat16* ftA = (__nv_bfloat16*)smem;
    __nv_bfloat16* wt  = (__nv_bfloat16*)(smem + SEMM_W_O);
    float*    bo_s = (float*)(smem + SEMM_BO_O);
    uint32_t* qh_s = (uint32_t*)(smem + SEMM_QH_O);
    float*  bucket = (float*)(smem + SEMM_BK_O);

    const int BR = 2 * T_TGT;
    int tid = threadIdx.x;
    int wid = tid >> 5, lane = tid & 31;
    int base = blockIdx.x * 64;

    if (tid < 64) ((float4*)bo_s)[tid] = __ldg((const float4*)(semb + b * D) + tid);
    else if (tid < 192) {
        int j = tid - 64;
        float q0 = __ldg(&semq[b * D + 2 * j]);
        float q1 = __ldg(&semq[b * D + 2 * j + 1]);
        qh_s[j] = pack_f16(q0, q1);
    }
    if (tid < 2) bucket[tid] = 0.f;

    {
        int r = tid >> 2, kq = tid & 3;
        const float* arow = g_meta + ((size_t)b * BR + base + r) * D;
#pragma unroll
        for (int i = 0; i < 8; i++) {
            int k = kq * 64 + i * 8;
            float4 v0 = __ldg((const float4*)(arow + k));
            float4 v1 = __ldg((const float4*)(arow + k) + 1);
            uint4 pk;
            pk.x = pack_bf16(v0.x, v0.y);
            pk.y = pack_bf16(v0.z, v0.w);
            pk.z = pack_bf16(v1.x, v1.y);
            pk.w = pack_bf16(v1.z, v1.w);
            *(uint4*)&ftA[r * SEMM_AS + k] = pk;
        }
    }

    int rw = wid >> 1, cw = wid & 1;
    float cacc[16][4];
#pragma unroll
    for (int ti = 0; ti < 16; ti++)
#pragma unroll
        for (int j = 0; j < 4; j++) cacc[ti][j] = 0.f;

    int a_tile = lane >> 3;
    int a_row = rw * 16 + (lane & 7) + (a_tile & 1) * 8;
    int a_koff = (a_tile >> 1) * 8;
    int b_g = lane >> 3;
    int b_nbase = cw * 128 + (b_g >> 1) * 8 + (lane & 7);
    int b_koff = (b_g & 1) * 8;

    for (int ch = 0; ch < 8; ch++) {
        __syncthreads();
        {   // coalesced copy of preconverted W^T bf16 chunk
            const uint4* wsrc =
                (const uint4*)&g_semWT[((size_t)b * 8 + ch) * 8192 + tid * 32];
            uint4* wdst = (uint4*)&wt[tid * SEMM_WS];
#pragma unroll
            for (int i = 0; i < 4; i++) wdst[i] = __ldg(wsrc + i);
        }
        __syncthreads();
#pragma unroll
        for (int ks = 0; ks < 2; ks++) {
            uint32_t a0, a1, a2, a3;
            ldsm_x4(a0, a1, a2, a3,
                    smem_u32(&ftA[a_row * SEMM_AS + ch * 32 + ks * 16 + a_koff]));
#pragma unroll
            for (int nt = 0; nt < 8; nt++) {
                uint32_t b0, b1, b2, b3;
                ldsm_x4(b0, b1, b2, b3,
                        smem_u32(&wt[(b_nbase + nt * 16) * SEMM_WS + ks * 16 + b_koff]));
                mma_bf16(cacc[nt * 2 + 0], a0, a1, a2, a3, b0, b1);
                mma_bf16(cacc[nt * 2 + 1], a0, a1, a2, a3, b2, b3);
            }
        }
    }

    int lr = lane >> 2, lc = lane & 3;
    float rs0 = 0.f, rs1 = 0.f;
#pragma unroll
    for (int ti = 0; ti < 16; ti++) {
        int col = cw * 128 + ti * 8 + lc * 2;
        uint32_t qh = qh_s[col >> 1];
        float b0v = bo_s[col], b1v = bo_s[col + 1];
        rs0 += tanh_dot2(cacc[ti][0] + b0v, cacc[ti][1] + b1v, qh);
        rs1 += tanh_dot2(cacc[ti][2] + b0v, cacc[ti][3] + b1v, qh);
    }
    rs0 += __shfl_down_sync(0xffffffffu, rs0, 2, 4);
    rs0 += __shfl_down_sync(0xffffffffu, rs0, 1, 4);
    rs1 += __shfl_down_sync(0xffffffffu, rs1, 2, 4);
    rs1 += __shfl_down_sync(0xffffffffu, rs1, 1, 4);
    if (lc == 0) {
        int r0 = base + rw * 16 + lr;
        int r1 = r0 + 8;
        atomicAdd(&bucket[r0 >= T_TGT ? 1 : 0], rs0);
        atomicAdd(&bucket[r1 >= T_TGT ? 1 : 0], rs1);
    }
    __syncthreads();
    if (tid < 2 && bucket[tid] != 0.f) atomicAdd(&g_wsum[b * 2 + tid], bucket[tid]);
}

// -------------- combine: beta-blend metas, @ fcout_W + bias -----------------
__global__ __launch_bounds__(256) void k_combine(
    const float* __restrict__ fW, const float* __restrict__ fb,
    float* __restrict__ outp, int b)
{
    __shared__ float ft[64][128];
    __shared__ float wt[64][64];

    int base = blockIdx.x * 128;
    int tid = threadIdx.x;
    int rg = tid & 31, cg = tid >> 5;

    float w0 = g_wsum[b * 2 + 0] * (1.f / T_TGT);
    float w1 = g_wsum[b * 2 + 1] * (1.f / T_TGT);
    float mx = fmaxf(w0, w1);
    float b0 = __expf(w0 - mx), b1 = __expf(w1 - mx);
    float sm = b0 + b1;
    b0 /= sm; b1 /= sm;

    const float* m0 = g_meta + ((size_t)(b * 2 + 0) * T_TGT) * D;
    const float* m1 = g_meta + ((size_t)(b * 2 + 1) * T_TGT) * D;
    const float* W = fW + (size_t)b * D * OUT_DIM;

    float acc[4][8];
#pragma unroll
    for (int a = 0; a < 4; a++)
#pragma unroll
        for (int j = 0; j < 8; j++) acc[a][j] = 0.f;

    for (int ch = 0; ch < 4; ch++) {
        __syncthreads();
        {
            int r = tid & 127, qb = tid >> 7;
            int row = base + r;
            bool val = row < T_TGT;
            const float4* p0 = (const float4*)(m0 + (size_t)row * D) + ch * 16;
            const float4* p1 = (const float4*)(m1 + (size_t)row * D) + ch * 16;
#pragma unroll
            for (int i = 0; i < 8; i++) {
                int q = qb + i * 2;
                float4 v0 = val ? __ldg(p0 + q) : make_float4(0.f, 0.f, 0.f, 0.f);
                float4 v1 = val ? __ldg(p1 + q) : make_float4(0.f, 0.f, 0.f, 0.f);
                ft[q * 4 + 0][r] = b0 * v0.x + b1 * v1.x;
                ft[q * 4 + 1][r] = b0 * v0.y + b1 * v1.y;
                ft[q * 4 + 2][r] = b0 * v0.z + b1 * v1.z;
                ft[q * 4 + 3][r] = b0 * v0.w + b1 * v1.w;
            }
        }
        {
            const float4* wp = (const float4*)(W + (size_t)ch * 64 * OUT_DIM);
            float4* wd = (float4*)&wt[0][0];
#pragma unroll
            for (int i = 0; i < 4; i++)
                wd[tid + i * 256] = __ldg(wp + tid + i * 256);
        }
        __syncthreads();
#pragma unroll 16
        for (int k = 0; k < 64; k++) {
            float4 fv = *(const float4*)&ft[k][rg * 4];
            float4 wv0 = *(const float4*)&wt[k][cg * 8];
            float4 wv1 = *(const float4*)&wt[k][cg * 8 + 4];
            float fr[4] = {fv.x, fv.y, fv.z, fv.w};
            float wc[8] = {wv0.x, wv0.y, wv0.z, wv0.w, wv1.x, wv1.y, wv1.z, wv1.w};
#pragma unroll
            for (int a = 0; a < 4; a++)
#pragma unroll
                for (int j = 0; j < 8; j++) acc[a][j] += fr[a] * wc[j];
        }
    }
    float bo[8];
#pragma unroll
    for (int j = 0; j < 8; j++) bo[j] = __ldg(&fb[b * OUT_DIM + cg * 8 + j]);
#pragma unroll
    for (int a = 0; a < 4; a++) {
        int row = base + rg * 4 + a;
        if (row < T_TGT) {
            float* op = outp + ((size_t)b * T_TGT + row) * OUT_DIM + cg * 8;
            *(float4*)op = make_float4(acc[a][0] + bo[0], acc[a][1] + bo[1],
                                       acc[a][2] + bo[2], acc[a][3] + bo[3]);
            *((float4*)op + 1) = make_float4(acc[a][4] + bo[4], acc[a][5] + bo[5],
                                             acc[a][6] + bo[6], acc[a][7] + bo[7]);
        }
    }
}

// ------------------------------- launch -------------------------------------
extern "C" void kernel_launch(void* const* d_in, const int* in_sizes, int n_in,
                              void* d_out, int out_size)
{
    const float* features0 = (const float*)d_in[0];
    const float* features1 = (const float*)d_in[1];
    const float* fc_W      = (const float*)d_in[2];
    const float* fc_b      = (const float*)d_in[3];
    const float* gat_W     = (const float*)d_in[4];
    const float* attn_l    = (const float*)d_in[5];
    const float* attn_r    = (const float*)d_in[6];
    const float* sem_W     = (const float*)d_in[7];
    const float* sem_b     = (const float*)d_in[8];
    const float* sem_q     = (const float*)d_in[9];
    const float* fcout_W   = (const float*)d_in[10];
    const float* fcout_b   = (const float*)d_in[11];
    const int*   type_idx  = (const int*)d_in[12];
    const int*   node_idx  = (const int*)d_in[13];
    const int*   edge_src  = (const int*)d_in[14];
    const int*   edge_dst  = (const int*)d_in[15];
    const int*   tgt_idx   = (const int*)d_in[16];
    float* out = (float*)d_out;

    static cudaStream_t s_side = nullptr;
    static cudaEvent_t ev_fork = nullptr, ev_scan = nullptr, ev_gatz = nullptr,
                       ev_done = nullptr;
    static bool attr_done = false;
    if (!s_side) {
        cudaStreamCreateWithFlags(&s_side, cudaStreamNonBlocking);
        cudaEventCreateWithFlags(&ev_fork, cudaEventDisableTiming);
        cudaEventCreateWithFlags(&ev_scan, cudaEventDisableTiming);
        cudaEventCreateWithFlags(&ev_gatz, cudaEventDisableTiming);
        cudaEventCreateWithFlags(&ev_done, cudaEventDisableTiming);
    }
    if (!attr_done) {
        cudaFuncSetAttribute(k_sem_mma, cudaFuncAttributeMaxDynamicSharedMemorySize,
                             SEMM_SZ);
        cudaFuncSetAttribute(k_gatz_mma, cudaFuncAttributeMaxDynamicSharedMemorySize,
                             GZ_SZ);
        cudaFuncSetAttribute(k_fc_mma, cudaFuncAttributeMaxDynamicSharedMemorySize,
                             FC_SZ);
        attr_done = true;
    }

    // main: init; fork side for mark/count/scan
    k_init<<<(G4 * NP_G + 255) / 256, 256>>>();
    cudaEventRecord(ev_fork, 0);
    cudaStreamWaitEvent(s_side, ev_fork, 0);
    k_mark<<<(G4 * T_TGT + 255) / 256, 256, 0, s_side>>>(tgt_idx);
    k_count<<<(G4 * E_G + 255) / 256, 256, 0, s_side>>>(edge_dst);
    k_scan<<<G4, 1024, 0, s_side>>>();
    cudaEventRecord(ev_scan, s_side);

    // main: weight prep + GEMMs
    k_wal<<<G4, 512>>>(gat_W, attn_l, attn_r);
    k_wprep<<<896, 256>>>(fc_W, gat_W, sem_W);
    k_fc_mma<<<dim3((NP_TYPE + 127) / 128, 2), 256, FC_SZ>>>(
        features0, features1, fc_b, type_idx);
    k_gatz_mma<<<dim3((NP_G + 63) / 64, G4), 256, GZ_SZ>>>(node_idx);
    cudaEventRecord(ev_gatz, 0);

    // main chain: branch 0 (graphs 0,1)
    cudaStreamWaitEvent(0, ev_scan, 0);
    k_fill<<<(2 * E_G + 255) / 256, 256>>>(edge_src, edge_dst, 0);
    k_aggregate<<<(2 * T_TGT) / 8, 256>>>(tgt_idx, 0);
    k_sem_mma<<<(2 * T_TGT) / 64, 256, SEMM_SZ>>>(sem_b, sem_q, 0);
    k_combine<<<(T_TGT + 127) / 128, 256>>>(fcout_W, fcout_b, out, 0);

    // side chain: branch 1 (graphs 2,3)
    cudaStreamWaitEvent(s_side, ev_gatz, 0);
    k_fill<<<(2 * E_G + 255) / 256, 256, 0, s_side>>>(edge_src, edge_dst, 2);
    k_aggregate<<<(2 * T_TGT) / 8, 256, 0, s_side>>>(tgt_idx, 2);
    k_sem_mma<<<(2 * T_TGT) / 64, 256, SEMM_SZ, s_side>>>(sem_b, sem_q, 1);
    k_combine<<<(T_TGT + 127) / 128, 256, 0, s_side>>>(fcout_W, fcout_b, out, 1);
    cudaEventRecord(ev_done, s_side);

    cudaStreamWaitEvent(0, ev_done, 0);
}

// round 14
// speedup vs baseline: 2.5000x; 1.0278x over previous
#include <cuda_runtime.h>
#include <cuda_bf16.h>
#include <cuda_fp16.h>
#include <math.h>
#include <stdint.h>

#define N_TOTAL 100000
#define NP_TYPE 50000
#define NP_G    50000
#define E_G     500000
#define NH      4
#define HD      64
#define HID     64
#define D       256
#define OUT_DIM 64
#define T_TGT   20000
#define G4      4
#define OFFS_S  50016   // padded offs stride (16B-aligned per graph)

// ------------------------- scratch (static device globals) -------------------
__device__ float  g_transformed[N_TOTAL * HID];          // 25.6 MB
__device__ __half g_zh[(size_t)G4 * NP_G * D];           // 102.4 MB (fp16 z)
__device__ float  g_el[G4 * NP_G * NH];
__device__ float  g_er[G4 * NP_G * NH];
__device__ float  g_wal[G4 * 64 * 8];                    // W@attn per graph
__device__ int    g_istgt[G4 * NP_G];
__device__ int    g_deg[G4 * NP_G];
__device__ int    g_offs[G4 * OFFS_S];
__device__ int    g_cur[G4 * NP_G];
__device__ int    g_csr_src[G4 * E_G];
__device__ float4 g_csr_ex[G4 * E_G];
__device__ float  g_meta[(size_t)G4 * T_TGT * D];        // 81.9 MB
__device__ float  g_wsum[4];
// preconverted weights
__device__ __half         g_fcWh[2 * 64 * 256];          // [t][o][k]
__device__ __half         g_gatWT[G4 * 256 * 64];        // [g][o][k]
__device__ __nv_bfloat16  g_semWT[2 * 8 * 256 * 32];     // [b][ch][o][kk]

// ------------------------------ small helpers --------------------------------
__device__ __forceinline__ uint32_t smem_u32(const void* p) {
    uint32_t a;
    asm("{ .reg .u64 t; cvta.to.shared.u64 t, %1; cvt.u32.u64 %0, t; }" : "=r"(a) : "l"(p));
    return a;
}
__device__ __forceinline__ uint32_t pack_bf16(float lo, float hi) {
    uint32_t r;
    asm("cvt.rn.bf16x2.f32 %0, %1, %2;" : "=r"(r) : "f"(hi), "f"(lo));
    return r;
}
__device__ __forceinline__ uint32_t pack_f16(float lo, float hi) {
    uint32_t r;
    asm("cvt.rn.f16x2.f32 %0, %1, %2;" : "=r"(r) : "f"(hi), "f"(lo));
    return r;
}
__device__ __forceinline__ float tanh_dot2(float x0, float x1, uint32_t qh) {
    uint32_t xp = pack_f16(x0, x1), tp, pp;
    asm("tanh.approx.f16x2 %0, %1;" : "=r"(tp) : "r"(xp));
    asm("mul.f16x2 %0, %1, %2;" : "=r"(pp) : "r"(tp), "r"(qh));
    __half2 h = *reinterpret_cast<__half2*>(&pp);
    return __low2float(h) + __high2float(h);
}
// accumulate 8 fp16 z-values (packed in uint4) scaled by w into a0/a1
__device__ __forceinline__ void acc_z(float4& a0, float4& a1, uint4 zv, float w) {
    float2 f0 = __half22float2(*reinterpret_cast<__half2*>(&zv.x));
    float2 f1 = __half22float2(*reinterpret_cast<__half2*>(&zv.y));
    float2 f2 = __half22float2(*reinterpret_cast<__half2*>(&zv.z));
    float2 f3 = __half22float2(*reinterpret_cast<__half2*>(&zv.w));
    a0.x += w * f0.x; a0.y += w * f0.y;
    a0.z += w * f1.x; a0.w += w * f1.y;
    a1.x += w * f2.x; a1.y += w * f2.y;
    a1.z += w * f3.x; a1.w += w * f3.y;
}
__device__ __forceinline__ void ldsm_x4(uint32_t& r0, uint32_t& r1, uint32_t& r2,
                                        uint32_t& r3, uint32_t addr) {
    asm volatile("ldmatrix.sync.aligned.m8n8.x4.shared.b16 {%0,%1,%2,%3}, [%4];"
                 : "=r"(r0), "=r"(r1), "=r"(r2), "=r"(r3) : "r"(addr));
}
__device__ __forceinline__ void mma_bf16(float* c, uint32_t a0, uint32_t a1,
                                         uint32_t a2, uint32_t a3,
                                         uint32_t b0, uint32_t b1) {
    asm volatile(
        "mma.sync.aligned.m16n8k16.row.col.f32.bf16.bf16.f32 "
        "{%0,%1,%2,%3}, {%4,%5,%6,%7}, {%8,%9}, {%0,%1,%2,%3};"
        : "+f"(c[0]), "+f"(c[1]), "+f"(c[2]), "+f"(c[3])
        : "r"(a0), "r"(a1), "r"(a2), "r"(a3), "r"(b0), "r"(b1));
}
__device__ __forceinline__ void mma_f16(float* c, uint32_t a0, uint32_t a1,
                                        uint32_t a2, uint32_t a3,
                                        uint32_t b0, uint32_t b1) {
    asm volatile(
        "mma.sync.aligned.m16n8k16.row.col.f32.f16.f16.f32 "
        "{%0,%1,%2,%3}, {%4,%5,%6,%7}, {%8,%9}, {%0,%1,%2,%3};"
        : "+f"(c[0]), "+f"(c[1]), "+f"(c[2]), "+f"(c[3])
        : "r"(a0), "r"(a1), "r"(a2), "r"(a3), "r"(b0), "r"(b1));
}

// k_sem_mma dynamic smem layout
#define SEMM_AS   264
#define SEMM_WS   40
#define SEMM_A_B  (64 * SEMM_AS * 2)
#define SEMM_W_O  SEMM_A_B
#define SEMM_W_B  (256 * SEMM_WS * 2)
#define SEMM_BO_O (SEMM_W_O + SEMM_W_B)
#define SEMM_QH_O (SEMM_BO_O + 1024)
#define SEMM_BK_O (SEMM_QH_O + 512)
#define SEMM_SZ   (SEMM_BK_O + 128)

// k_gatz_mma fp16 layout
#define GZ_S      72
#define GZ_AH_O   0
#define GZ_BH_O   9216
#define GZ_WAL_O  46080
#define GZ_SZ     (GZ_WAL_O + 2048)

// k_fc_mma fp16 layout
#define FC_AS     264
#define FC_A_O    0
#define FC_A_B    (128 * FC_AS * 2)
#define FC_B_O    FC_A_B
#define FC_B_B    (64 * FC_AS * 2)
#define FC_BO_O   (FC_B_O + FC_B_B)
#define FC_SZ     (FC_BO_O + 256)

// ------------------------------- init ---------------------------------------
__global__ void k_init() {
    int i = blockIdx.x * blockDim.x + threadIdx.x;
    if (i < G4 * NP_G) { g_deg[i] = 0; g_istgt[i] = 0; }
    if (i < 4) g_wsum[i] = 0.f;
}

__global__ void k_mark(const int* __restrict__ tgt) {
    int t = blockIdx.x * blockDim.x + threadIdx.x;
    if (t < G4 * T_TGT) {
        int g = t / T_TGT;
        g_istgt[g * NP_G + __ldg(&tgt[t])] = 1;
    }
}

// one-time weight preconversion into MMA-friendly layouts
__global__ void k_wprep(const float* __restrict__ fcW,
                        const float* __restrict__ gatW,
                        const float* __restrict__ semW) {
    int i = blockIdx.x * blockDim.x + threadIdx.x;
    if (i < 2 * 64 * 256) {
        g_fcWh[i] = __float2half(__ldg(&fcW[i]));
        return;
    }
    int j = i - 2 * 64 * 256;
    if (j < G4 * 256 * 64) {
        int g = j >> 14, r = j & 16383;
        int o = r >> 6, k = r & 63;
        g_gatWT[j] = __float2half(__ldg(&gatW[g * 16384 + k * 256 + o]));
        return;
    }
    int m = j - G4 * 256 * 64;
    if (m < 2 * 8 * 256 * 32) {
        int b = m >> 16, r2 = m & 65535;
        int ch = r2 >> 13, r3 = r2 & 8191;
        int o = r3 >> 5, kk = r3 & 31;
        g_semWT[m] = __float2bfloat16(__ldg(&semW[b * 65536 + (ch * 32 + kk) * 256 + o]));
    }
}

// ---- wal/war: per-graph W @ attn --------------------------------------------
__global__ void k_wal(const float* __restrict__ gatW,
                      const float* __restrict__ attn_l,
                      const float* __restrict__ attn_r)
{
    int g = blockIdx.x;
    int idx = threadIdx.x;
    int k = idx >> 3, o = idx & 7;
    int side = o >> 2, h = o & 3;
    const float* att = (side ? attn_r : attn_l) + (size_t)g * D + h * 64;
    const float* wr = gatW + (size_t)g * HID * D + (size_t)k * D + h * 64;
    float s = 0.f;
#pragma unroll 16
    for (int d = 0; d < 64; d++) s += __ldg(&wr[d]) * __ldg(&att[d]);
    g_wal[g * 512 + k * 8 + o] = s;
}

// ---------- fc on mma.sync fp16 ----------------------------------------------
__global__ __launch_bounds__(256) void k_fc_mma(
    const float* __restrict__ f0, const float* __restrict__ f1,
    const float* __restrict__ fcb, const int* __restrict__ type_idx)
{
    extern __shared__ char smem[];
    __half* fA = (__half*)(smem + FC_A_O);
    __half* fB = (__half*)(smem + FC_B_O);
    float* bo_s = (float*)(smem + FC_BO_O);

    int t = blockIdx.y;
    int base = blockIdx.x * 128;
    const float* feat = t ? f1 : f0;
    int tid = threadIdx.x;
    int wid = tid >> 5, lane = tid & 31;

    if (tid < 64) bo_s[tid] = __ldg(&fcb[t * HID + tid]);

    {   // A: 128 rows x 256 k fp32 -> fp16
        int r = tid >> 2, kq = tid & 3;
#pragma unroll
        for (int rr = 0; rr < 2; rr++) {
            int row = base + rr * 64 + r;
            bool val = row < NP_TYPE;
            const float4* fp = (const float4*)(feat + (size_t)row * D) + kq * 16;
            __half* dst = &fA[(rr * 64 + r) * FC_AS + kq * 64];
#pragma unroll 4
            for (int i = 0; i < 16; i++) {
                float4 v = val ? __ldg(fp + i) : make_float4(0.f, 0.f, 0.f, 0.f);
                *(uint2*)(dst + i * 4) =
                    make_uint2(pack_f16(v.x, v.y), pack_f16(v.z, v.w));
            }
        }
    }
    {   // B: coalesced copy of preconverted fp16 weights
        int o = tid & 63, sq = tid >> 6;
        const uint4* wsrc = (const uint4*)&g_fcWh[(size_t)t * 16384 + o * 256 + sq * 64];
        uint4* wdst = (uint4*)&fB[o * FC_AS + sq * 64];
#pragma unroll
        for (int i = 0; i < 8; i++) wdst[i] = __ldg(wsrc + i);
    }
    __syncthreads();

    float cacc[8][4];
#pragma unroll
    for (int ti = 0; ti < 8; ti++)
#pragma unroll
        for (int j = 0; j < 4; j++) cacc[ti][j] = 0.f;

    int a_tile = lane >> 3;
    int a_row = wid * 16 + (lane & 7) + (a_tile & 1) * 8;
    int a_koff = (a_tile >> 1) * 8;
    int b_g = lane >> 3;
    int b_nbase = (b_g >> 1) * 8 + (lane & 7);
    int b_koff = (b_g & 1) * 8;

#pragma unroll
    for (int ks = 0; ks < 16; ks++) {
        uint32_t a0, a1, a2, a3;
        ldsm_x4(a0, a1, a2, a3, smem_u32(&fA[a_row * FC_AS + ks * 16 + a_koff]));
#pragma unroll
        for (int nt = 0; nt < 4; nt++) {
            uint32_t b0, b1, b2, b3;
            ldsm_x4(b0, b1, b2, b3,
                    smem_u32(&fB[(b_nbase + nt * 16) * FC_AS + ks * 16 + b_koff]));
            mma_f16(cacc[nt * 2 + 0], a0, a1, a2, a3, b0, b1);
            mma_f16(cacc[nt * 2 + 1], a0, a1, a2, a3, b2, b3);
        }
    }

    int lr = lane >> 2, lc = lane & 3;
    int r0 = base + wid * 16 + lr, r1 = r0 + 8;
    const int* ti_p = type_idx + t * NP_TYPE;
    int d0 = (r0 < NP_TYPE) ? __ldg(&ti_p[r0]) : -1;
    int d1 = (r1 < NP_TYPE) ? __ldg(&ti_p[r1]) : -1;
#pragma unroll
    for (int ti = 0; ti < 8; ti++) {
        int col = ti * 8 + lc * 2;
        float b0v = bo_s[col], b1v = bo_s[col + 1];
        if (d0 >= 0)
            *(float2*)&g_transformed[(size_t)d0 * HID + col] =
                make_float2(cacc[ti][0] + b0v, cacc[ti][1] + b1v);
        if (d1 >= 0)
            *(float2*)&g_transformed[(size_t)d1 * HID + col] =
                make_float2(cacc[ti][2] + b0v, cacc[ti][3] + b1v);
    }
}

// -------- gatz on mma.sync fp16 (per-branch: 2 graphs via gbase) -------------
__global__ __launch_bounds__(256) void k_gatz_mma(const int* __restrict__ node_idx,
                                                  int gbase)
{
    extern __shared__ char smem[];
    __half* ah = (__half*)(smem + GZ_AH_O);
    __half* bh = (__half*)(smem + GZ_BH_O);
    float* wal_s = (float*)(smem + GZ_WAL_O);

    int g = gbase + blockIdx.y;
    int base = blockIdx.x * 64;
    int tid = threadIdx.x;
    int wid = tid >> 5, lane = tid & 31;

    {   // A: gather 64 rows x 64 cols fp32 -> fp16
        int r = tid >> 2, kq = tid & 3;
        int row = base + r;
        int node = (row < NP_G) ? __ldg(&node_idx[(size_t)g * NP_G + row]) : -1;
        const float4* hp = (const float4*)(g_transformed + (size_t)node * HID) + kq * 4;
#pragma unroll
        for (int i = 0; i < 4; i++) {
            float4 v = (node >= 0) ? __ldg(hp + i) : make_float4(0.f, 0.f, 0.f, 0.f);
            *(uint2*)&ah[r * GZ_S + kq * 16 + i * 4] =
                make_uint2(pack_f16(v.x, v.y), pack_f16(v.z, v.w));
        }
    }
    {   // B: coalesced copy of preconverted W^T fp16
        const uint4* wsrc = (const uint4*)&g_gatWT[(size_t)g * 16384 + tid * 64];
        uint4* wdst = (uint4*)&bh[tid * GZ_S];
#pragma unroll
        for (int i = 0; i < 8; i++) wdst[i] = __ldg(wsrc + i);
    }
    wal_s[tid] = g_wal[g * 512 + tid];
    wal_s[tid + 256] = g_wal[g * 512 + tid + 256];
    __syncthreads();

    int rw = wid >> 1, cw = wid & 1;
    float cacc[16][4];
#pragma unroll
    for (int ti = 0; ti < 16; ti++)
#pragma unroll
        for (int j = 0; j < 4; j++) cacc[ti][j] = 0.f;

    int a_tile = lane >> 3;
    int a_row = rw * 16 + (lane & 7) + (a_tile & 1) * 8;
    int a_koff = (a_tile >> 1) * 8;
    int b_g = lane >> 3;
    int b_nbase = cw * 128 + (b_g >> 1) * 8 + (lane & 7);
    int b_koff = (b_g & 1) * 8;

#pragma unroll
    for (int ks = 0; ks < 4; ks++) {
        uint32_t a0, a1, a2, a3;
        ldsm_x4(a0, a1, a2, a3, smem_u32(&ah[a_row * GZ_S + ks * 16 + a_koff]));
#pragma unroll
        for (int nt = 0; nt < 8; nt++) {
            uint32_t b0, b1, b2, b3;
            ldsm_x4(b0, b1, b2, b3,
                    smem_u32(&bh[(b_nbase + nt * 16) * GZ_S + ks * 16 + b_koff]));
            mma_f16(cacc[nt * 2 + 0], a0, a1, a2, a3, b0, b1);
            mma_f16(cacc[nt * 2 + 1], a0, a1, a2, a3, b2, b3);
        }
    }

    {   // z stores (fp16 pairs)
        int lr = lane >> 2, lc = lane & 3;
        int r0 = base + rw * 16 + lr, r1 = r0 + 8;
        bool v0 = r0 < NP_G, v1 = r1 < NP_G;
        __half* z0 = g_zh + ((size_t)g * NP_G + r0) * D + cw * 128 + lc * 2;
        __half* z1 = g_zh + ((size_t)g * NP_G + r1) * D + cw * 128 + lc * 2;
#pragma unroll
        for (int ti = 0; ti < 16; ti++) {
            if (v0) *(uint32_t*)(z0 + ti * 8) = pack_f16(cacc[ti][0], cacc[ti][1]);
            if (v1) *(uint32_t*)(z1 + ti * 8) = pack_f16(cacc[ti][2], cacc[ti][3]);
        }
    }

    {   // el/er: h . wal (fp16 h)
        int r = tid & 63;
        int ob = (tid >> 6) * 2;
        int row = base + r;
        if (row < NP_G) {
            float e0 = 0.f, e1 = 0.f;
#pragma unroll 8
            for (int k = 0; k < 64; k += 2) {
                __half2 hb = *(__half2*)&ah[r * GZ_S + k];
                float h0 = __low2float(hb), h1 = __high2float(hb);
                e0 += h0 * wal_s[k * 8 + ob]     + h1 * wal_s[(k + 1) * 8 + ob];
                e1 += h0 * wal_s[k * 8 + ob + 1] + h1 * wal_s[(k + 1) * 8 + ob + 1];
            }
            size_t nbase = ((size_t)g * NP_G + row) * NH;
            if (ob < 4) {
                g_el[nbase + ob] = e0;
                g_el[nbase + ob + 1] = e1;
            } else {
                g_er[nbase + ob - 4] = e0;
                g_er[nbase + ob - 3] = e1;
            }
        }
    }
}

// ------------------------------- CSR build (target-filtered) -----------------
__global__ void k_count(const int* __restrict__ dst) {
    int e = blockIdx.x * blockDim.x + threadIdx.x;
    if (e < G4 * E_G) {
        int g = e / E_G;
        int gn = g * NP_G + __ldg(&dst[e]);
        if (g_istgt[gn]) atomicAdd(&g_deg[gn], 1);
    }
}

// vectorized single-block-per-graph scan
__global__ __launch_bounds__(1024) void k_scan() {
    __shared__ int ws[32];
    int g = blockIdx.x;
    int tid = threadIdx.x;
    int lane = tid & 31, wid = tid >> 5;
    const int CH = 52;
    int lo = tid * CH;
    const int* deg = g_deg + g * NP_G;
    bool fast = (lo + CH) <= NP_G;
    int s = 0;
    if (fast) {
        const int4* p = (const int4*)(deg + lo);
#pragma unroll
        for (int c = 0; c < 13; c++) {
            int4 v = p[c];
            s += v.x + v.y + v.z + v.w;
        }
    } else {
        for (int i = lo; i < NP_G; i++) s += deg[i];
    }
    int v = s;
#pragma unroll
    for (int off = 1; off < 32; off <<= 1) {
        int n = __shfl_up_sync(0xffffffffu, v, off);
        if (lane >= off) v += n;
    }
    if (lane == 31) ws[wid] = v;
    __syncthreads();
    if (wid == 0) {
        int w = ws[lane];
#pragma unroll
        for (int off = 1; off < 32; off <<= 1) {
            int n = __shfl_up_sync(0xffffffffu, w, off);
            if (lane >= off) w += n;
        }
        ws[lane] = w;
    }
    __syncthreads();
    int run = v - s + (wid ? ws[wid - 1] : 0);
    int* offs = g_offs + g * OFFS_S;
    int* cur = g_cur + g * NP_G;
    if (fast) {
        const int4* p = (const int4*)(deg + lo);
        int4* po = (int4*)(offs + lo);
        int4* pc = (int4*)(cur + lo);
#pragma unroll
        for (int c = 0; c < 13; c++) {
            int4 d4 = p[c];
            int4 o4;
            o4.x = run;
            o4.y = run + d4.x;
            o4.z = o4.y + d4.y;
            o4.w = o4.z + d4.z;
            run = o4.w + d4.w;
            po[c] = o4;
            pc[c] = o4;
        }
    } else {
        for (int i = lo; i < NP_G; i++) {
            offs[i] = run;
            cur[i] = run;
            run += deg[i];
        }
    }
    if (tid == 0) offs[NP_G] = ws[31];
}

__global__ void k_fill(const int* __restrict__ src, const int* __restrict__ dst,
                       int gbase) {
    int e = blockIdx.x * blockDim.x + threadIdx.x;
    if (e >= 2 * E_G) return;
    int gl = e / E_G;
    int g = gbase + gl;
    size_t eidx = (size_t)g * E_G + (e - gl * E_G);
    int d = __ldg(&dst[eidx]);
    int gn = g * NP_G;
    if (!g_istgt[gn + d]) return;
    int s = __ldg(&src[eidx]);
    float4 elv = __ldg((const float4*)g_el + gn + s);
    float4 erv = __ldg((const float4*)g_er + gn + d);
    float e0 = elv.x + erv.x, e1 = elv.y + erv.y;
    float e2 = elv.z + erv.z, e3 = elv.w + erv.w;
    e0 = e0 > 0.f ? e0 : 0.2f * e0;
    e1 = e1 > 0.f ? e1 : 0.2f * e1;
    e2 = e2 > 0.f ? e2 : 0.2f * e2;
    e3 = e3 > 0.f ? e3 : 0.2f * e3;
    float4 ex = make_float4(__expf(e0), __expf(e1), __expf(e2), __expf(e3));
    int pos = atomicAdd(&g_cur[gn + d], 1);
    g_csr_src[(size_t)g * E_G + pos] = s;
    g_csr_ex[(size_t)g * E_G + pos] = ex;
}

// ------ aggregate: warp per TARGET, fused softmax, fp16 z gathers -----------
__global__ __launch_bounds__(256) void k_aggregate(const int* __restrict__ tgt,
                                                   int gbase) {
    int t = (blockIdx.x * blockDim.x + threadIdx.x) >> 5;
    if (t >= 2 * T_TGT) return;
    int g = gbase + t / T_TGT;
    int tglob = gbase * T_TGT + t;
    int lane = threadIdx.x & 31;
    int hsel = lane >> 3;
    int nl = __ldg(&tgt[tglob]);
    int beg = g_offs[g * OFFS_S + nl];
    int end = g_offs[g * OFFS_S + nl + 1];
    const int* cs = g_csr_src + (size_t)g * E_G;
    const float4* ce = g_csr_ex + (size_t)g * E_G;
    const __half* zb = g_zh + (size_t)g * NP_G * D;

    float4 a0 = {0.f, 0.f, 0.f, 0.f}, a1 = {0.f, 0.f, 0.f, 0.f};
    float den = 0.f;

    int i = beg;
    for (; i + 4 <= end; i += 4) {
        int s0 = __ldg(cs + i), s1 = __ldg(cs + i + 1);
        int s2 = __ldg(cs + i + 2), s3 = __ldg(cs + i + 3);
        float4 e0 = __ldg(ce + i), e1 = __ldg(ce + i + 1);
        float4 e2 = __ldg(ce + i + 2), e3 = __ldg(ce + i + 3);
        uint4 zv0 = __ldg((const uint4*)(zb + (size_t)s0 * D + lane * 8));
        uint4 zv1 = __ldg((const uint4*)(zb + (size_t)s1 * D + lane * 8));
        uint4 zv2 = __ldg((const uint4*)(zb + (size_t)s2 * D + lane * 8));
        uint4 zv3 = __ldg((const uint4*)(zb + (size_t)s3 * D + lane * 8));
        float x0 = (hsel == 0) ? e0.x : (hsel == 1) ? e0.y : (hsel == 2) ? e0.z : e0.w;
        float x1 = (hsel == 0) ? e1.x : (hsel == 1) ? e1.y : (hsel == 2) ? e1.z : e1.w;
        float x2 = (hsel == 0) ? e2.x : (hsel == 1) ? e2.y : (hsel == 2) ? e2.z : e2.w;
        float x3 = (hsel == 0) ? e3.x : (hsel == 1) ? e3.y : (hsel == 2) ? e3.z : e3.w;
        acc_z(a0, a1, zv0, x0);
        acc_z(a0, a1, zv1, x1);
        acc_z(a0, a1, zv2, x2);
        acc_z(a0, a1, zv3, x3);
        den += x0 + x1 + x2 + x3;
    }
    for (; i < end; i++) {
        int s0 = __ldg(cs + i);
        float4 e0 = __ldg(ce + i);
        uint4 zv0 = __ldg((const uint4*)(zb + (size_t)s0 * D + lane * 8));
        float x0 = (hsel == 0) ? e0.x : (hsel == 1) ? e0.y : (hsel == 2) ? e0.z : e0.w;
        acc_z(a0, a1, zv0, x0);
        den += x0;
    }
    float inv = 1.f / (den + 1e-9f);
    float v[8] = {a0.x * inv, a0.y * inv, a0.z * inv, a0.w * inv,
                  a1.x * inv, a1.y * inv, a1.z * inv, a1.w * inv};
#pragma unroll
    for (int j = 0; j < 8; j++) v[j] = v[j] > 0.f ? v[j] : expm1f(v[j]);
    float* op = g_meta + (size_t)tglob * D + lane * 8;
    *(float4*)op = make_float4(v[0], v[1], v[2], v[3]);
    *((float4*)op + 1) = make_float4(v[4], v[5], v[6], v[7]);
}

// ----- semantic attention on mma.sync bf16 HMMA -----------------------------
__global__ __launch_bounds__(256) void k_sem_mma(
    const float* __restrict__ semb, const float* __restrict__ semq, int b)
{
    extern __shared__ char smem[];
    __nv_bfloat16* ftA = (__nv_bfloat16*)smem;
    __nv_bfloat16* wt  = (__nv_bfloat16*)(smem + SEMM_W_O);
    float*    bo_s = (float*)(smem + SEMM_BO_O);
    uint32_t* qh_s = (uint32_t*)(smem + SEMM_QH_O);
    float*  bucket = (float*)(smem + SEMM_BK_O);

    const int BR = 2 * T_TGT;
    int tid = threadIdx.x;
    int wid = tid >> 5, lane = tid & 31;
    int base = blockIdx.x * 64;

    if (tid < 64) ((float4*)bo_s)[tid] = __ldg((const float4*)(semb + b * D) + tid);
    else if (tid < 192) {
        int j = tid - 64;
        float q0 = __ldg(&semq[b * D + 2 * j]);
        float q1 = __ldg(&semq[b * D + 2 * j + 1]);
        qh_s[j] = pack_f16(q0, q1);
    }
    if (tid < 2) bucket[tid] = 0.f;

    {
        int r = tid >> 2, kq = tid & 3;
        const float* arow = g_meta + ((size_t)b * BR + base + r) * D;
#pragma unroll
        for (int i = 0; i < 8; i++) {
            int k = kq * 64 + i * 8;
            float4 v0 = __ldg((const float4*)(arow + k));
            float4 v1 = __ldg((const float4*)(arow + k) + 1);
            uint4 pk;
            pk.x = pack_bf16(v0.x, v0.y);
            pk.y = pack_bf16(v0.z, v0.w);
            pk.z = pack_bf16(v1.x, v1.y);
            pk.w = pack_bf16(v1.z, v1.w);
            *(uint4*)&ftA[r * SEMM_AS + k] = pk;
        }
    }

    int rw = wid >> 1, cw = wid & 1;
    float cacc[16][4];
#pragma unroll
    for (int ti = 0; ti < 16; ti++)
#pragma unroll
        for (int j = 0; j < 4; j++) cacc[ti][j] = 0.f;

    int a_tile = lane >> 3;
    int a_row = rw * 16 + (lane & 7) + (a_tile & 1) * 8;
    int a_koff = (a_tile >> 1) * 8;
    int b_g = lane >> 3;
    int b_nbase = cw * 128 + (b_g >> 1) * 8 + (lane & 7);
    int b_koff = (b_g & 1) * 8;

    for (int ch = 0; ch < 8; ch++) {
        __syncthreads();
        {
            const uint4* wsrc =
                (const uint4*)&g_semWT[((size_t)b * 8 + ch) * 8192 + tid * 32];
            uint4* wdst = (uint4*)&wt[tid * SEMM_WS];
#pragma unroll
            for (int i = 0; i < 4; i++) wdst[i] = __ldg(wsrc + i);
        }
        __syncthreads();
#pragma unroll
        for (int ks = 0; ks < 2; ks++) {
            uint32_t a0, a1, a2, a3;
            ldsm_x4(a0, a1, a2, a3,
                    smem_u32(&ftA[a_row * SEMM_AS + ch * 32 + ks * 16 + a_koff]));
#pragma unroll
            for (int nt = 0; nt < 8; nt++) {
                uint32_t b0, b1, b2, b3;
                ldsm_x4(b0, b1, b2, b3,
                        smem_u32(&wt[(b_nbase + nt * 16) * SEMM_WS + ks * 16 + b_koff]));
                mma_bf16(cacc[nt * 2 + 0], a0, a1, a2, a3, b0, b1);
                mma_bf16(cacc[nt * 2 + 1], a0, a1, a2, a3, b2, b3);
            }
        }
    }

    int lr = lane >> 2, lc = lane & 3;
    float rs0 = 0.f, rs1 = 0.f;
#pragma unroll
    for (int ti = 0; ti < 16; ti++) {
        int col = cw * 128 + ti * 8 + lc * 2;
        uint32_t qh = qh_s[col >> 1];
        float b0v = bo_s[col], b1v = bo_s[col + 1];
        rs0 += tanh_dot2(cacc[ti][0] + b0v, cacc[ti][1] + b1v, qh);
        rs1 += tanh_dot2(cacc[ti][2] + b0v, cacc[ti][3] + b1v, qh);
    }
    rs0 += __shfl_down_sync(0xffffffffu, rs0, 2, 4);
    rs0 += __shfl_down_sync(0xffffffffu, rs0, 1, 4);
    rs1 += __shfl_down_sync(0xffffffffu, rs1, 2, 4);
    rs1 += __shfl_down_sync(0xffffffffu, rs1, 1, 4);
    if (lc == 0) {
        int r0 = base + rw * 16 + lr;
        int r1 = r0 + 8;
        atomicAdd(&bucket[r0 >= T_TGT ? 1 : 0], rs0);
        atomicAdd(&bucket[r1 >= T_TGT ? 1 : 0], rs1);
    }
    __syncthreads();
    if (tid < 2 && bucket[tid] != 0.f) atomicAdd(&g_wsum[b * 2 + tid], bucket[tid]);
}

// -------------- combine: beta-blend metas, @ fcout_W + bias -----------------
__global__ __launch_bounds__(256) void k_combine(
    const float* __restrict__ fW, const float* __restrict__ fb,
    float* __restrict__ outp, int b)
{
    __shared__ float ft[64][128];
    __shared__ float wt[64][64];

    int base = blockIdx.x * 128;
    int tid = threadIdx.x;
    int rg = tid & 31, cg = tid >> 5;

    float w0 = g_wsum[b * 2 + 0] * (1.f / T_TGT);
    float w1 = g_wsum[b * 2 + 1] * (1.f / T_TGT);
    float mx = fmaxf(w0, w1);
    float b0 = __expf(w0 - mx), b1 = __expf(w1 - mx);
    float sm = b0 + b1;
    b0 /= sm; b1 /= sm;

    const float* m0 = g_meta + ((size_t)(b * 2 + 0) * T_TGT) * D;
    const float* m1 = g_meta + ((size_t)(b * 2 + 1) * T_TGT) * D;
    const float* W = fW + (size_t)b * D * OUT_DIM;

    float acc[4][8];
#pragma unroll
    for (int a = 0; a < 4; a++)
#pragma unroll
        for (int j = 0; j < 8; j++) acc[a][j] = 0.f;

    for (int ch = 0; ch < 4; ch++) {
        __syncthreads();
        {
            int r = tid & 127, qb = tid >> 7;
            int row = base + r;
            bool val = row < T_TGT;
            const float4* p0 = (const float4*)(m0 + (size_t)row * D) + ch * 16;
            const float4* p1 = (const float4*)(m1 + (size_t)row * D) + ch * 16;
#pragma unroll
            for (int i = 0; i < 8; i++) {
                int q = qb + i * 2;
                float4 v0 = val ? __ldg(p0 + q) : make_float4(0.f, 0.f, 0.f, 0.f);
                float4 v1 = val ? __ldg(p1 + q) : make_float4(0.f, 0.f, 0.f, 0.f);
                ft[q * 4 + 0][r] = b0 * v0.x + b1 * v1.x;
                ft[q * 4 + 1][r] = b0 * v0.y + b1 * v1.y;
                ft[q * 4 + 2][r] = b0 * v0.z + b1 * v1.z;
                ft[q * 4 + 3][r] = b0 * v0.w + b1 * v1.w;
            }
        }
        {
            const float4* wp = (const float4*)(W + (size_t)ch * 64 * OUT_DIM);
            float4* wd = (float4*)&wt[0][0];
#pragma unroll
            for (int i = 0; i < 4; i++)
                wd[tid + i * 256] = __ldg(wp + tid + i * 256);
        }
        __syncthreads();
#pragma unroll 16
        for (int k = 0; k < 64; k++) {
            float4 fv = *(const float4*)&ft[k][rg * 4];
            float4 wv0 = *(const float4*)&wt[k][cg * 8];
            float4 wv1 = *(const float4*)&wt[k][cg * 8 + 4];
            float fr[4] = {fv.x, fv.y, fv.z, fv.w};
            float wc[8] = {wv0.x, wv0.y, wv0.z, wv0.w, wv1.x, wv1.y, wv1.z, wv1.w};
#pragma unroll
            for (int a = 0; a < 4; a++)
#pragma unroll
                for (int j = 0; j < 8; j++) acc[a][j] += fr[a] * wc[j];
        }
    }
    float bo[8];
#pragma unroll
    for (int j = 0; j < 8; j++) bo[j] = __ldg(&fb[b * OUT_DIM + cg * 8 + j]);
#pragma unroll
    for (int a = 0; a < 4; a++) {
        int row = base + rg * 4 + a;
        if (row < T_TGT) {
            float* op = outp + ((size_t)b * T_TGT + row) * OUT_DIM + cg * 8;
            *(float4*)op = make_float4(acc[a][0] + bo[0], acc[a][1] + bo[1],
                                       acc[a][2] + bo[2], acc[a][3] + bo[3]);
            *((float4*)op + 1) = make_float4(acc[a][4] + bo[4], acc[a][5] + bo[5],
                                             acc[a][6] + bo[6], acc[a][7] + bo[7]);
        }
    }
}

// ------------------------------- launch -------------------------------------
extern "C" void kernel_launch(void* const* d_in, const int* in_sizes, int n_in,
                              void* d_out, int out_size)
{
    const float* features0 = (const float*)d_in[0];
    const float* features1 = (const float*)d_in[1];
    const float* fc_W      = (const float*)d_in[2];
    const float* fc_b      = (const float*)d_in[3];
    const float* gat_W     = (const float*)d_in[4];
    const float* attn_l    = (const float*)d_in[5];
    const float* attn_r    = (const float*)d_in[6];
    const float* sem_W     = (const float*)d_in[7];
    const float* sem_b     = (const float*)d_in[8];
    const float* sem_q     = (const float*)d_in[9];
    const float* fcout_W   = (const float*)d_in[10];
    const float* fcout_b   = (const float*)d_in[11];
    const int*   type_idx  = (const int*)d_in[12];
    const int*   node_idx  = (const int*)d_in[13];
    const int*   edge_src  = (const int*)d_in[14];
    const int*   edge_dst  = (const int*)d_in[15];
    const int*   tgt_idx   = (const int*)d_in[16];
    float* out = (float*)d_out;

    static cudaStream_t s_side = nullptr;
    static cudaEvent_t ev_fork = nullptr, ev_scan = nullptr, ev_fc = nullptr,
                       ev_done = nullptr;
    static bool attr_done = false;
    if (!s_side) {
        cudaStreamCreateWithFlags(&s_side, cudaStreamNonBlocking);
        cudaEventCreateWithFlags(&ev_fork, cudaEventDisableTiming);
        cudaEventCreateWithFlags(&ev_scan, cudaEventDisableTiming);
        cudaEventCreateWithFlags(&ev_fc, cudaEventDisableTiming);
        cudaEventCreateWithFlags(&ev_done, cudaEventDisableTiming);
    }
    if (!attr_done) {
        cudaFuncSetAttribute(k_sem_mma, cudaFuncAttributeMaxDynamicSharedMemorySize,
                             SEMM_SZ);
        cudaFuncSetAttribute(k_gatz_mma, cudaFuncAttributeMaxDynamicSharedMemorySize,
                             GZ_SZ);
        cudaFuncSetAttribute(k_fc_mma, cudaFuncAttributeMaxDynamicSharedMemorySize,
                             FC_SZ);
        attr_done = true;
    }

    // main: init; fork side for mark/count/scan
    k_init<<<(G4 * NP_G + 255) / 256, 256>>>();
    cudaEventRecord(ev_fork, 0);
    cudaStreamWaitEvent(s_side, ev_fork, 0);
    k_mark<<<(G4 * T_TGT + 255) / 256, 256, 0, s_side>>>(tgt_idx);
    k_count<<<(G4 * E_G + 255) / 256, 256, 0, s_side>>>(edge_dst);
    k_scan<<<G4, 1024, 0, s_side>>>();
    cudaEventRecord(ev_scan, s_side);

    // main: weight prep + fc
    k_wal<<<G4, 512>>>(gat_W, attn_l, attn_r);
    k_wprep<<<896, 256>>>(fc_W, gat_W, sem_W);
    k_fc_mma<<<dim3((NP_TYPE + 127) / 128, 2), 256, FC_SZ>>>(
        features0, features1, fc_b, type_idx);
    cudaEventRecord(ev_fc, 0);

    // main chain: branch 0 (graphs 0,1)
    k_gatz_mma<<<dim3((NP_G + 63) / 64, 2), 256, GZ_SZ>>>(node_idx, 0);
    cudaStreamWaitEvent(0, ev_scan, 0);
    k_fill<<<(2 * E_G + 255) / 256, 256>>>(edge_src, edge_dst, 0);
    k_aggregate<<<(2 * T_TGT) / 8, 256>>>(tgt_idx, 0);
    k_sem_mma<<<(2 * T_TGT) / 64, 256, SEMM_SZ>>>(sem_b, sem_q, 0);
    k_combine<<<(T_TGT + 127) / 128, 256>>>(fcout_W, fcout_b, out, 0);

    // side chain: branch 1 (graphs 2,3)
    cudaStreamWaitEvent(s_side, ev_fc, 0);
    k_gatz_mma<<<dim3((NP_G + 63) / 64, 2), 256, GZ_SZ, s_side>>>(node_idx, 2);
    k_fill<<<(2 * E_G + 255) / 256, 256, 0, s_side>>>(edge_src, edge_dst, 2);
    k_aggregate<<<(2 * T_TGT) / 8, 256, 0, s_side>>>(tgt_idx, 2);
    k_sem_mma<<<(2 * T_TGT) / 64, 256, SEMM_SZ, s_side>>>(sem_b, sem_q, 1);
    k_combine<<<(T_TGT + 127) / 128, 256, 0, s_side>>>(fcout_W, fcout_b, out, 1);
    cudaEventRecord(ev_done, s_side);

    cudaStreamWaitEvent(0, ev_done, 0);
}

// round 15
// speedup vs baseline: 2.7289x; 1.0915x over previous
#include <cuda_runtime.h>
#include <cuda_bf16.h>
#include <cuda_fp16.h>
#include <math.h>
#include <stdint.h>

#define N_TOTAL 100000
#define NP_TYPE 50000
#define NP_G    50000
#define E_G     500000
#define NH      4
#define HD      64
#define HID     64
#define D       256
#define OUT_DIM 64
#define T_TGT   20000
#define G4      4
#define OFFS_S  50016   // padded offs stride (16B-aligned per graph)

// ------------------------- scratch (static device globals) -------------------
__device__ __half g_th[N_TOTAL * HID];                   // 12.8 MB (fp16 h)
__device__ __half g_zh[(size_t)G4 * NP_G * D];           // 102.4 MB (fp16 z)
__device__ float  g_el[G4 * NP_G * NH];
__device__ float  g_er[G4 * NP_G * NH];
__device__ float  g_wal[G4 * 64 * 8];                    // W@attn per graph
__device__ int    g_istgt[G4 * NP_G];
__device__ int    g_deg[G4 * NP_G];
__device__ int    g_offs[G4 * OFFS_S];
__device__ int    g_cur[G4 * NP_G];
__device__ int    g_csr_src[G4 * E_G];
__device__ float4 g_csr_ex[G4 * E_G];
__device__ __half g_metah[(size_t)G4 * T_TGT * D];       // 41 MB (fp16 meta)
__device__ float  g_wsum[4];
// preconverted weights
__device__ __half g_fcWh[2 * 64 * 256];                  // [t][o][k]
__device__ __half g_gatWT[G4 * 256 * 64];                // [g][o][k]
__device__ __half g_semWT[2 * 8 * 256 * 32];             // [b][ch][o][kk]

// ------------------------------ small helpers --------------------------------
__device__ __forceinline__ uint32_t smem_u32(const void* p) {
    uint32_t a;
    asm("{ .reg .u64 t; cvta.to.shared.u64 t, %1; cvt.u32.u64 %0, t; }" : "=r"(a) : "l"(p));
    return a;
}
__device__ __forceinline__ uint32_t pack_f16(float lo, float hi) {
    uint32_t r;
    asm("cvt.rn.f16x2.f32 %0, %1, %2;" : "=r"(r) : "f"(hi), "f"(lo));
    return r;
}
__device__ __forceinline__ float tanh_dot2(float x0, float x1, uint32_t qh) {
    uint32_t xp = pack_f16(x0, x1), tp, pp;
    asm("tanh.approx.f16x2 %0, %1;" : "=r"(tp) : "r"(xp));
    asm("mul.f16x2 %0, %1, %2;" : "=r"(pp) : "r"(tp), "r"(qh));
    __half2 h = *reinterpret_cast<__half2*>(&pp);
    return __low2float(h) + __high2float(h);
}
// accumulate 8 fp16 z-values (packed in uint4) scaled by w into a0/a1
__device__ __forceinline__ void acc_z(float4& a0, float4& a1, uint4 zv, float w) {
    float2 f0 = __half22float2(*reinterpret_cast<__half2*>(&zv.x));
    float2 f1 = __half22float2(*reinterpret_cast<__half2*>(&zv.y));
    float2 f2 = __half22float2(*reinterpret_cast<__half2*>(&zv.z));
    float2 f3 = __half22float2(*reinterpret_cast<__half2*>(&zv.w));
    a0.x += w * f0.x; a0.y += w * f0.y;
    a0.z += w * f1.x; a0.w += w * f1.y;
    a1.x += w * f2.x; a1.y += w * f2.y;
    a1.z += w * f3.x; a1.w += w * f3.y;
}
__device__ __forceinline__ void ldsm_x4(uint32_t& r0, uint32_t& r1, uint32_t& r2,
                                        uint32_t& r3, uint32_t addr) {
    asm volatile("ldmatrix.sync.aligned.m8n8.x4.shared.b16 {%0,%1,%2,%3}, [%4];"
                 : "=r"(r0), "=r"(r1), "=r"(r2), "=r"(r3) : "r"(addr));
}
__device__ __forceinline__ void mma_f16(float* c, uint32_t a0, uint32_t a1,
                                        uint32_t a2, uint32_t a3,
                                        uint32_t b0, uint32_t b1) {
    asm volatile(
        "mma.sync.aligned.m16n8k16.row.col.f32.f16.f16.f32 "
        "{%0,%1,%2,%3}, {%4,%5,%6,%7}, {%8,%9}, {%0,%1,%2,%3};"
        : "+f"(c[0]), "+f"(c[1]), "+f"(c[2]), "+f"(c[3])
        : "r"(a0), "r"(a1), "r"(a2), "r"(a3), "r"(b0), "r"(b1));
}

// k_sem_mma dynamic smem layout
#define SEMM_AS   264
#define SEMM_WS   40
#define SEMM_A_B  (64 * SEMM_AS * 2)
#define SEMM_W_O  SEMM_A_B
#define SEMM_W_B  (256 * SEMM_WS * 2)
#define SEMM_BO_O (SEMM_W_O + SEMM_W_B)
#define SEMM_QH_O (SEMM_BO_O + 1024)
#define SEMM_BK_O (SEMM_QH_O + 512)
#define SEMM_SZ   (SEMM_BK_O + 128)

// k_gatz_mma fp16 layout
#define GZ_S      72
#define GZ_AH_O   0
#define GZ_BH_O   9216
#define GZ_WAL_O  46080
#define GZ_SZ     (GZ_WAL_O + 2048)

// k_fc_mma fp16 layout
#define FC_AS     264
#define FC_A_O    0
#define FC_A_B    (128 * FC_AS * 2)
#define FC_B_O    FC_A_B
#define FC_B_B    (64 * FC_AS * 2)
#define FC_BO_O   (FC_B_O + FC_B_B)
#define FC_SZ     (FC_BO_O + 256)

// ------------------------------- init ---------------------------------------
__global__ void k_init() {
    int i = blockIdx.x * blockDim.x + threadIdx.x;
    if (i < G4 * NP_G) { g_deg[i] = 0; g_istgt[i] = 0; }
    if (i < 4) g_wsum[i] = 0.f;
}

__global__ void k_mark(const int* __restrict__ tgt) {
    int t = blockIdx.x * blockDim.x + threadIdx.x;
    if (t < G4 * T_TGT) {
        int g = t / T_TGT;
        g_istgt[g * NP_G + __ldg(&tgt[t])] = 1;
    }
}

// one-time weight preconversion into MMA-friendly layouts
__global__ void k_wprep(const float* __restrict__ fcW,
                        const float* __restrict__ gatW,
                        const float* __restrict__ semW) {
    int i = blockIdx.x * blockDim.x + threadIdx.x;
    if (i < 2 * 64 * 256) {
        g_fcWh[i] = __float2half(__ldg(&fcW[i]));
        return;
    }
    int j = i - 2 * 64 * 256;
    if (j < G4 * 256 * 64) {
        int g = j >> 14, r = j & 16383;
        int o = r >> 6, k = r & 63;
        g_gatWT[j] = __float2half(__ldg(&gatW[g * 16384 + k * 256 + o]));
        return;
    }
    int m = j - G4 * 256 * 64;
    if (m < 2 * 8 * 256 * 32) {
        int b = m >> 16, r2 = m & 65535;
        int ch = r2 >> 13, r3 = r2 & 8191;
        int o = r3 >> 5, kk = r3 & 31;
        g_semWT[m] = __float2half(__ldg(&semW[b * 65536 + (ch * 32 + kk) * 256 + o]));
    }
}

// ---- wal/war: per-graph W @ attn --------------------------------------------
__global__ void k_wal(const float* __restrict__ gatW,
                      const float* __restrict__ attn_l,
                      const float* __restrict__ attn_r)
{
    int g = blockIdx.x;
    int idx = threadIdx.x;
    int k = idx >> 3, o = idx & 7;
    int side = o >> 2, h = o & 3;
    const float* att = (side ? attn_r : attn_l) + (size_t)g * D + h * 64;
    const float* wr = gatW + (size_t)g * HID * D + (size_t)k * D + h * 64;
    float s = 0.f;
#pragma unroll 16
    for (int d = 0; d < 64; d++) s += __ldg(&wr[d]) * __ldg(&att[d]);
    g_wal[g * 512 + k * 8 + o] = s;
}

// ---------- fc on mma.sync fp16; fp16 output stores --------------------------
__global__ __launch_bounds__(256) void k_fc_mma(
    const float* __restrict__ f0, const float* __restrict__ f1,
    const float* __restrict__ fcb, const int* __restrict__ type_idx)
{
    extern __shared__ char smem[];
    __half* fA = (__half*)(smem + FC_A_O);
    __half* fB = (__half*)(smem + FC_B_O);
    float* bo_s = (float*)(smem + FC_BO_O);

    int t = blockIdx.y;
    int base = blockIdx.x * 128;
    const float* feat = t ? f1 : f0;
    int tid = threadIdx.x;
    int wid = tid >> 5, lane = tid & 31;

    if (tid < 64) bo_s[tid] = __ldg(&fcb[t * HID + tid]);

    {   // A: 128 rows x 256 k fp32 -> fp16
        int r = tid >> 2, kq = tid & 3;
#pragma unroll
        for (int rr = 0; rr < 2; rr++) {
            int row = base + rr * 64 + r;
            bool val = row < NP_TYPE;
            const float4* fp = (const float4*)(feat + (size_t)row * D) + kq * 16;
            __half* dst = &fA[(rr * 64 + r) * FC_AS + kq * 64];
#pragma unroll 4
            for (int i = 0; i < 16; i++) {
                float4 v = val ? __ldg(fp + i) : make_float4(0.f, 0.f, 0.f, 0.f);
                *(uint2*)(dst + i * 4) =
                    make_uint2(pack_f16(v.x, v.y), pack_f16(v.z, v.w));
            }
        }
    }
    {   // B: coalesced copy of preconverted fp16 weights
        int o = tid & 63, sq = tid >> 6;
        const uint4* wsrc = (const uint4*)&g_fcWh[(size_t)t * 16384 + o * 256 + sq * 64];
        uint4* wdst = (uint4*)&fB[o * FC_AS + sq * 64];
#pragma unroll
        for (int i = 0; i < 8; i++) wdst[i] = __ldg(wsrc + i);
    }
    __syncthreads();

    float cacc[8][4];
#pragma unroll
    for (int ti = 0; ti < 8; ti++)
#pragma unroll
        for (int j = 0; j < 4; j++) cacc[ti][j] = 0.f;

    int a_tile = lane >> 3;
    int a_row = wid * 16 + (lane & 7) + (a_tile & 1) * 8;
    int a_koff = (a_tile >> 1) * 8;
    int b_g = lane >> 3;
    int b_nbase = (b_g >> 1) * 8 + (lane & 7);
    int b_koff = (b_g & 1) * 8;

#pragma unroll
    for (int ks = 0; ks < 16; ks++) {
        uint32_t a0, a1, a2, a3;
        ldsm_x4(a0, a1, a2, a3, smem_u32(&fA[a_row * FC_AS + ks * 16 + a_koff]));
#pragma unroll
        for (int nt = 0; nt < 4; nt++) {
            uint32_t b0, b1, b2, b3;
            ldsm_x4(b0, b1, b2, b3,
                    smem_u32(&fB[(b_nbase + nt * 16) * FC_AS + ks * 16 + b_koff]));
            mma_f16(cacc[nt * 2 + 0], a0, a1, a2, a3, b0, b1);
            mma_f16(cacc[nt * 2 + 1], a0, a1, a2, a3, b2, b3);
        }
    }

    int lr = lane >> 2, lc = lane & 3;
    int r0 = base + wid * 16 + lr, r1 = r0 + 8;
    const int* ti_p = type_idx + t * NP_TYPE;
    int d0 = (r0 < NP_TYPE) ? __ldg(&ti_p[r0]) : -1;
    int d1 = (r1 < NP_TYPE) ? __ldg(&ti_p[r1]) : -1;
#pragma unroll
    for (int ti = 0; ti < 8; ti++) {
        int col = ti * 8 + lc * 2;
        float b0v = bo_s[col], b1v = bo_s[col + 1];
        if (d0 >= 0)
            *(uint32_t*)&g_th[(size_t)d0 * HID + col] =
                pack_f16(cacc[ti][0] + b0v, cacc[ti][1] + b1v);
        if (d1 >= 0)
            *(uint32_t*)&g_th[(size_t)d1 * HID + col] =
                pack_f16(cacc[ti][2] + b0v, cacc[ti][3] + b1v);
    }
}

// -------- gatz on mma.sync fp16 (per-branch: 2 graphs via gbase) -------------
__global__ __launch_bounds__(256) void k_gatz_mma(const int* __restrict__ node_idx,
                                                  int gbase)
{
    extern __shared__ char smem[];
    __half* ah = (__half*)(smem + GZ_AH_O);
    __half* bh = (__half*)(smem + GZ_BH_O);
    float* wal_s = (float*)(smem + GZ_WAL_O);

    int g = gbase + blockIdx.y;
    int base = blockIdx.x * 64;
    int tid = threadIdx.x;
    int wid = tid >> 5, lane = tid & 31;

    {   // A: gather 64 rows x 64 cols fp16 (direct uint4 copies, no cvt)
        int r = tid >> 2, kq = tid & 3;
        int row = base + r;
        int node = (row < NP_G) ? __ldg(&node_idx[(size_t)g * NP_G + row]) : -1;
        uint4 v0 = make_uint4(0, 0, 0, 0), v1 = make_uint4(0, 0, 0, 0);
        if (node >= 0) {
            const uint4* hp = (const uint4*)(g_th + (size_t)node * HID + kq * 16);
            v0 = __ldg(hp);
            v1 = __ldg(hp + 1);
        }
        *(uint4*)&ah[r * GZ_S + kq * 16] = v0;
        *(uint4*)&ah[r * GZ_S + kq * 16 + 8] = v1;
    }
    {   // B: coalesced copy of preconverted W^T fp16
        const uint4* wsrc = (const uint4*)&g_gatWT[(size_t)g * 16384 + tid * 64];
        uint4* wdst = (uint4*)&bh[tid * GZ_S];
#pragma unroll
        for (int i = 0; i < 8; i++) wdst[i] = __ldg(wsrc + i);
    }
    wal_s[tid] = g_wal[g * 512 + tid];
    wal_s[tid + 256] = g_wal[g * 512 + tid + 256];
    __syncthreads();

    int rw = wid >> 1, cw = wid & 1;
    float cacc[16][4];
#pragma unroll
    for (int ti = 0; ti < 16; ti++)
#pragma unroll
        for (int j = 0; j < 4; j++) cacc[ti][j] = 0.f;

    int a_tile = lane >> 3;
    int a_row = rw * 16 + (lane & 7) + (a_tile & 1) * 8;
    int a_koff = (a_tile >> 1) * 8;
    int b_g = lane >> 3;
    int b_nbase = cw * 128 + (b_g >> 1) * 8 + (lane & 7);
    int b_koff = (b_g & 1) * 8;

#pragma unroll
    for (int ks = 0; ks < 4; ks++) {
        uint32_t a0, a1, a2, a3;
        ldsm_x4(a0, a1, a2, a3, smem_u32(&ah[a_row * GZ_S + ks * 16 + a_koff]));
#pragma unroll
        for (int nt = 0; nt < 8; nt++) {
            uint32_t b0, b1, b2, b3;
            ldsm_x4(b0, b1, b2, b3,
                    smem_u32(&bh[(b_nbase + nt * 16) * GZ_S + ks * 16 + b_koff]));
            mma_f16(cacc[nt * 2 + 0], a0, a1, a2, a3, b0, b1);
            mma_f16(cacc[nt * 2 + 1], a0, a1, a2, a3, b2, b3);
        }
    }

    {   // z stores (fp16 pairs)
        int lr = lane >> 2, lc = lane & 3;
        int r0 = base + rw * 16 + lr, r1 = r0 + 8;
        bool v0 = r0 < NP_G, v1 = r1 < NP_G;
        __half* z0 = g_zh + ((size_t)g * NP_G + r0) * D + cw * 128 + lc * 2;
        __half* z1 = g_zh + ((size_t)g * NP_G + r1) * D + cw * 128 + lc * 2;
#pragma unroll
        for (int ti = 0; ti < 16; ti++) {
            if (v0) *(uint32_t*)(z0 + ti * 8) = pack_f16(cacc[ti][0], cacc[ti][1]);
            if (v1) *(uint32_t*)(z1 + ti * 8) = pack_f16(cacc[ti][2], cacc[ti][3]);
        }
    }

    {   // el/er: h . wal (fp16 h)
        int r = tid & 63;
        int ob = (tid >> 6) * 2;
        int row = base + r;
        if (row < NP_G) {
            float e0 = 0.f, e1 = 0.f;
#pragma unroll 8
            for (int k = 0; k < 64; k += 2) {
                __half2 hb = *(__half2*)&ah[r * GZ_S + k];
                float h0 = __low2float(hb), h1 = __high2float(hb);
                e0 += h0 * wal_s[k * 8 + ob]     + h1 * wal_s[(k + 1) * 8 + ob];
                e1 += h0 * wal_s[k * 8 + ob + 1] + h1 * wal_s[(k + 1) * 8 + ob + 1];
            }
            size_t nbase = ((size_t)g * NP_G + row) * NH;
            if (ob < 4) {
                g_el[nbase + ob] = e0;
                g_el[nbase + ob + 1] = e1;
            } else {
                g_er[nbase + ob - 4] = e0;
                g_er[nbase + ob - 3] = e1;
            }
        }
    }
}

// ------------------------------- CSR build (target-filtered) -----------------
__global__ void k_count(const int* __restrict__ dst) {
    int e = blockIdx.x * blockDim.x + threadIdx.x;
    if (e < G4 * E_G) {
        int g = e / E_G;
        int gn = g * NP_G + __ldg(&dst[e]);
        if (g_istgt[gn]) atomicAdd(&g_deg[gn], 1);
    }
}

// vectorized single-block-per-graph scan
__global__ __launch_bounds__(1024) void k_scan() {
    __shared__ int ws[32];
    int g = blockIdx.x;
    int tid = threadIdx.x;
    int lane = tid & 31, wid = tid >> 5;
    const int CH = 52;
    int lo = tid * CH;
    const int* deg = g_deg + g * NP_G;
    bool fast = (lo + CH) <= NP_G;
    int s = 0;
    if (fast) {
        const int4* p = (const int4*)(deg + lo);
#pragma unroll
        for (int c = 0; c < 13; c++) {
            int4 v = p[c];
            s += v.x + v.y + v.z + v.w;
        }
    } else {
        for (int i = lo; i < NP_G; i++) s += deg[i];
    }
    int v = s;
#pragma unroll
    for (int off = 1; off < 32; off <<= 1) {
        int n = __shfl_up_sync(0xffffffffu, v, off);
        if (lane >= off) v += n;
    }
    if (lane == 31) ws[wid] = v;
    __syncthreads();
    if (wid == 0) {
        int w = ws[lane];
#pragma unroll
        for (int off = 1; off < 32; off <<= 1) {
            int n = __shfl_up_sync(0xffffffffu, w, off);
            if (lane >= off) w += n;
        }
        ws[lane] = w;
    }
    __syncthreads();
    int run = v - s + (wid ? ws[wid - 1] : 0);
    int* offs = g_offs + g * OFFS_S;
    int* cur = g_cur + g * NP_G;
    if (fast) {
        const int4* p = (const int4*)(deg + lo);
        int4* po = (int4*)(offs + lo);
        int4* pc = (int4*)(cur + lo);
#pragma unroll
        for (int c = 0; c < 13; c++) {
            int4 d4 = p[c];
            int4 o4;
            o4.x = run;
            o4.y = run + d4.x;
            o4.z = o4.y + d4.y;
            o4.w = o4.z + d4.z;
            run = o4.w + d4.w;
            po[c] = o4;
            pc[c] = o4;
        }
    } else {
        for (int i = lo; i < NP_G; i++) {
            offs[i] = run;
            cur[i] = run;
            run += deg[i];
        }
    }
    if (tid == 0) offs[NP_G] = ws[31];
}

__global__ void k_fill(const int* __restrict__ src, const int* __restrict__ dst,
                       int gbase) {
    int e = blockIdx.x * blockDim.x + threadIdx.x;
    if (e >= 2 * E_G) return;
    int gl = e / E_G;
    int g = gbase + gl;
    size_t eidx = (size_t)g * E_G + (e - gl * E_G);
    int d = __ldg(&dst[eidx]);
    int gn = g * NP_G;
    if (!g_istgt[gn + d]) return;
    int s = __ldg(&src[eidx]);
    float4 elv = __ldg((const float4*)g_el + gn + s);
    float4 erv = __ldg((const float4*)g_er + gn + d);
    float e0 = elv.x + erv.x, e1 = elv.y + erv.y;
    float e2 = elv.z + erv.z, e3 = elv.w + erv.w;
    e0 = e0 > 0.f ? e0 : 0.2f * e0;
    e1 = e1 > 0.f ? e1 : 0.2f * e1;
    e2 = e2 > 0.f ? e2 : 0.2f * e2;
    e3 = e3 > 0.f ? e3 : 0.2f * e3;
    float4 ex = make_float4(__expf(e0), __expf(e1), __expf(e2), __expf(e3));
    int pos = atomicAdd(&g_cur[gn + d], 1);
    g_csr_src[(size_t)g * E_G + pos] = s;
    g_csr_ex[(size_t)g * E_G + pos] = ex;
}

// ------ aggregate: warp per TARGET, fused softmax, fp16 z + fp16 meta -------
__global__ __launch_bounds__(256) void k_aggregate(const int* __restrict__ tgt,
                                                   int gbase) {
    int t = (blockIdx.x * blockDim.x + threadIdx.x) >> 5;
    if (t >= 2 * T_TGT) return;
    int g = gbase + t / T_TGT;
    int tglob = gbase * T_TGT + t;
    int lane = threadIdx.x & 31;
    int hsel = lane >> 3;
    int nl = __ldg(&tgt[tglob]);
    int beg = g_offs[g * OFFS_S + nl];
    int end = g_offs[g * OFFS_S + nl + 1];
    const int* cs = g_csr_src + (size_t)g * E_G;
    const float4* ce = g_csr_ex + (size_t)g * E_G;
    const __half* zb = g_zh + (size_t)g * NP_G * D;

    float4 a0 = {0.f, 0.f, 0.f, 0.f}, a1 = {0.f, 0.f, 0.f, 0.f};
    float den = 0.f;

    int i = beg;
    for (; i + 4 <= end; i += 4) {
        int s0 = __ldg(cs + i), s1 = __ldg(cs + i + 1);
        int s2 = __ldg(cs + i + 2), s3 = __ldg(cs + i + 3);
        float4 e0 = __ldg(ce + i), e1 = __ldg(ce + i + 1);
        float4 e2 = __ldg(ce + i + 2), e3 = __ldg(ce + i + 3);
        uint4 zv0 = __ldg((const uint4*)(zb + (size_t)s0 * D + lane * 8));
        uint4 zv1 = __ldg((const uint4*)(zb + (size_t)s1 * D + lane * 8));
        uint4 zv2 = __ldg((const uint4*)(zb + (size_t)s2 * D + lane * 8));
        uint4 zv3 = __ldg((const uint4*)(zb + (size_t)s3 * D + lane * 8));
        float x0 = (hsel == 0) ? e0.x : (hsel == 1) ? e0.y : (hsel == 2) ? e0.z : e0.w;
        float x1 = (hsel == 0) ? e1.x : (hsel == 1) ? e1.y : (hsel == 2) ? e1.z : e1.w;
        float x2 = (hsel == 0) ? e2.x : (hsel == 1) ? e2.y : (hsel == 2) ? e2.z : e2.w;
        float x3 = (hsel == 0) ? e3.x : (hsel == 1) ? e3.y : (hsel == 2) ? e3.z : e3.w;
        acc_z(a0, a1, zv0, x0);
        acc_z(a0, a1, zv1, x1);
        acc_z(a0, a1, zv2, x2);
        acc_z(a0, a1, zv3, x3);
        den += x0 + x1 + x2 + x3;
    }
    for (; i < end; i++) {
        int s0 = __ldg(cs + i);
        float4 e0 = __ldg(ce + i);
        uint4 zv0 = __ldg((const uint4*)(zb + (size_t)s0 * D + lane * 8));
        float x0 = (hsel == 0) ? e0.x : (hsel == 1) ? e0.y : (hsel == 2) ? e0.z : e0.w;
        acc_z(a0, a1, zv0, x0);
        den += x0;
    }
    float inv = 1.f / (den + 1e-9f);
    float v[8] = {a0.x * inv, a0.y * inv, a0.z * inv, a0.w * inv,
                  a1.x * inv, a1.y * inv, a1.z * inv, a1.w * inv};
#pragma unroll
    for (int j = 0; j < 8; j++) v[j] = v[j] > 0.f ? v[j] : expm1f(v[j]);
    __half* op = g_metah + (size_t)tglob * D + lane * 8;
    *(uint2*)op = make_uint2(pack_f16(v[0], v[1]), pack_f16(v[2], v[3]));
    *(uint2*)(op + 4) = make_uint2(pack_f16(v[4], v[5]), pack_f16(v[6], v[7]));
}

// ----- semantic attention on mma.sync fp16 (fp16 meta, direct copies) -------
__global__ __launch_bounds__(256) void k_sem_mma(
    const float* __restrict__ semb, const float* __restrict__ semq, int b)
{
    extern __shared__ char smem[];
    __half* ftA = (__half*)smem;
    __half* wt  = (__half*)(smem + SEMM_W_O);
    float*    bo_s = (float*)(smem + SEMM_BO_O);
    uint32_t* qh_s = (uint32_t*)(smem + SEMM_QH_O);
    float*  bucket = (float*)(smem + SEMM_BK_O);

    const int BR = 2 * T_TGT;
    int tid = threadIdx.x;
    int wid = tid >> 5, lane = tid & 31;
    int base = blockIdx.x * 64;

    if (tid < 64) ((float4*)bo_s)[tid] = __ldg((const float4*)(semb + b * D) + tid);
    else if (tid < 192) {
        int j = tid - 64;
        float q0 = __ldg(&semq[b * D + 2 * j]);
        float q1 = __ldg(&semq[b * D + 2 * j + 1]);
        qh_s[j] = pack_f16(q0, q1);
    }
    if (tid < 2) bucket[tid] = 0.f;

    {   // A: direct fp16 copies from g_metah (8 uint4 per thread)
        int r = tid >> 2, kq = tid & 3;
        const uint4* ap =
            (const uint4*)(g_metah + ((size_t)b * BR + base + r) * D + kq * 64);
        __half* dst = &ftA[r * SEMM_AS + kq * 64];
#pragma unroll
        for (int i = 0; i < 8; i++) *(uint4*)(dst + i * 8) = __ldg(ap + i);
    }

    int rw = wid >> 1, cw = wid & 1;
    float cacc[16][4];
#pragma unroll
    for (int ti = 0; ti < 16; ti++)
#pragma unroll
        for (int j = 0; j < 4; j++) cacc[ti][j] = 0.f;

    int a_tile = lane >> 3;
    int a_row = rw * 16 + (lane & 7) + (a_tile & 1) * 8;
    int a_koff = (a_tile >> 1) * 8;
    int b_g = lane >> 3;
    int b_nbase = cw * 128 + (b_g >> 1) * 8 + (lane & 7);
    int b_koff = (b_g & 1) * 8;

    for (int ch = 0; ch < 8; ch++) {
        __syncthreads();
        {
            const uint4* wsrc =
                (const uint4*)&g_semWT[((size_t)b * 8 + ch) * 8192 + tid * 32];
            uint4* wdst = (uint4*)&wt[tid * SEMM_WS];
#pragma unroll
            for (int i = 0; i < 4; i++) wdst[i] = __ldg(wsrc + i);
        }
        __syncthreads();
#pragma unroll
        for (int ks = 0; ks < 2; ks++) {
            uint32_t a0, a1, a2, a3;
            ldsm_x4(a0, a1, a2, a3,
                    smem_u32(&ftA[a_row * SEMM_AS + ch * 32 + ks * 16 + a_koff]));
#pragma unroll
            for (int nt = 0; nt < 8; nt++) {
                uint32_t b0, b1, b2, b3;
                ldsm_x4(b0, b1, b2, b3,
                        smem_u32(&wt[(b_nbase + nt * 16) * SEMM_WS + ks * 16 + b_koff]));
                mma_f16(cacc[nt * 2 + 0], a0, a1, a2, a3, b0, b1);
                mma_f16(cacc[nt * 2 + 1], a0, a1, a2, a3, b2, b3);
            }
        }
    }

    int lr = lane >> 2, lc = lane & 3;
    float rs0 = 0.f, rs1 = 0.f;
#pragma unroll
    for (int ti = 0; ti < 16; ti++) {
        int col = cw * 128 + ti * 8 + lc * 2;
        uint32_t qh = qh_s[col >> 1];
        float b0v = bo_s[col], b1v = bo_s[col + 1];
        rs0 += tanh_dot2(cacc[ti][0] + b0v, cacc[ti][1] + b1v, qh);
        rs1 += tanh_dot2(cacc[ti][2] + b0v, cacc[ti][3] + b1v, qh);
    }
    rs0 += __shfl_down_sync(0xffffffffu, rs0, 2, 4);
    rs0 += __shfl_down_sync(0xffffffffu, rs0, 1, 4);
    rs1 += __shfl_down_sync(0xffffffffu, rs1, 2, 4);
    rs1 += __shfl_down_sync(0xffffffffu, rs1, 1, 4);
    if (lc == 0) {
        int r0 = base + rw * 16 + lr;
        int r1 = r0 + 8;
        atomicAdd(&bucket[r0 >= T_TGT ? 1 : 0], rs0);
        atomicAdd(&bucket[r1 >= T_TGT ? 1 : 0], rs1);
    }
    __syncthreads();
    if (tid < 2 && bucket[tid] != 0.f) atomicAdd(&g_wsum[b * 2 + tid], bucket[tid]);
}

// -------------- combine: beta-blend fp16 metas, @ fcout_W + bias ------------
__global__ __launch_bounds__(256) void k_combine(
    const float* __restrict__ fW, const float* __restrict__ fb,
    float* __restrict__ outp, int b)
{
    __shared__ float ft[64][128];
    __shared__ float wt[64][64];

    int base = blockIdx.x * 128;
    int tid = threadIdx.x;
    int rg = tid & 31, cg = tid >> 5;

    float w0 = g_wsum[b * 2 + 0] * (1.f / T_TGT);
    float w1 = g_wsum[b * 2 + 1] * (1.f / T_TGT);
    float mx = fmaxf(w0, w1);
    float b0 = __expf(w0 - mx), b1 = __expf(w1 - mx);
    float sm = b0 + b1;
    b0 /= sm; b1 /= sm;

    const __half* m0 = g_metah + ((size_t)(b * 2 + 0) * T_TGT) * D;
    const __half* m1 = g_metah + ((size_t)(b * 2 + 1) * T_TGT) * D;
    const float* W = fW + (size_t)b * D * OUT_DIM;

    float acc[4][8];
#pragma unroll
    for (int a = 0; a < 4; a++)
#pragma unroll
        for (int j = 0; j < 8; j++) acc[a][j] = 0.f;

    for (int ch = 0; ch < 4; ch++) {
        __syncthreads();
        {   // blended ft chunk: 64 k x 128 rows, fp16 sources
            int r = tid & 127, qb = tid >> 7;
            int row = base + r;
            bool val = row < T_TGT;
            const uint4* p0 = (const uint4*)(m0 + (size_t)row * D + ch * 64) + qb * 4;
            const uint4* p1 = (const uint4*)(m1 + (size_t)row * D + ch * 64) + qb * 4;
#pragma unroll
            for (int i = 0; i < 4; i++) {
                uint4 u0 = val ? __ldg(p0 + i) : make_uint4(0, 0, 0, 0);
                uint4 u1 = val ? __ldg(p1 + i) : make_uint4(0, 0, 0, 0);
                int k = qb * 32 + i * 8;
                float2 a0p = __half22float2(*(__half2*)&u0.x);
                float2 a1p = __half22float2(*(__half2*)&u0.y);
                float2 a2p = __half22float2(*(__half2*)&u0.z);
                float2 a3p = __half22float2(*(__half2*)&u0.w);
                float2 c0p = __half22float2(*(__half2*)&u1.x);
                float2 c1p = __half22float2(*(__half2*)&u1.y);
                float2 c2p = __half22float2(*(__half2*)&u1.z);
                float2 c3p = __half22float2(*(__half2*)&u1.w);
                ft[k + 0][r] = b0 * a0p.x + b1 * c0p.x;
                ft[k + 1][r] = b0 * a0p.y + b1 * c0p.y;
                ft[k + 2][r] = b0 * a1p.x + b1 * c1p.x;
                ft[k + 3][r] = b0 * a1p.y + b1 * c1p.y;
                ft[k + 4][r] = b0 * a2p.x + b1 * c2p.x;
                ft[k + 5][r] = b0 * a2p.y + b1 * c2p.y;
                ft[k + 6][r] = b0 * a3p.x + b1 * c3p.x;
                ft[k + 7][r] = b0 * a3p.y + b1 * c3p.y;
            }
        }
        {
            const float4* wp = (const float4*)(W + (size_t)ch * 64 * OUT_DIM);
            float4* wd = (float4*)&wt[0][0];
#pragma unroll
            for (int i = 0; i < 4; i++)
                wd[tid + i * 256] = __ldg(wp + tid + i * 256);
        }
        __syncthreads();
#pragma unroll 16
        for (int k = 0; k < 64; k++) {
            float4 fv = *(const float4*)&ft[k][rg * 4];
            float4 wv0 = *(const float4*)&wt[k][cg * 8];
            float4 wv1 = *(const float4*)&wt[k][cg * 8 + 4];
            float fr[4] = {fv.x, fv.y, fv.z, fv.w};
            float wc[8] = {wv0.x, wv0.y, wv0.z, wv0.w, wv1.x, wv1.y, wv1.z, wv1.w};
#pragma unroll
            for (int a = 0; a < 4; a++)
#pragma unroll
                for (int j = 0; j < 8; j++) acc[a][j] += fr[a] * wc[j];
        }
    }
    float bo[8];
#pragma unroll
    for (int j = 0; j < 8; j++) bo[j] = __ldg(&fb[b * OUT_DIM + cg * 8 + j]);
#pragma unroll
    for (int a = 0; a < 4; a++) {
        int row = base + rg * 4 + a;
        if (row < T_TGT) {
            float* op = outp + ((size_t)b * T_TGT + row) * OUT_DIM + cg * 8;
            *(float4*)op = make_float4(acc[a][0] + bo[0], acc[a][1] + bo[1],
                                       acc[a][2] + bo[2], acc[a][3] + bo[3]);
            *((float4*)op + 1) = make_float4(acc[a][4] + bo[4], acc[a][5] + bo[5],
                                             acc[a][6] + bo[6], acc[a][7] + bo[7]);
        }
    }
}

// ------------------------------- launch -------------------------------------
extern "C" void kernel_launch(void* const* d_in, const int* in_sizes, int n_in,
                              void* d_out, int out_size)
{
    const float* features0 = (const float*)d_in[0];
    const float* features1 = (const float*)d_in[1];
    const float* fc_W      = (const float*)d_in[2];
    const float* fc_b      = (const float*)d_in[3];
    const float* gat_W     = (const float*)d_in[4];
    const float* attn_l    = (const float*)d_in[5];
    const float* attn_r    = (const float*)d_in[6];
    const float* sem_W     = (const float*)d_in[7];
    const float* sem_b     = (const float*)d_in[8];
    const float* sem_q     = (const float*)d_in[9];
    const float* fcout_W   = (const float*)d_in[10];
    const float* fcout_b   = (const float*)d_in[11];
    const int*   type_idx  = (const int*)d_in[12];
    const int*   node_idx  = (const int*)d_in[13];
    const int*   edge_src  = (const int*)d_in[14];
    const int*   edge_dst  = (const int*)d_in[15];
    const int*   tgt_idx   = (const int*)d_in[16];
    float* out = (float*)d_out;

    static cudaStream_t s_side = nullptr;
    static cudaEvent_t ev_fork = nullptr, ev_scan = nullptr, ev_fc = nullptr,
                       ev_done = nullptr;
    static bool attr_done = false;
    if (!s_side) {
        cudaStreamCreateWithFlags(&s_side, cudaStreamNonBlocking);
        cudaEventCreateWithFlags(&ev_fork, cudaEventDisableTiming);
        cudaEventCreateWithFlags(&ev_scan, cudaEventDisableTiming);
        cudaEventCreateWithFlags(&ev_fc, cudaEventDisableTiming);
        cudaEventCreateWithFlags(&ev_done, cudaEventDisableTiming);
    }
    if (!attr_done) {
        cudaFuncSetAttribute(k_sem_mma, cudaFuncAttributeMaxDynamicSharedMemorySize,
                             SEMM_SZ);
        cudaFuncSetAttribute(k_gatz_mma, cudaFuncAttributeMaxDynamicSharedMemorySize,
                             GZ_SZ);
        cudaFuncSetAttribute(k_fc_mma, cudaFuncAttributeMaxDynamicSharedMemorySize,
                             FC_SZ);
        attr_done = true;
    }

    // main: init; fork side for mark/count/scan
    k_init<<<(G4 * NP_G + 255) / 256, 256>>>();
    cudaEventRecord(ev_fork, 0);
    cudaStreamWaitEvent(s_side, ev_fork, 0);
    k_mark<<<(G4 * T_TGT + 255) / 256, 256, 0, s_side>>>(tgt_idx);
    k_count<<<(G4 * E_G + 255) / 256, 256, 0, s_side>>>(edge_dst);
    k_scan<<<G4, 1024, 0, s_side>>>();
    cudaEventRecord(ev_scan, s_side);

    // main: weight prep + fc
    k_wal<<<G4, 512>>>(gat_W, attn_l, attn_r);
    k_wprep<<<896, 256>>>(fc_W, gat_W, sem_W);
    k_fc_mma<<<dim3((NP_TYPE + 127) / 128, 2), 256, FC_SZ>>>(
        features0, features1, fc_b, type_idx);
    cudaEventRecord(ev_fc, 0);

    // main chain: branch 0 (graphs 0,1)
    k_gatz_mma<<<dim3((NP_G + 63) / 64, 2), 256, GZ_SZ>>>(node_idx, 0);
    cudaStreamWaitEvent(0, ev_scan, 0);
    k_fill<<<(2 * E_G + 255) / 256, 256>>>(edge_src, edge_dst, 0);
    k_aggregate<<<(2 * T_TGT) / 8, 256>>>(tgt_idx, 0);
    k_sem_mma<<<(2 * T_TGT) / 64, 256, SEMM_SZ>>>(sem_b, sem_q, 0);
    k_combine<<<(T_TGT + 127) / 128, 256>>>(fcout_W, fcout_b, out, 0);

    // side chain: branch 1 (graphs 2,3)
    cudaStreamWaitEvent(s_side, ev_fc, 0);
    k_gatz_mma<<<dim3((NP_G + 63) / 64, 2), 256, GZ_SZ, s_side>>>(node_idx, 2);
    k_fill<<<(2 * E_G + 255) / 256, 256, 0, s_side>>>(edge_src, edge_dst, 2);
    k_aggregate<<<(2 * T_TGT) / 8, 256, 0, s_side>>>(tgt_idx, 2);
    k_sem_mma<<<(2 * T_TGT) / 64, 256, SEMM_SZ, s_side>>>(sem_b, sem_q, 1);
    k_combine<<<(T_TGT + 127) / 128, 256, 0, s_side>>>(fcout_W, fcout_b, out, 1);
    cudaEventRecord(ev_done, s_side);

    cudaStreamWaitEvent(0, ev_done, 0);
}

// round 16
// speedup vs baseline: 2.8539x; 1.0458x over previous
#include <cuda_runtime.h>
#include <cuda_bf16.h>
#include <cuda_fp16.h>
#include <math.h>
#include <stdint.h>

#define N_TOTAL 100000
#define NP_TYPE 50000
#define NP_G    50000
#define E_G     500000
#define NH      4
#define HD      64
#define HID     64
#define D       256
#define OUT_DIM 64
#define T_TGT   20000
#define G4      4
#define OFFS_S  50016   // padded offs stride (16B-aligned per graph)

// ------------------------- scratch (static device globals) -------------------
__device__ __half g_th[N_TOTAL * HID];                   // 12.8 MB (fp16 h)
__device__ __half g_zh[(size_t)G4 * NP_G * D];           // 102.4 MB (fp16 z)
__device__ float  g_el[G4 * NP_G * NH];
__device__ float  g_er[G4 * NP_G * NH];
__device__ float  g_wal[G4 * 64 * 8];                    // W@attn per graph
__device__ int    g_istgt[G4 * NP_G];
__device__ int    g_deg[G4 * NP_G];
__device__ int    g_offs[G4 * OFFS_S];
__device__ int    g_cur[G4 * NP_G];
__device__ int    g_csr_src[G4 * E_G];
__device__ __half g_metah[(size_t)G4 * T_TGT * D];       // 41 MB (fp16 meta)
__device__ float  g_wsum[4];
// preconverted weights
__device__ __half g_fcWh[2 * 64 * 256];                  // [t][o][k]
__device__ __half g_gatWT[G4 * 256 * 64];                // [g][o][k]
__device__ __half g_semWT[2 * 8 * 256 * 32];             // [b][ch][o][kk]

// ------------------------------ small helpers --------------------------------
__device__ __forceinline__ uint32_t smem_u32(const void* p) {
    uint32_t a;
    asm("{ .reg .u64 t; cvta.to.shared.u64 t, %1; cvt.u32.u64 %0, t; }" : "=r"(a) : "l"(p));
    return a;
}
__device__ __forceinline__ uint32_t pack_f16(float lo, float hi) {
    uint32_t r;
    asm("cvt.rn.f16x2.f32 %0, %1, %2;" : "=r"(r) : "f"(hi), "f"(lo));
    return r;
}
__device__ __forceinline__ float tanh_dot2(float x0, float x1, uint32_t qh) {
    uint32_t xp = pack_f16(x0, x1), tp, pp;
    asm("tanh.approx.f16x2 %0, %1;" : "=r"(tp) : "r"(xp));
    asm("mul.f16x2 %0, %1, %2;" : "=r"(pp) : "r"(tp), "r"(qh));
    __half2 h = *reinterpret_cast<__half2*>(&pp);
    return __low2float(h) + __high2float(h);
}
// accumulate 8 fp16 z-values (packed in uint4) scaled by w into a0/a1
__device__ __forceinline__ void acc_z(float4& a0, float4& a1, uint4 zv, float w) {
    float2 f0 = __half22float2(*reinterpret_cast<__half2*>(&zv.x));
    float2 f1 = __half22float2(*reinterpret_cast<__half2*>(&zv.y));
    float2 f2 = __half22float2(*reinterpret_cast<__half2*>(&zv.z));
    float2 f3 = __half22float2(*reinterpret_cast<__half2*>(&zv.w));
    a0.x += w * f0.x; a0.y += w * f0.y;
    a0.z += w * f1.x; a0.w += w * f1.y;
    a1.x += w * f2.x; a1.y += w * f2.y;
    a1.z += w * f3.x; a1.w += w * f3.y;
}
__device__ __forceinline__ void ldsm_x4(uint32_t& r0, uint32_t& r1, uint32_t& r2,
                                        uint32_t& r3, uint32_t addr) {
    asm volatile("ldmatrix.sync.aligned.m8n8.x4.shared.b16 {%0,%1,%2,%3}, [%4];"
                 : "=r"(r0), "=r"(r1), "=r"(r2), "=r"(r3) : "r"(addr));
}
__device__ __forceinline__ void mma_f16(float* c, uint32_t a0, uint32_t a1,
                                        uint32_t a2, uint32_t a3,
                                        uint32_t b0, uint32_t b1) {
    asm volatile(
        "mma.sync.aligned.m16n8k16.row.col.f32.f16.f16.f32 "
        "{%0,%1,%2,%3}, {%4,%5,%6,%7}, {%8,%9}, {%0,%1,%2,%3};"
        : "+f"(c[0]), "+f"(c[1]), "+f"(c[2]), "+f"(c[3])
        : "r"(a0), "r"(a1), "r"(a2), "r"(a3), "r"(b0), "r"(b1));
}

// k_sem_mma dynamic smem layout
#define SEMM_AS   264
#define SEMM_WS   40
#define SEMM_A_B  (64 * SEMM_AS * 2)
#define SEMM_W_O  SEMM_A_B
#define SEMM_W_B  (256 * SEMM_WS * 2)
#define SEMM_BO_O (SEMM_W_O + SEMM_W_B)
#define SEMM_QH_O (SEMM_BO_O + 1024)
#define SEMM_BK_O (SEMM_QH_O + 512)
#define SEMM_SZ   (SEMM_BK_O + 128)

// k_gatz_mma fp16 layout
#define GZ_S      72
#define GZ_AH_O   0
#define GZ_BH_O   9216
#define GZ_WAL_O  46080
#define GZ_SZ     (GZ_WAL_O + 2048)

// k_fc_mma fp16 layout
#define FC_AS     264
#define FC_A_O    0
#define FC_A_B    (128 * FC_AS * 2)
#define FC_B_O    FC_A_B
#define FC_B_B    (64 * FC_AS * 2)
#define FC_BO_O   (FC_B_O + FC_B_B)
#define FC_SZ     (FC_BO_O + 256)

// ------------------------------- init ---------------------------------------
__global__ void k_init() {
    int i = blockIdx.x * blockDim.x + threadIdx.x;
    if (i < G4 * NP_G) { g_deg[i] = 0; g_istgt[i] = 0; }
    if (i < 4) g_wsum[i] = 0.f;
}

__global__ void k_mark(const int* __restrict__ tgt) {
    int t = blockIdx.x * blockDim.x + threadIdx.x;
    if (t < G4 * T_TGT) {
        int g = t / T_TGT;
        g_istgt[g * NP_G + __ldg(&tgt[t])] = 1;
    }
}

// one-time weight preconversion into MMA-friendly layouts
__global__ void k_wprep(const float* __restrict__ fcW,
                        const float* __restrict__ gatW,
                        const float* __restrict__ semW) {
    int i = blockIdx.x * blockDim.x + threadIdx.x;
    if (i < 2 * 64 * 256) {
        g_fcWh[i] = __float2half(__ldg(&fcW[i]));
        return;
    }
    int j = i - 2 * 64 * 256;
    if (j < G4 * 256 * 64) {
        int g = j >> 14, r = j & 16383;
        int o = r >> 6, k = r & 63;
        g_gatWT[j] = __float2half(__ldg(&gatW[g * 16384 + k * 256 + o]));
        return;
    }
    int m = j - G4 * 256 * 64;
    if (m < 2 * 8 * 256 * 32) {
        int b = m >> 16, r2 = m & 65535;
        int ch = r2 >> 13, r3 = r2 & 8191;
        int o = r3 >> 5, kk = r3 & 31;
        g_semWT[m] = __float2half(__ldg(&semW[b * 65536 + (ch * 32 + kk) * 256 + o]));
    }
}

// ---- wal/war: per-graph W @ attn --------------------------------------------
__global__ void k_wal(const float* __restrict__ gatW,
                      const float* __restrict__ attn_l,
                      const float* __restrict__ attn_r)
{
    int g = blockIdx.x;
    int idx = threadIdx.x;
    int k = idx >> 3, o = idx & 7;
    int side = o >> 2, h = o & 3;
    const float* att = (side ? attn_r : attn_l) + (size_t)g * D + h * 64;
    const float* wr = gatW + (size_t)g * HID * D + (size_t)k * D + h * 64;
    float s = 0.f;
#pragma unroll 16
    for (int d = 0; d < 64; d++) s += __ldg(&wr[d]) * __ldg(&att[d]);
    g_wal[g * 512 + k * 8 + o] = s;
}

// ---------- fc on mma.sync fp16; fp16 output stores --------------------------
__global__ __launch_bounds__(256) void k_fc_mma(
    const float* __restrict__ f0, const float* __restrict__ f1,
    const float* __restrict__ fcb, const int* __restrict__ type_idx)
{
    extern __shared__ char smem[];
    __half* fA = (__half*)(smem + FC_A_O);
    __half* fB = (__half*)(smem + FC_B_O);
    float* bo_s = (float*)(smem + FC_BO_O);

    int t = blockIdx.y;
    int base = blockIdx.x * 128;
    const float* feat = t ? f1 : f0;
    int tid = threadIdx.x;
    int wid = tid >> 5, lane = tid & 31;

    if (tid < 64) bo_s[tid] = __ldg(&fcb[t * HID + tid]);

    {   // A: 128 rows x 256 k fp32 -> fp16
        int r = tid >> 2, kq = tid & 3;
#pragma unroll
        for (int rr = 0; rr < 2; rr++) {
            int row = base + rr * 64 + r;
            bool val = row < NP_TYPE;
            const float4* fp = (const float4*)(feat + (size_t)row * D) + kq * 16;
            __half* dst = &fA[(rr * 64 + r) * FC_AS + kq * 64];
#pragma unroll 4
            for (int i = 0; i < 16; i++) {
                float4 v = val ? __ldg(fp + i) : make_float4(0.f, 0.f, 0.f, 0.f);
                *(uint2*)(dst + i * 4) =
                    make_uint2(pack_f16(v.x, v.y), pack_f16(v.z, v.w));
            }
        }
    }
    {   // B: coalesced copy of preconverted fp16 weights
        int o = tid & 63, sq = tid >> 6;
        const uint4* wsrc = (const uint4*)&g_fcWh[(size_t)t * 16384 + o * 256 + sq * 64];
        uint4* wdst = (uint4*)&fB[o * FC_AS + sq * 64];
#pragma unroll
        for (int i = 0; i < 8; i++) wdst[i] = __ldg(wsrc + i);
    }
    __syncthreads();

    float cacc[8][4];
#pragma unroll
    for (int ti = 0; ti < 8; ti++)
#pragma unroll
        for (int j = 0; j < 4; j++) cacc[ti][j] = 0.f;

    int a_tile = lane >> 3;
    int a_row = wid * 16 + (lane & 7) + (a_tile & 1) * 8;
    int a_koff = (a_tile >> 1) * 8;
    int b_g = lane >> 3;
    int b_nbase = (b_g >> 1) * 8 + (lane & 7);
    int b_koff = (b_g & 1) * 8;

#pragma unroll
    for (int ks = 0; ks < 16; ks++) {
        uint32_t a0, a1, a2, a3;
        ldsm_x4(a0, a1, a2, a3, smem_u32(&fA[a_row * FC_AS + ks * 16 + a_koff]));
#pragma unroll
        for (int nt = 0; nt < 4; nt++) {
            uint32_t b0, b1, b2, b3;
            ldsm_x4(b0, b1, b2, b3,
                    smem_u32(&fB[(b_nbase + nt * 16) * FC_AS + ks * 16 + b_koff]));
            mma_f16(cacc[nt * 2 + 0], a0, a1, a2, a3, b0, b1);
            mma_f16(cacc[nt * 2 + 1], a0, a1, a2, a3, b2, b3);
        }
    }

    int lr = lane >> 2, lc = lane & 3;
    int r0 = base + wid * 16 + lr, r1 = r0 + 8;
    const int* ti_p = type_idx + t * NP_TYPE;
    int d0 = (r0 < NP_TYPE) ? __ldg(&ti_p[r0]) : -1;
    int d1 = (r1 < NP_TYPE) ? __ldg(&ti_p[r1]) : -1;
#pragma unroll
    for (int ti = 0; ti < 8; ti++) {
        int col = ti * 8 + lc * 2;
        float b0v = bo_s[col], b1v = bo_s[col + 1];
        if (d0 >= 0)
            *(uint32_t*)&g_th[(size_t)d0 * HID + col] =
                pack_f16(cacc[ti][0] + b0v, cacc[ti][1] + b1v);
        if (d1 >= 0)
            *(uint32_t*)&g_th[(size_t)d1 * HID + col] =
                pack_f16(cacc[ti][2] + b0v, cacc[ti][3] + b1v);
    }
}

// -------- gatz on mma.sync fp16 (single graph g) -----------------------------
__global__ __launch_bounds__(256) void k_gatz_mma(const int* __restrict__ node_idx,
                                                  int g)
{
    extern __shared__ char smem[];
    __half* ah = (__half*)(smem + GZ_AH_O);
    __half* bh = (__half*)(smem + GZ_BH_O);
    float* wal_s = (float*)(smem + GZ_WAL_O);

    int base = blockIdx.x * 64;
    int tid = threadIdx.x;
    int wid = tid >> 5, lane = tid & 31;

    {   // A: gather 64 rows x 64 cols fp16 (direct uint4 copies, no cvt)
        int r = tid >> 2, kq = tid & 3;
        int row = base + r;
        int node = (row < NP_G) ? __ldg(&node_idx[(size_t)g * NP_G + row]) : -1;
        uint4 v0 = make_uint4(0, 0, 0, 0), v1 = make_uint4(0, 0, 0, 0);
        if (node >= 0) {
            const uint4* hp = (const uint4*)(g_th + (size_t)node * HID + kq * 16);
            v0 = __ldg(hp);
            v1 = __ldg(hp + 1);
        }
        *(uint4*)&ah[r * GZ_S + kq * 16] = v0;
        *(uint4*)&ah[r * GZ_S + kq * 16 + 8] = v1;
    }
    {   // B: coalesced copy of preconverted W^T fp16
        const uint4* wsrc = (const uint4*)&g_gatWT[(size_t)g * 16384 + tid * 64];
        uint4* wdst = (uint4*)&bh[tid * GZ_S];
#pragma unroll
        for (int i = 0; i < 8; i++) wdst[i] = __ldg(wsrc + i);
    }
    wal_s[tid] = g_wal[g * 512 + tid];
    wal_s[tid + 256] = g_wal[g * 512 + tid + 256];
    __syncthreads();

    int rw = wid >> 1, cw = wid & 1;
    float cacc[16][4];
#pragma unroll
    for (int ti = 0; ti < 16; ti++)
#pragma unroll
        for (int j = 0; j < 4; j++) cacc[ti][j] = 0.f;

    int a_tile = lane >> 3;
    int a_row = rw * 16 + (lane & 7) + (a_tile & 1) * 8;
    int a_koff = (a_tile >> 1) * 8;
    int b_g = lane >> 3;
    int b_nbase = cw * 128 + (b_g >> 1) * 8 + (lane & 7);
    int b_koff = (b_g & 1) * 8;

#pragma unroll
    for (int ks = 0; ks < 4; ks++) {
        uint32_t a0, a1, a2, a3;
        ldsm_x4(a0, a1, a2, a3, smem_u32(&ah[a_row * GZ_S + ks * 16 + a_koff]));
#pragma unroll
        for (int nt = 0; nt < 8; nt++) {
            uint32_t b0, b1, b2, b3;
            ldsm_x4(b0, b1, b2, b3,
                    smem_u32(&bh[(b_nbase + nt * 16) * GZ_S + ks * 16 + b_koff]));
            mma_f16(cacc[nt * 2 + 0], a0, a1, a2, a3, b0, b1);
            mma_f16(cacc[nt * 2 + 1], a0, a1, a2, a3, b2, b3);
        }
    }

    {   // z stores (fp16 pairs)
        int lr = lane >> 2, lc = lane & 3;
        int r0 = base + rw * 16 + lr, r1 = r0 + 8;
        bool v0 = r0 < NP_G, v1 = r1 < NP_G;
        __half* z0 = g_zh + ((size_t)g * NP_G + r0) * D + cw * 128 + lc * 2;
        __half* z1 = g_zh + ((size_t)g * NP_G + r1) * D + cw * 128 + lc * 2;
#pragma unroll
        for (int ti = 0; ti < 16; ti++) {
            if (v0) *(uint32_t*)(z0 + ti * 8) = pack_f16(cacc[ti][0], cacc[ti][1]);
            if (v1) *(uint32_t*)(z1 + ti * 8) = pack_f16(cacc[ti][2], cacc[ti][3]);
        }
    }

    {   // el/er: h . wal (fp16 h)
        int r = tid & 63;
        int ob = (tid >> 6) * 2;
        int row = base + r;
        if (row < NP_G) {
            float e0 = 0.f, e1 = 0.f;
#pragma unroll 8
            for (int k = 0; k < 64; k += 2) {
                __half2 hb = *(__half2*)&ah[r * GZ_S + k];
                float h0 = __low2float(hb), h1 = __high2float(hb);
                e0 += h0 * wal_s[k * 8 + ob]     + h1 * wal_s[(k + 1) * 8 + ob];
                e1 += h0 * wal_s[k * 8 + ob + 1] + h1 * wal_s[(k + 1) * 8 + ob + 1];
            }
            size_t nbase = ((size_t)g * NP_G + row) * NH;
            if (ob < 4) {
                g_el[nbase + ob] = e0;
                g_el[nbase + ob + 1] = e1;
            } else {
                g_er[nbase + ob - 4] = e0;
                g_er[nbase + ob - 3] = e1;
            }
        }
    }
}

// ------------------------------- CSR build (target-filtered) -----------------
__global__ void k_count(const int* __restrict__ dst) {
    int e = blockIdx.x * blockDim.x + threadIdx.x;
    if (e < G4 * E_G) {
        int g = e / E_G;
        int gn = g * NP_G + __ldg(&dst[e]);
        if (g_istgt[gn]) atomicAdd(&g_deg[gn], 1);
    }
}

// vectorized single-block-per-graph scan
__global__ __launch_bounds__(1024) void k_scan() {
    __shared__ int ws[32];
    int g = blockIdx.x;
    int tid = threadIdx.x;
    int lane = tid & 31, wid = tid >> 5;
    const int CH = 52;
    int lo = tid * CH;
    const int* deg = g_deg + g * NP_G;
    bool fast = (lo + CH) <= NP_G;
    int s = 0;
    if (fast) {
        const int4* p = (const int4*)(deg + lo);
#pragma unroll
        for (int c = 0; c < 13; c++) {
            int4 v = p[c];
            s += v.x + v.y + v.z + v.w;
        }
    } else {
        for (int i = lo; i < NP_G; i++) s += deg[i];
    }
    int v = s;
#pragma unroll
    for (int off = 1; off < 32; off <<= 1) {
        int n = __shfl_up_sync(0xffffffffu, v, off);
        if (lane >= off) v += n;
    }
    if (lane == 31) ws[wid] = v;
    __syncthreads();
    if (wid == 0) {
        int w = ws[lane];
#pragma unroll
        for (int off = 1; off < 32; off <<= 1) {
            int n = __shfl_up_sync(0xffffffffu, w, off);
            if (lane >= off) w += n;
        }
        ws[lane] = w;
    }
    __syncthreads();
    int run = v - s + (wid ? ws[wid - 1] : 0);
    int* offs = g_offs + g * OFFS_S;
    int* cur = g_cur + g * NP_G;
    if (fast) {
        const int4* p = (const int4*)(deg + lo);
        int4* po = (int4*)(offs + lo);
        int4* pc = (int4*)(cur + lo);
#pragma unroll
        for (int c = 0; c < 13; c++) {
            int4 d4 = p[c];
            int4 o4;
            o4.x = run;
            o4.y = run + d4.x;
            o4.z = o4.y + d4.y;
            o4.w = o4.z + d4.z;
            run = o4.w + d4.w;
            po[c] = o4;
            pc[c] = o4;
        }
    } else {
        for (int i = lo; i < NP_G; i++) {
            offs[i] = run;
            cur[i] = run;
            run += deg[i];
        }
    }
    if (tid == 0) offs[NP_G] = ws[31];
}

// ---- fill: src-only scatter (exp moved into aggregate) ----------------------
__global__ void k_fill(const int* __restrict__ src, const int* __restrict__ dst,
                       int g) {
    int e = blockIdx.x * blockDim.x + threadIdx.x;
    if (e >= E_G) return;
    size_t eidx = (size_t)g * E_G + e;
    int d = __ldg(&dst[eidx]);
    int gn = g * NP_G;
    if (!g_istgt[gn + d]) return;
    int pos = atomicAdd(&g_cur[gn + d], 1);
    g_csr_src[(size_t)g * E_G + pos] = __ldg(&src[eidx]);
}

// ------ aggregate: warp per TARGET, inline edge-softmax, fp16 z gathers -----
__global__ __launch_bounds__(256) void k_aggregate(const int* __restrict__ tgt,
                                                   int g) {
    int t = (blockIdx.x * blockDim.x + threadIdx.x) >> 5;
    if (t >= T_TGT) return;
    int tglob = g * T_TGT + t;
    int lane = threadIdx.x & 31;
    int hsel = lane >> 3;
    int nl = __ldg(&tgt[tglob]);
    int gn = g * NP_G;
    int beg = g_offs[g * OFFS_S + nl];
    int end = g_offs[g * OFFS_S + nl + 1];
    const int* cs = g_csr_src + (size_t)g * E_G;
    const __half* zb = g_zh + (size_t)g * NP_G * D;
    const float* elb = g_el;
    float erv = __ldg(&g_er[(size_t)(gn + nl) * NH + hsel]);

    float4 a0 = {0.f, 0.f, 0.f, 0.f}, a1 = {0.f, 0.f, 0.f, 0.f};
    float den = 0.f;

    int i = beg;
    for (; i + 4 <= end; i += 4) {
        int s0 = __ldg(cs + i), s1 = __ldg(cs + i + 1);
        int s2 = __ldg(cs + i + 2), s3 = __ldg(cs + i + 3);
        float el0 = __ldg(&elb[(size_t)(gn + s0) * NH + hsel]);
        float el1 = __ldg(&elb[(size_t)(gn + s1) * NH + hsel]);
        float el2 = __ldg(&elb[(size_t)(gn + s2) * NH + hsel]);
        float el3 = __ldg(&elb[(size_t)(gn + s3) * NH + hsel]);
        uint4 zv0 = __ldg((const uint4*)(zb + (size_t)s0 * D + lane * 8));
        uint4 zv1 = __ldg((const uint4*)(zb + (size_t)s1 * D + lane * 8));
        uint4 zv2 = __ldg((const uint4*)(zb + (size_t)s2 * D + lane * 8));
        uint4 zv3 = __ldg((const uint4*)(zb + (size_t)s3 * D + lane * 8));
        float x0 = el0 + erv; x0 = x0 > 0.f ? x0 : 0.2f * x0; x0 = __expf(x0);
        float x1 = el1 + erv; x1 = x1 > 0.f ? x1 : 0.2f * x1; x1 = __expf(x1);
        float x2 = el2 + erv; x2 = x2 > 0.f ? x2 : 0.2f * x2; x2 = __expf(x2);
        float x3 = el3 + erv; x3 = x3 > 0.f ? x3 : 0.2f * x3; x3 = __expf(x3);
        acc_z(a0, a1, zv0, x0);
        acc_z(a0, a1, zv1, x1);
        acc_z(a0, a1, zv2, x2);
        acc_z(a0, a1, zv3, x3);
        den += x0 + x1 + x2 + x3;
    }
    for (; i < end; i++) {
        int s0 = __ldg(cs + i);
        float el0 = __ldg(&elb[(size_t)(gn + s0) * NH + hsel]);
        uint4 zv0 = __ldg((const uint4*)(zb + (size_t)s0 * D + lane * 8));
        float x0 = el0 + erv; x0 = x0 > 0.f ? x0 : 0.2f * x0; x0 = __expf(x0);
        acc_z(a0, a1, zv0, x0);
        den += x0;
    }
    float inv = 1.f / (den + 1e-9f);
    float v[8] = {a0.x * inv, a0.y * inv, a0.z * inv, a0.w * inv,
                  a1.x * inv, a1.y * inv, a1.z * inv, a1.w * inv};
#pragma unroll
    for (int j = 0; j < 8; j++) v[j] = v[j] > 0.f ? v[j] : expm1f(v[j]);
    __half* op = g_metah + (size_t)tglob * D + lane * 8;
    *(uint2*)op = make_uint2(pack_f16(v[0], v[1]), pack_f16(v[2], v[3]));
    *(uint2*)(op + 4) = make_uint2(pack_f16(v[4], v[5]), pack_f16(v[6], v[7]));
}

// ----- semantic attention on mma.sync fp16 (fp16 meta, direct copies) -------
__global__ __launch_bounds__(256) void k_sem_mma(
    const float* __restrict__ semb, const float* __restrict__ semq, int b)
{
    extern __shared__ char smem[];
    __half* ftA = (__half*)smem;
    __half* wt  = (__half*)(smem + SEMM_W_O);
    float*    bo_s = (float*)(smem + SEMM_BO_O);
    uint32_t* qh_s = (uint32_t*)(smem + SEMM_QH_O);
    float*  bucket = (float*)(smem + SEMM_BK_O);

    const int BR = 2 * T_TGT;
    int tid = threadIdx.x;
    int wid = tid >> 5, lane = tid & 31;
    int base = blockIdx.x * 64;

    if (tid < 64) ((float4*)bo_s)[tid] = __ldg((const float4*)(semb + b * D) + tid);
    else if (tid < 192) {
        int j = tid - 64;
        float q0 = __ldg(&semq[b * D + 2 * j]);
        float q1 = __ldg(&semq[b * D + 2 * j + 1]);
        qh_s[j] = pack_f16(q0, q1);
    }
    if (tid < 2) bucket[tid] = 0.f;

    {   // A: direct fp16 copies from g_metah (8 uint4 per thread)
        int r = tid >> 2, kq = tid & 3;
        const uint4* ap =
            (const uint4*)(g_metah + ((size_t)b * BR + base + r) * D + kq * 64);
        __half* dst = &ftA[r * SEMM_AS + kq * 64];
#pragma unroll
        for (int i = 0; i < 8; i++) *(uint4*)(dst + i * 8) = __ldg(ap + i);
    }

    int rw = wid >> 1, cw = wid & 1;
    float cacc[16][4];
#pragma unroll
    for (int ti = 0; ti < 16; ti++)
#pragma unroll
        for (int j = 0; j < 4; j++) cacc[ti][j] = 0.f;

    int a_tile = lane >> 3;
    int a_row = rw * 16 + (lane & 7) + (a_tile & 1) * 8;
    int a_koff = (a_tile >> 1) * 8;
    int b_g = lane >> 3;
    int b_nbase = cw * 128 + (b_g >> 1) * 8 + (lane & 7);
    int b_koff = (b_g & 1) * 8;

    for (int ch = 0; ch < 8; ch++) {
        __syncthreads();
        {
            const uint4* wsrc =
                (const uint4*)&g_semWT[((size_t)b * 8 + ch) * 8192 + tid * 32];
            uint4* wdst = (uint4*)&wt[tid * SEMM_WS];
#pragma unroll
            for (int i = 0; i < 4; i++) wdst[i] = __ldg(wsrc + i);
        }
        __syncthreads();
#pragma unroll
        for (int ks = 0; ks < 2; ks++) {
            uint32_t a0, a1, a2, a3;
            ldsm_x4(a0, a1, a2, a3,
                    smem_u32(&ftA[a_row * SEMM_AS + ch * 32 + ks * 16 + a_koff]));
#pragma unroll
            for (int nt = 0; nt < 8; nt++) {
                uint32_t b0, b1, b2, b3;
                ldsm_x4(b0, b1, b2, b3,
                        smem_u32(&wt[(b_nbase + nt * 16) * SEMM_WS + ks * 16 + b_koff]));
                mma_f16(cacc[nt * 2 + 0], a0, a1, a2, a3, b0, b1);
                mma_f16(cacc[nt * 2 + 1], a0, a1, a2, a3, b2, b3);
            }
        }
    }

    int lr = lane >> 2, lc = lane & 3;
    float rs0 = 0.f, rs1 = 0.f;
#pragma unroll
    for (int ti = 0; ti < 16; ti++) {
        int col = cw * 128 + ti * 8 + lc * 2;
        uint32_t qh = qh_s[col >> 1];
        float b0v = bo_s[col], b1v = bo_s[col + 1];
        rs0 += tanh_dot2(cacc[ti][0] + b0v, cacc[ti][1] + b1v, qh);
        rs1 += tanh_dot2(cacc[ti][2] + b0v, cacc[ti][3] + b1v, qh);
    }
    rs0 += __shfl_down_sync(0xffffffffu, rs0, 2, 4);
    rs0 += __shfl_down_sync(0xffffffffu, rs0, 1, 4);
    rs1 += __shfl_down_sync(0xffffffffu, rs1, 2, 4);
    rs1 += __shfl_down_sync(0xffffffffu, rs1, 1, 4);
    if (lc == 0) {
        int r0 = base + rw * 16 + lr;
        int r1 = r0 + 8;
        atomicAdd(&bucket[r0 >= T_TGT ? 1 : 0], rs0);
        atomicAdd(&bucket[r1 >= T_TGT ? 1 : 0], rs1);
    }
    __syncthreads();
    if (tid < 2 && bucket[tid] != 0.f) atomicAdd(&g_wsum[b * 2 + tid], bucket[tid]);
}

// -------------- combine: beta-blend fp16 metas, @ fcout_W + bias ------------
__global__ __launch_bounds__(256) void k_combine(
    const float* __restrict__ fW, const float* __restrict__ fb,
    float* __restrict__ outp, int b)
{
    __shared__ float ft[64][128];
    __shared__ float wt[64][64];

    int base = blockIdx.x * 128;
    int tid = threadIdx.x;
    int rg = tid & 31, cg = tid >> 5;

    float w0 = g_wsum[b * 2 + 0] * (1.f / T_TGT);
    float w1 = g_wsum[b * 2 + 1] * (1.f / T_TGT);
    float mx = fmaxf(w0, w1);
    float b0 = __expf(w0 - mx), b1 = __expf(w1 - mx);
    float sm = b0 + b1;
    b0 /= sm; b1 /= sm;

    const __half* m0 = g_metah + ((size_t)(b * 2 + 0) * T_TGT) * D;
    const __half* m1 = g_metah + ((size_t)(b * 2 + 1) * T_TGT) * D;
    const float* W = fW + (size_t)b * D * OUT_DIM;

    float acc[4][8];
#pragma unroll
    for (int a = 0; a < 4; a++)
#pragma unroll
        for (int j = 0; j < 8; j++) acc[a][j] = 0.f;

    for (int ch = 0; ch < 4; ch++) {
        __syncthreads();
        {   // blended ft chunk: 64 k x 128 rows, fp16 sources
            int r = tid & 127, qb = tid >> 7;
            int row = base + r;
            bool val = row < T_TGT;
            const uint4* p0 = (const uint4*)(m0 + (size_t)row * D + ch * 64) + qb * 4;
            const uint4* p1 = (const uint4*)(m1 + (size_t)row * D + ch * 64) + qb * 4;
#pragma unroll
            for (int i = 0; i < 4; i++) {
                uint4 u0 = val ? __ldg(p0 + i) : make_uint4(0, 0, 0, 0);
                uint4 u1 = val ? __ldg(p1 + i) : make_uint4(0, 0, 0, 0);
                int k = qb * 32 + i * 8;
                float2 a0p = __half22float2(*(__half2*)&u0.x);
                float2 a1p = __half22float2(*(__half2*)&u0.y);
                float2 a2p = __half22float2(*(__half2*)&u0.z);
                float2 a3p = __half22float2(*(__half2*)&u0.w);
                float2 c0p = __half22float2(*(__half2*)&u1.x);
                float2 c1p = __half22float2(*(__half2*)&u1.y);
                float2 c2p = __half22float2(*(__half2*)&u1.z);
                float2 c3p = __half22float2(*(__half2*)&u1.w);
                ft[k + 0][r] = b0 * a0p.x + b1 * c0p.x;
                ft[k + 1][r] = b0 * a0p.y + b1 * c0p.y;
                ft[k + 2][r] = b0 * a1p.x + b1 * c1p.x;
                ft[k + 3][r] = b0 * a1p.y + b1 * c1p.y;
                ft[k + 4][r] = b0 * a2p.x + b1 * c2p.x;
                ft[k + 5][r] = b0 * a2p.y + b1 * c2p.y;
                ft[k + 6][r] = b0 * a3p.x + b1 * c3p.x;
                ft[k + 7][r] = b0 * a3p.y + b1 * c3p.y;
            }
        }
        {
            const float4* wp = (const float4*)(W + (size_t)ch * 64 * OUT_DIM);
            float4* wd = (float4*)&wt[0][0];
#pragma unroll
            for (int i = 0; i < 4; i++)
                wd[tid + i * 256] = __ldg(wp + tid + i * 256);
        }
        __syncthreads();
#pragma unroll 16
        for (int k = 0; k < 64; k++) {
            float4 fv = *(const float4*)&ft[k][rg * 4];
            float4 wv0 = *(const float4*)&wt[k][cg * 8];
            float4 wv1 = *(const float4*)&wt[k][cg * 8 + 4];
            float fr[4] = {fv.x, fv.y, fv.z, fv.w};
            float wc[8] = {wv0.x, wv0.y, wv0.z, wv0.w, wv1.x, wv1.y, wv1.z, wv1.w};
#pragma unroll
            for (int a = 0; a < 4; a++)
#pragma unroll
                for (int j = 0; j < 8; j++) acc[a][j] += fr[a] * wc[j];
        }
    }
    float bo[8];
#pragma unroll
    for (int j = 0; j < 8; j++) bo[j] = __ldg(&fb[b * OUT_DIM + cg * 8 + j]);
#pragma unroll
    for (int a = 0; a < 4; a++) {
        int row = base + rg * 4 + a;
        if (row < T_TGT) {
            float* op = outp + ((size_t)b * T_TGT + row) * OUT_DIM + cg * 8;
            *(float4*)op = make_float4(acc[a][0] + bo[0], acc[a][1] + bo[1],
                                       acc[a][2] + bo[2], acc[a][3] + bo[3]);
            *((float4*)op + 1) = make_float4(acc[a][4] + bo[4], acc[a][5] + bo[5],
                                             acc[a][6] + bo[6], acc[a][7] + bo[7]);
        }
    }
}

// ------------------------------- launch -------------------------------------
extern "C" void kernel_launch(void* const* d_in, const int* in_sizes, int n_in,
                              void* d_out, int out_size)
{
    const float* features0 = (const float*)d_in[0];
    const float* features1 = (const float*)d_in[1];
    const float* fc_W      = (const float*)d_in[2];
    const float* fc_b      = (const float*)d_in[3];
    const float* gat_W     = (const float*)d_in[4];
    const float* attn_l    = (const float*)d_in[5];
    const float* attn_r    = (const float*)d_in[6];
    const float* sem_W     = (const float*)d_in[7];
    const float* sem_b     = (const float*)d_in[8];
    const float* sem_q     = (const float*)d_in[9];
    const float* fcout_W   = (const float*)d_in[10];
    const float* fcout_b   = (const float*)d_in[11];
    const int*   type_idx  = (const int*)d_in[12];
    const int*   node_idx  = (const int*)d_in[13];
    const int*   edge_src  = (const int*)d_in[14];
    const int*   edge_dst  = (const int*)d_in[15];
    const int*   tgt_idx   = (const int*)d_in[16];
    float* out = (float*)d_out;

    static cudaStream_t s1 = nullptr, s2 = nullptr, s3 = nullptr;
    static cudaEvent_t ev_fork = nullptr, ev_scan = nullptr, ev_fc = nullptr,
                       ev_a1 = nullptr, ev_a3 = nullptr, ev_done = nullptr;
    static bool attr_done = false;
    if (!s1) {
        cudaStreamCreateWithFlags(&s1, cudaStreamNonBlocking);
        cudaStreamCreateWithFlags(&s2, cudaStreamNonBlocking);
        cudaStreamCreateWithFlags(&s3, cudaStreamNonBlocking);
        cudaEventCreateWithFlags(&ev_fork, cudaEventDisableTiming);
        cudaEventCreateWithFlags(&ev_scan, cudaEventDisableTiming);
        cudaEventCreateWithFlags(&ev_fc, cudaEventDisableTiming);
        cudaEventCreateWithFlags(&ev_a1, cudaEventDisableTiming);
        cudaEventCreateWithFlags(&ev_a3, cudaEventDisableTiming);
        cudaEventCreateWithFlags(&ev_done, cudaEventDisableTiming);
    }
    if (!attr_done) {
        cudaFuncSetAttribute(k_sem_mma, cudaFuncAttributeMaxDynamicSharedMemorySize,
                             SEMM_SZ);
        cudaFuncSetAttribute(k_gatz_mma, cudaFuncAttributeMaxDynamicSharedMemorySize,
                             GZ_SZ);
        cudaFuncSetAttribute(k_fc_mma, cudaFuncAttributeMaxDynamicSharedMemorySize,
                             FC_SZ);
        attr_done = true;
    }

    const int FILL_G = (E_G + 255) / 256;
    const int AGG_G  = (T_TGT + 7) / 8;

    // main: init; fork s2 for mark/count/scan
    k_init<<<(G4 * NP_G + 255) / 256, 256>>>();
    cudaEventRecord(ev_fork, 0);
    cudaStreamWaitEvent(s2, ev_fork, 0);
    k_mark<<<(G4 * T_TGT + 255) / 256, 256, 0, s2>>>(tgt_idx);
    k_count<<<(G4 * E_G + 255) / 256, 256, 0, s2>>>(edge_dst);
    k_scan<<<G4, 1024, 0, s2>>>();
    cudaEventRecord(ev_scan, s2);

    // main: weight prep + fc
    k_wal<<<G4, 512>>>(gat_W, attn_l, attn_r);
    k_wprep<<<896, 256>>>(fc_W, gat_W, sem_W);
    k_fc_mma<<<dim3((NP_TYPE + 127) / 128, 2), 256, FC_SZ>>>(
        features0, features1, fc_b, type_idx);
    cudaEventRecord(ev_fc, 0);

    // graph 0 chain (main)
    k_gatz_mma<<<(NP_G + 63) / 64, 256, GZ_SZ>>>(node_idx, 0);
    cudaStreamWaitEvent(0, ev_scan, 0);
    k_fill<<<FILL_G, 256>>>(edge_src, edge_dst, 0);
    k_aggregate<<<AGG_G, 256>>>(tgt_idx, 0);

    // graph 1 chain (s1)
    cudaStreamWaitEvent(s1, ev_fc, 0);
    k_gatz_mma<<<(NP_G + 63) / 64, 256, GZ_SZ, s1>>>(node_idx, 1);
    cudaStreamWaitEvent(s1, ev_scan, 0);
    k_fill<<<FILL_G, 256, 0, s1>>>(edge_src, edge_dst, 1);
    k_aggregate<<<AGG_G, 256, 0, s1>>>(tgt_idx, 1);
    cudaEventRecord(ev_a1, s1);

    // graph 3 chain (s3)
    cudaStreamWaitEvent(s3, ev_fc, 0);
    k_gatz_mma<<<(NP_G + 63) / 64, 256, GZ_SZ, s3>>>(node_idx, 3);
    cudaStreamWaitEvent(s3, ev_scan, 0);
    k_fill<<<FILL_G, 256, 0, s3>>>(edge_src, edge_dst, 3);
    k_aggregate<<<AGG_G, 256, 0, s3>>>(tgt_idx, 3);
    cudaEventRecord(ev_a3, s3);

    // graph 2 chain + branch 1 tail (s2; scan already done on s2)
    cudaStreamWaitEvent(s2, ev_fc, 0);
    k_gatz_mma<<<(NP_G + 63) / 64, 256, GZ_SZ, s2>>>(node_idx, 2);
    k_fill<<<FILL_G, 256, 0, s2>>>(edge_src, edge_dst, 2);
    k_aggregate<<<AGG_G, 256, 0, s2>>>(tgt_idx, 2);
    cudaStreamWaitEvent(s2, ev_a3, 0);
    k_sem_mma<<<(2 * T_TGT) / 64, 256, SEMM_SZ, s2>>>(sem_b, sem_q, 1);
    k_combine<<<(T_TGT + 127) / 128, 256, 0, s2>>>(fcout_W, fcout_b, out, 1);
    cudaEventRecord(ev_done, s2);

    // branch 0 tail (main)
    cudaStreamWaitEvent(0, ev_a1, 0);
    k_sem_mma<<<(2 * T_TGT) / 64, 256, SEMM_SZ>>>(sem_b, sem_q, 0);
    k_combine<<<(T_TGT + 127) / 128, 256>>>(fcout_W, fcout_b, out, 0);
    cudaStreamWaitEvent(0, ev_done, 0);
}